// round 8
// baseline (speedup 1.0000x reference)
#include <cuda_runtime.h>
#include <cuda_bf16.h>
#include <cstdint>
#include <math.h>

#define T_SEQ   4096
#define DM      1024
#define DFF     4096
#define NHEADS  16
#define HDIM    64
#define LN_EPS  1e-5f

// ---- arch-specific feature gate: tcgen05 only exists on sm_10xa/f targets ----
#if defined(__CUDA_ARCH__)
#  if defined(__CUDA_ARCH_FEAT_SM103_ALL) || defined(__CUDA_ARCH_FEAT_SM100_ALL) || defined(__CUDA_ARCH_FEAT_SM101_ALL)
#    define GEMM_TC 1
#  elif defined(__CUDA_ARCH_SPECIFIC__)
#    define GEMM_TC ((__CUDA_ARCH_SPECIFIC__ >= 1000) ? 1 : 0)
#  elif defined(__CUDA_ARCH_FAMILY_SPECIFIC__)
#    define GEMM_TC ((__CUDA_ARCH_FAMILY_SPECIFIC__ >= 1000) ? 1 : 0)
#  else
#    define GEMM_TC 0
#  endif
#else
#  define GEMM_TC 0
#endif

// ---------------- scratch (static device globals; no allocation) ----------------
static __device__ float g_ln [T_SEQ * DM];
static __device__ float g_y  [T_SEQ * DM];
static __device__ float g_x2 [T_SEQ * DM];
static __device__ float g_ff [T_SEQ * DFF];
// transposed (tf32-rounded) weights, [N, K] K-major
static __device__ float g_wt_qkv[3 * DM * DM];
static __device__ float g_wt_o  [DM * DM];
static __device__ float g_wt_1  [DFF * DM];
static __device__ float g_wt_2  [DM * DFF];
// bf16 attention operands written by the QKV GEMM epilogue
static __device__ __nv_bfloat16 g_q16[NHEADS * T_SEQ * HDIM];     // [h][t][d], scaled log2e/8
static __device__ __nv_bfloat16 g_k16[NHEADS * T_SEQ * HDIM];     // [h][t][d]
static __device__ uint32_t      g_v16[NHEADS * (T_SEQ/2) * HDIM]; // [h][t/2][d] pair-packed

#define QSCALE 0.18033688011112042f   // (1/8) * log2(e)

// ---------------- helpers ----------------
__device__ __forceinline__ float to_tf32(float x) {
    uint32_t u;
    asm("cvt.rna.tf32.f32 %0, %1;" : "=r"(u) : "f"(x));
    return __uint_as_float(u);
}

__device__ __forceinline__ uint32_t packbf(float hi, float lo) {
    uint32_t r;
    asm("cvt.rn.bf16x2.f32 %0, %1, %2;" : "=r"(r) : "f"(hi), "f"(lo));
    return r;
}

__device__ __forceinline__ float ex2(float x) {
    float r;
    asm("ex2.approx.f32 %0, %1;" : "=f"(r) : "f"(x));
    return r;
}

__device__ __forceinline__ void mma_tf32(float* c,
    uint32_t a0, uint32_t a1, uint32_t a2, uint32_t a3,
    uint32_t b0, uint32_t b1)
{
    asm volatile(
        "mma.sync.aligned.m16n8k8.row.col.f32.tf32.tf32.f32 "
        "{%0,%1,%2,%3}, {%4,%5,%6,%7}, {%8,%9}, {%0,%1,%2,%3};\n"
        : "+f"(c[0]), "+f"(c[1]), "+f"(c[2]), "+f"(c[3])
        : "r"(a0), "r"(a1), "r"(a2), "r"(a3), "r"(b0), "r"(b1));
}

__device__ __forceinline__ void mma_bf16(float* c,
    uint32_t a0, uint32_t a1, uint32_t a2, uint32_t a3,
    uint32_t b0, uint32_t b1)
{
    asm volatile(
        "mma.sync.aligned.m16n8k16.row.col.f32.bf16.bf16.f32 "
        "{%0,%1,%2,%3}, {%4,%5,%6,%7}, {%8,%9}, {%0,%1,%2,%3};\n"
        : "+f"(c[0]), "+f"(c[1]), "+f"(c[2]), "+f"(c[3])
        : "r"(a0), "r"(a1), "r"(a2), "r"(a3), "r"(b0), "r"(b1));
}

__device__ __forceinline__ void cp16(uint32_t dst, const void* src) {
    asm volatile("cp.async.ca.shared.global [%0], [%1], 16;\n"
                 :: "r"(dst), "l"(src));
}

__device__ __forceinline__ float gelu_exact(float v) {
    return 0.5f * v * (1.0f + erff(v * 0.70710678118654752440f));
}

// ---------------- merged weight transpose + tf32 round (one launch) ----------------
// out[n][k] = rn(in[k][n]) for all 4 weights; 32x32 tiles, flattened 1D grid.
__global__ __launch_bounds__(256) void transpose_all(
    const float* __restrict__ Wqkv, const float* __restrict__ Wo,
    const float* __restrict__ W1,   const float* __restrict__ W2,
    float* __restrict__ oqkv, float* __restrict__ oo,
    float* __restrict__ o1,   float* __restrict__ o2)
{
    __shared__ float t[32][33];
    int tb = blockIdx.x;
    const float* in; float* out; int R, C, txw;
    if (tb < 3072)      { in = Wqkv; out = oqkv; R = 1024; C = 3072; txw = 96; }
    else if (tb < 4096) { tb -= 3072; in = Wo; out = oo; R = 1024; C = 1024; txw = 32; }
    else if (tb < 8192) { tb -= 4096; in = W1; out = o1; R = 1024; C = 4096; txw = 128; }
    else                { tb -= 8192; in = W2; out = o2; R = 4096; C = 1024; txw = 32; }
    int bx = (tb % txw) * 32, by = (tb / txw) * 32;
    int x = threadIdx.x & 31, y = threadIdx.x >> 5;
    #pragma unroll
    for (int i = 0; i < 32; i += 8)
        t[y + i][x] = in[(size_t)(by + y + i) * C + bx + x];
    __syncthreads();
    #pragma unroll
    for (int i = 0; i < 32; i += 8)
        out[(size_t)(bx + y + i) * R + by + x] = to_tf32(t[x][y + i]);
}

// ---------------- LayerNorm (writes tf32-rounded output) ----------------
__global__ __launch_bounds__(256) void ln_kernel(
    const float* __restrict__ x, const float* __restrict__ g,
    const float* __restrict__ b, float* __restrict__ out)
{
    int row = blockIdx.x;
    int tid = threadIdx.x;
    const float4 v = ((const float4*)(x + (size_t)row * DM))[tid];
    float s  = v.x + v.y + v.z + v.w;
    float sq = v.x * v.x + v.y * v.y + v.z * v.z + v.w * v.w;
    #pragma unroll
    for (int o = 16; o; o >>= 1) {
        s  += __shfl_xor_sync(0xffffffffu, s,  o);
        sq += __shfl_xor_sync(0xffffffffu, sq, o);
    }
    __shared__ float ss[8], ssq[8];
    __shared__ float mean_s, inv_s;
    int w = tid >> 5, l = tid & 31;
    if (l == 0) { ss[w] = s; ssq[w] = sq; }
    __syncthreads();
    if (tid == 0) {
        float st = 0.f, sqt = 0.f;
        #pragma unroll
        for (int i = 0; i < 8; i++) { st += ss[i]; sqt += ssq[i]; }
        float mean = st * (1.0f / DM);
        float var  = sqt * (1.0f / DM) - mean * mean;
        mean_s = mean;
        inv_s  = rsqrtf(var + LN_EPS);
    }
    __syncthreads();
    float mean = mean_s, inv = inv_s;
    const float4 gv = ((const float4*)g)[tid];
    const float4 bv = ((const float4*)b)[tid];
    float4 o;
    o.x = to_tf32((v.x - mean) * inv * gv.x + bv.x);
    o.y = to_tf32((v.y - mean) * inv * gv.y + bv.y);
    o.z = to_tf32((v.z - mean) * inv * gv.z + bv.z);
    o.w = to_tf32((v.w - mean) * inv * gv.w + bv.w);
    ((float4*)(out + (size_t)row * DM))[tid] = o;
}

// ---------------- unified GEMM (unchanged from R7 winner) --------
#define GS        3
#define G_TILE_AB 32768
#define G_STAGE   (2 * G_TILE_AB)
#define G_BASE    1024
#define G_SMEM    (G_BASE + GS * G_STAGE)   // 197632

#if GEMM_TC
__device__ __forceinline__ bool elect_one() {
    uint32_t pred;
    asm volatile(
        "{\n\t.reg .pred p;\n\t"
        "elect.sync _|p, 0xFFFFFFFF;\n\t"
        "selp.b32 %0, 1, 0, p;\n\t}"
        : "=r"(pred));
    return pred != 0;
}
__device__ __forceinline__ uint64_t make_desc(uint32_t addr) {
    const uint64_t base = (2ULL << 61) | (1ULL << 46) | (64ULL << 32) | (1ULL << 16);
    return base | ((uint64_t)(addr >> 4) & 0x3FFF);
}
__device__ __forceinline__ void tc_mma_tf32_ss(uint32_t d, uint64_t ad, uint64_t bd,
                                               uint32_t idesc, bool acc)
{
    uint32_t en = acc ? 1u : 0u;
    asm volatile(
        "{\n\t.reg .pred p;\n\t"
        "setp.ne.u32 p, %4, 0;\n\t"
        "tcgen05.mma.cta_group::1.kind::tf32 [%0], %1, %2, %3, {%5, %5, %5, %5}, p;\n\t}"
        :: "r"(d), "l"(ad), "l"(bd), "r"(idesc), "r"(en), "r"(0u)
        : "memory");
}
#define MBAR_INIT(a, c) \
    asm volatile("mbarrier.init.shared.b64 [%0], %1;" :: "r"(a), "r"(c) : "memory")
#define MBAR_WAIT(a, par) do { \
    uint32_t _m = (a), _p = (par), _d; \
    asm volatile("{\n\t.reg .pred p;\n\t" \
        "mbarrier.try_wait.parity.acquire.cta.shared::cta.b64 p, [%1], %2;\n\t" \
        "selp.b32 %0, 1, 0, p;\n\t}" : "=r"(_d) : "r"(_m), "r"(_p) : "memory"); \
    if (!_d) { \
        asm volatile("{\n\t.reg .pred P1;\n\t" \
            "WL_%=:\n\t" \
            "mbarrier.try_wait.parity.acquire.cta.shared::cta.b64 P1, [%0], %1, 0x989680;\n\t" \
            "@P1 bra.uni WD_%=;\n\t" \
            "bra.uni WL_%=;\n\t" \
            "WD_%=:\n\t}" :: "r"(_m), "r"(_p) : "memory"); \
    } \
} while (0)
#endif  // GEMM_TC

// epilogue write helper for MODE 3 (pair of adjacent columns, one row)
__device__ __forceinline__ void qkv_write_pair(int n, int row, float v0, float v1) {
    if (n < 1024) {
        int hd = n >> 6, d = n & 63;
        ((uint32_t*)g_q16)[(((size_t)hd * T_SEQ + row) * 64 + d) >> 1]
            = packbf(v1 * QSCALE, v0 * QSCALE);
    } else if (n < 2048) {
        int hd = (n - 1024) >> 6, d = (n - 1024) & 63;
        ((uint32_t*)g_k16)[(((size_t)hd * T_SEQ + row) * 64 + d) >> 1]
            = packbf(v1, v0);
    } else {
        int hd = (n - 2048) >> 6, d = (n - 2048) & 63;
        __nv_bfloat16* vp = (__nv_bfloat16*)g_v16;
        size_t wi = ((size_t)hd * (T_SEQ / 2) + (row >> 1)) * 64 + d;
        vp[wi * 2 + (row & 1)]       = __float2bfloat16(v0);
        vp[(wi + 1) * 2 + (row & 1)] = __float2bfloat16(v1);
    }
}

template<int MODE>
__global__ __launch_bounds__(256)
void gemm_any(const float* __restrict__ A, const float* __restrict__ Bt,
              const float* __restrict__ bias, const float* __restrict__ res,
              float* __restrict__ C, int M, int N, int K)
{
    extern __shared__ __align__(1024) char gsm[];
    const int tid = threadIdx.x, wid = tid >> 5, lane = tid & 31;

#if GEMM_TC
    // ================= tcgen05 path (256x256 tile) =================
    const int m0 = blockIdx.y * 256, n0 = blockIdx.x * 256;
    const uint32_t sb = (uint32_t)__cvta_generic_to_shared(gsm);
    const uint32_t mb0 = sb + 16, mb1 = sb + 24;

    if (wid == 0) {
        asm volatile("tcgen05.alloc.cta_group::1.sync.aligned.shared::cta.b32 [%0], %1;"
                     :: "r"(sb), "r"(512u) : "memory");
        asm volatile("tcgen05.relinquish_alloc_permit.cta_group::1.sync.aligned;");
    }
    if (tid == 0) { MBAR_INIT(mb0, 1); MBAR_INIT(mb1, 1); }
    __syncthreads();
    uint32_t tb;
    asm volatile("ld.shared.b32 %0, [%1];" : "=r"(tb) : "r"(sb));

    const int KT = K >> 5;

    auto fill = [&](int slot, int ktile) {
        uint32_t s = sb + G_BASE + slot * G_STAGE;
        const float* Ap = A  + (size_t)m0 * K + ktile * 32;
        const float* Bp = Bt + (size_t)n0 * K + ktile * 32;
        #pragma unroll
        for (int i = 0; i < 8; i++) {
            int idx = tid + i * 256;
            int r = idx >> 3, ch = (idx & 7) * 16;
            uint32_t byte = (uint32_t)(r * 128 + ch);
            uint32_t sw = byte ^ ((byte >> 3) & 0x70);
            cp16(s + sw,             Ap + (size_t)r * K + (ch >> 2));
            cp16(s + G_TILE_AB + sw, Bp + (size_t)r * K + (ch >> 2));
        }
    };

    #pragma unroll
    for (int st = 0; st < GS - 1; st++) {
        fill(st, st);
        asm volatile("cp.async.commit_group;" ::: "memory");
    }

    const uint32_t idesc = (1u << 4) | (2u << 7) | (2u << 10)
                         | (32u << 17) | (8u << 24);

    int ph0 = 0, ph1 = 0;
    for (int kt = 0; kt < KT; kt++) {
        asm volatile("cp.async.wait_group %0;" :: "n"(GS - 2) : "memory");
        asm volatile("fence.proxy.async.shared::cta;" ::: "memory");
        __syncthreads();

        if (wid == 0 && elect_one()) {
            uint32_t s = sb + G_BASE + (kt % GS) * G_STAGE;
            uint64_t ad = make_desc(s);
            uint64_t bd = make_desc(s + G_TILE_AB);
            #pragma unroll
            for (int ks = 0; ks < 4; ks++) {
                bool acc = (kt > 0) || (ks > 0);
                tc_mma_tf32_ss(tb,       ad + ks * 2,        bd + ks * 2, idesc, acc);
                tc_mma_tf32_ss(tb + 256, ad + 1024 + ks * 2, bd + ks * 2, idesc, acc);
            }
            uint32_t mb = (kt & 1) ? mb1 : mb0;
            asm volatile(
                "tcgen05.commit.cta_group::1.mbarrier::arrive::one.shared::cluster.b64 [%0];"
                :: "r"(mb) : "memory");
        }

        if (kt >= 1) {
            if ((kt - 1) & 1) { MBAR_WAIT(mb1, ph1); ph1 ^= 1; }
            else              { MBAR_WAIT(mb0, ph0); ph0 ^= 1; }
        }
        if (kt + GS - 1 < KT) fill((kt + GS - 1) % GS, kt + GS - 1);
        asm volatile("cp.async.commit_group;" ::: "memory");
    }

    if ((KT - 1) & 1) { MBAR_WAIT(mb1, ph1); }
    else              { MBAR_WAIT(mb0, ph0); }
    asm volatile("tcgen05.fence::after_thread_sync;" ::: "memory");

    {
        const int row = m0 + ((wid < 4) ? wid * 32 : 128 + (wid - 4) * 32) + lane;
        const uint32_t dbase = tb + ((wid < 4) ? 0u : 256u);
        #pragma unroll
        for (int c0 = 0; c0 < 256; c0 += 32) {
            float d[32];
            asm volatile(
                "tcgen05.ld.sync.aligned.32x32b.x32.b32 "
                "{%0,%1,%2,%3,%4,%5,%6,%7,%8,%9,%10,%11,%12,%13,%14,%15,"
                "%16,%17,%18,%19,%20,%21,%22,%23,%24,%25,%26,%27,%28,%29,%30,%31}, [%32];"
                : "=f"(d[0]),  "=f"(d[1]),  "=f"(d[2]),  "=f"(d[3]),
                  "=f"(d[4]),  "=f"(d[5]),  "=f"(d[6]),  "=f"(d[7]),
                  "=f"(d[8]),  "=f"(d[9]),  "=f"(d[10]), "=f"(d[11]),
                  "=f"(d[12]), "=f"(d[13]), "=f"(d[14]), "=f"(d[15]),
                  "=f"(d[16]), "=f"(d[17]), "=f"(d[18]), "=f"(d[19]),
                  "=f"(d[20]), "=f"(d[21]), "=f"(d[22]), "=f"(d[23]),
                  "=f"(d[24]), "=f"(d[25]), "=f"(d[26]), "=f"(d[27]),
                  "=f"(d[28]), "=f"(d[29]), "=f"(d[30]), "=f"(d[31])
                : "r"(dbase + c0));
            asm volatile("tcgen05.wait::ld.sync.aligned;" ::: "memory");

            #pragma unroll
            for (int c = 0; c < 32; c += 4) {
                const int n = n0 + c0 + c;
                const float4 bv = *(const float4*)(bias + n);
                float4 v;
                v.x = d[c + 0] + bv.x; v.y = d[c + 1] + bv.y;
                v.z = d[c + 2] + bv.z; v.w = d[c + 3] + bv.w;
                if (MODE == 3) {
                    qkv_write_pair(n,     row, v.x, v.y);
                    qkv_write_pair(n + 2, row, v.z, v.w);
                } else {
                    if (MODE == 1) {
                        const float4 rv = *(const float4*)(res + (size_t)row * N + n);
                        v.x += rv.x; v.y += rv.y; v.z += rv.z; v.w += rv.w;
                    }
                    if (MODE == 2) {
                        v.x = to_tf32(gelu_exact(v.x)); v.y = to_tf32(gelu_exact(v.y));
                        v.z = to_tf32(gelu_exact(v.z)); v.w = to_tf32(gelu_exact(v.w));
                    }
                    *(float4*)(C + (size_t)row * N + n) = v;
                }
            }
        }
    }

    __syncthreads();
    if (tid == 0) {
        asm volatile("mbarrier.inval.shared.b64 [%0];" :: "r"(mb0) : "memory");
        asm volatile("mbarrier.inval.shared.b64 [%0];" :: "r"(mb1) : "memory");
    }
    __syncthreads();
    if (wid == 0)
        asm volatile("tcgen05.dealloc.cta_group::1.sync.aligned.b32 %0, %1;"
                     :: "r"(tb), "r"(512u));

#else
    // ================= mma.sync fallback: 2x2 subtiles of 128x128 =================
    float* As = (float*)gsm;
    float* Bs = As + 2 * 16 * 132;
    #define AS(buf, k, m) As[((buf) * 16 + (k)) * 132 + (m)]
    #define BS(buf, k, n) Bs[((buf) * 16 + (k)) * 132 + (n)]

    const int wm = wid >> 2, wn = wid & 3;
    const int gp = lane >> 2, tg = lane & 3;

    for (int mi = 0; mi < 2; mi++)
    for (int ni = 0; ni < 2; ni++) {
        const int m0 = blockIdx.y * 256 + mi * 128;
        const int n0 = blockIdx.x * 256 + ni * 128;

        float c[4][4][4];
        #pragma unroll
        for (int i = 0; i < 4; i++)
            #pragma unroll
            for (int j = 0; j < 4; j++)
                #pragma unroll
                for (int r = 0; r < 4; r++) c[i][j][r] = 0.f;

        const int KT = K >> 4;
        float4 va[2], vb[2];

        __syncthreads();
        #pragma unroll
        for (int i = 0; i < 2; i++) {
            int idx = tid + i * 256;
            int r = idx >> 2, c4 = (idx & 3) << 2;
            va[i] = *(const float4*)(A  + (size_t)(m0 + r) * K + c4);
            vb[i] = *(const float4*)(Bt + (size_t)(n0 + r) * K + c4);
        }
        #pragma unroll
        for (int i = 0; i < 2; i++) {
            int idx = tid + i * 256;
            int r = idx >> 2, c4 = (idx & 3) << 2;
            AS(0, c4 + 0, r) = to_tf32(va[i].x);
            AS(0, c4 + 1, r) = to_tf32(va[i].y);
            AS(0, c4 + 2, r) = to_tf32(va[i].z);
            AS(0, c4 + 3, r) = to_tf32(va[i].w);
            BS(0, c4 + 0, r) = to_tf32(vb[i].x);
            BS(0, c4 + 1, r) = to_tf32(vb[i].y);
            BS(0, c4 + 2, r) = to_tf32(vb[i].z);
            BS(0, c4 + 3, r) = to_tf32(vb[i].w);
        }
        __syncthreads();

        int cur = 0;
        for (int kt = 0; kt < KT; kt++) {
            if (kt + 1 < KT) {
                #pragma unroll
                for (int i = 0; i < 2; i++) {
                    int idx = tid + i * 256;
                    int r = idx >> 2, c4 = (idx & 3) << 2;
                    va[i] = *(const float4*)(A  + (size_t)(m0 + r) * K + (kt + 1) * 16 + c4);
                    vb[i] = *(const float4*)(Bt + (size_t)(n0 + r) * K + (kt + 1) * 16 + c4);
                }
            }
            #pragma unroll
            for (int ks = 0; ks < 2; ks++) {
                const int k = ks * 8;
                uint32_t a[4][4], b[4][2];
                #pragma unroll
                for (int mf = 0; mf < 4; mf++) {
                    int r0 = wm * 64 + mf * 16;
                    a[mf][0] = __float_as_uint(AS(cur, k + tg,     r0 + gp));
                    a[mf][1] = __float_as_uint(AS(cur, k + tg,     r0 + gp + 8));
                    a[mf][2] = __float_as_uint(AS(cur, k + tg + 4, r0 + gp));
                    a[mf][3] = __float_as_uint(AS(cur, k + tg + 4, r0 + gp + 8));
                }
                #pragma unroll
                for (int nf = 0; nf < 4; nf++) {
                    int c0 = wn * 32 + nf * 8;
                    b[nf][0] = __float_as_uint(BS(cur, k + tg,     c0 + gp));
                    b[nf][1] = __float_as_uint(BS(cur, k + tg + 4, c0 + gp));
                }
                #pragma unroll
                for (int mf = 0; mf < 4; mf++)
                    #pragma unroll
                    for (int nf = 0; nf < 4; nf++)
                        mma_tf32(c[mf][nf], a[mf][0], a[mf][1], a[mf][2], a[mf][3],
                                 b[nf][0], b[nf][1]);
            }
            if (kt + 1 < KT) {
                int nxt = cur ^ 1;
                #pragma unroll
                for (int i = 0; i < 2; i++) {
                    int idx = tid + i * 256;
                    int r = idx >> 2, c4 = (idx & 3) << 2;
                    AS(nxt, c4 + 0, r) = to_tf32(va[i].x);
                    AS(nxt, c4 + 1, r) = to_tf32(va[i].y);
                    AS(nxt, c4 + 2, r) = to_tf32(va[i].z);
                    AS(nxt, c4 + 3, r) = to_tf32(va[i].w);
                    BS(nxt, c4 + 0, r) = to_tf32(vb[i].x);
                    BS(nxt, c4 + 1, r) = to_tf32(vb[i].y);
                    BS(nxt, c4 + 2, r) = to_tf32(vb[i].z);
                    BS(nxt, c4 + 3, r) = to_tf32(vb[i].w);
                }
                __syncthreads();
                cur = nxt;
            }
        }

        #pragma unroll
        for (int mf = 0; mf < 4; mf++) {
            #pragma unroll
            for (int nf = 0; nf < 4; nf++) {
                int col = n0 + wn * 32 + nf * 8 + 2 * tg;
                float bi0 = bias[col], bi1 = bias[col + 1];
                #pragma unroll
                for (int hh = 0; hh < 2; hh++) {
                    int row = m0 + wm * 64 + mf * 16 + gp + hh * 8;
                    float v0 = c[mf][nf][hh * 2 + 0] + bi0;
                    float v1 = c[mf][nf][hh * 2 + 1] + bi1;
                    if (MODE == 3) {
                        qkv_write_pair(col, row, v0, v1);
                    } else {
                        if (MODE == 1) {
                            const float2 rv = *(const float2*)(res + (size_t)row * N + col);
                            v0 += rv.x; v1 += rv.y;
                        }
                        if (MODE == 2) {
                            v0 = to_tf32(gelu_exact(v0));
                            v1 = to_tf32(gelu_exact(v1));
                        }
                        float2 o; o.x = v0; o.y = v1;
                        *(float2*)(C + (size_t)row * N + col) = o;
                    }
                }
            }
        }
    }
    #undef AS
    #undef BS
#endif
}

// ---------------- causal flash attention, bf16 m16n8k16, 128-key tiles -------
// grid (32 qtiles, 16 heads), 256 threads (8 warps), 128-q x 128-key tiles.
// Q pre-scaled by log2e/8; softmax in log2 domain (ex2.approx).
// Causal masking only on the diagonal keytile (kt == ktmax).
// smem words: Qs[128][36]=4608 | Ks 2x[128][36]=9216 | Vs 2x[64][72]=9216 | msk 2x[128]
#define AQ_OFF  0
#define AK_OFF  4608
#define AV_OFF  13824
#define AM_OFF  23040
#define ATTN_SMEM ((23040 + 256) * 4)   // 93184

__global__ __launch_bounds__(256) void attn_kernel(
    const int* __restrict__ amask, float* __restrict__ y)
{
    extern __shared__ uint32_t shw[];
    uint32_t* Qs = shw + AQ_OFF;
    uint32_t* Ks = shw + AK_OFF;
    uint32_t* Vs = shw + AV_OFF;
    int*      mk = (int*)(shw + AM_OFF);

    const int tid = threadIdx.x, lane = tid & 31, w = tid >> 5;
    const int gp = lane >> 2, tg = lane & 3;
    const int h = blockIdx.y;
    const int q0 = (gridDim.x - 1 - blockIdx.x) * 128;
    const int qw = q0 + w * 16;

    // ---- stage Q (bf16, pre-scaled) ----
    {
        const __nv_bfloat16* qb = g_q16 + ((size_t)h * T_SEQ + q0) * 64;
        #pragma unroll
        for (int i = 0; i < 4; i++) {
            int idx = tid + i * 256;
            int r = idx >> 3, ch = idx & 7;
            cp16((uint32_t)__cvta_generic_to_shared(Qs + r * 36 + ch * 4),
                 qb + (size_t)r * 64 + ch * 8);
        }
    }
    asm volatile("cp.async.commit_group;" ::: "memory");

    auto fill_kv = [&](int buf, int kt) {
        const __nv_bfloat16* kbs = g_k16 + ((size_t)h * T_SEQ + kt * 128) * 64;
        #pragma unroll
        for (int i = 0; i < 4; i++) {
            int idx = tid + i * 256;
            int r = idx >> 3, ch = idx & 7;
            cp16((uint32_t)__cvta_generic_to_shared(Ks + buf * 4608 + r * 36 + ch * 4),
                 kbs + (size_t)r * 64 + ch * 8);
        }
        const uint32_t* vbs = g_v16 + ((size_t)h * (T_SEQ / 2) + kt * 64) * 64;
        #pragma unroll
        for (int i = 0; i < 4; i++) {
            int idx = tid + i * 256;
            int pr = idx >> 4, ch = idx & 15;
            cp16((uint32_t)__cvta_generic_to_shared(Vs + buf * 4608 + pr * 72 + ch * 4),
                 vbs + (size_t)pr * 64 + ch * 4);
        }
        if (tid < 32)
            cp16((uint32_t)__cvta_generic_to_shared(mk + buf * 128 + tid * 4),
                 amask + kt * 128 + tid * 4);
    };

    fill_kv(0, 0);
    asm volatile("cp.async.commit_group;" ::: "memory");
    asm volatile("cp.async.wait_group 0;" ::: "memory");
    __syncthreads();

    // ---- Q fragments ----
    uint32_t qa[4][4];
    {
        int r0 = w * 16;
        #pragma unroll
        for (int ks = 0; ks < 4; ks++) {
            qa[ks][0] = Qs[(r0 + gp    ) * 36 + 8 * ks + tg    ];
            qa[ks][1] = Qs[(r0 + gp + 8) * 36 + 8 * ks + tg    ];
            qa[ks][2] = Qs[(r0 + gp    ) * 36 + 8 * ks + 4 + tg];
            qa[ks][3] = Qs[(r0 + gp + 8) * 36 + 8 * ks + 4 + tg];
        }
    }

    float m0 = -INFINITY, m1 = -INFINITY, l0 = 0.f, l1 = 0.f;
    float o[8][4];
    #pragma unroll
    for (int nf = 0; nf < 8; nf++)
        #pragma unroll
        for (int r = 0; r < 4; r++) o[nf][r] = 0.f;

    const int ktmax = q0 >> 7;
    const int row0 = qw + gp, row1 = qw + gp + 8;
    int cur = 0;

    for (int kt = 0; kt <= ktmax; kt++) {
        asm volatile("cp.async.wait_group 0;" ::: "memory");
        __syncthreads();

        if (kt < ktmax) {
            fill_kv(cur ^ 1, kt + 1);
            asm volatile("cp.async.commit_group;" ::: "memory");
        }

        const uint32_t* K = Ks + cur * 4608;
        const uint32_t* V = Vs + cur * 4608;
        const int*      M = mk + cur * 128;
        const bool diag = (kt == ktmax);

        // ---- S = Q @ K^T (16 x 128 per warp) ----
        float sc[16][4];
        #pragma unroll
        for (int nf = 0; nf < 16; nf++)
            #pragma unroll
            for (int r = 0; r < 4; r++) sc[nf][r] = 0.f;

        #pragma unroll
        for (int ks = 0; ks < 4; ks++) {
            #pragma unroll
            for (int nf = 0; nf < 16; nf++) {
                uint32_t b0 = K[(nf * 8 + gp) * 36 + 8 * ks + tg    ];
                uint32_t b1 = K[(nf * 8 + gp) * 36 + 8 * ks + 4 + tg];
                mma_bf16(sc[nf], qa[ks][0], qa[ks][1], qa[ks][2], qa[ks][3], b0, b1);
            }
        }

        // ---- mask (causal only on diagonal tile) ----
        float tm0 = -INFINITY, tm1 = -INFINITY;
        if (diag) {
            #pragma unroll
            for (int nf = 0; nf < 16; nf++) {
                int cl = nf * 8 + 2 * tg;
                int c  = kt * 128 + cl;
                bool mk0 = M[cl] != 0, mk1 = M[cl + 1] != 0;
                float s0 = sc[nf][0], s1 = sc[nf][1];
                float s2 = sc[nf][2], s3 = sc[nf][3];
                s0 = (c     <= row0 && mk0) ? s0 : -INFINITY;
                s1 = (c + 1 <= row0 && mk1) ? s1 : -INFINITY;
                s2 = (c     <= row1 && mk0) ? s2 : -INFINITY;
                s3 = (c + 1 <= row1 && mk1) ? s3 : -INFINITY;
                sc[nf][0] = s0; sc[nf][1] = s1; sc[nf][2] = s2; sc[nf][3] = s3;
                tm0 = fmaxf(tm0, fmaxf(s0, s1));
                tm1 = fmaxf(tm1, fmaxf(s2, s3));
            }
        } else {
            #pragma unroll
            for (int nf = 0; nf < 16; nf++) {
                int cl = nf * 8 + 2 * tg;
                bool mk0 = M[cl] != 0, mk1 = M[cl + 1] != 0;
                float s0 = mk0 ? sc[nf][0] : -INFINITY;
                float s1 = mk1 ? sc[nf][1] : -INFINITY;
                float s2 = mk0 ? sc[nf][2] : -INFINITY;
                float s3 = mk1 ? sc[nf][3] : -INFINITY;
                sc[nf][0] = s0; sc[nf][1] = s1; sc[nf][2] = s2; sc[nf][3] = s3;
                tm0 = fmaxf(tm0, fmaxf(s0, s1));
                tm1 = fmaxf(tm1, fmaxf(s2, s3));
            }
        }
        tm0 = fmaxf(tm0, __shfl_xor_sync(0xffffffffu, tm0, 1));
        tm0 = fmaxf(tm0, __shfl_xor_sync(0xffffffffu, tm0, 2));
        tm1 = fmaxf(tm1, __shfl_xor_sync(0xffffffffu, tm1, 1));
        tm1 = fmaxf(tm1, __shfl_xor_sync(0xffffffffu, tm1, 2));

        float nm0 = fmaxf(m0, tm0), nm1 = fmaxf(m1, tm1);
        float ne0 = fmaxf(nm0, -1e30f), ne1 = fmaxf(nm1, -1e30f);
        float al0 = ex2(m0 - ne0), al1 = ex2(m1 - ne1);
        m0 = nm0; m1 = nm1;

        float ps0 = 0.f, ps1 = 0.f;
        #pragma unroll
        for (int nf = 0; nf < 16; nf++) {
            float p0 = ex2(sc[nf][0] - ne0);
            float p1 = ex2(sc[nf][1] - ne0);
            float p2 = ex2(sc[nf][2] - ne1);
            float p3 = ex2(sc[nf][3] - ne1);
            sc[nf][0] = p0; sc[nf][1] = p1; sc[nf][2] = p2; sc[nf][3] = p3;
            ps0 += p0 + p1; ps1 += p2 + p3;
        }
        ps0 += __shfl_xor_sync(0xffffffffu, ps0, 1);
        ps0 += __shfl_xor_sync(0xffffffffu, ps0, 2);
        ps1 += __shfl_xor_sync(0xffffffffu, ps1, 1);
        ps1 += __shfl_xor_sync(0xffffffffu, ps1, 2);
        l0 = l0 * al0 + ps0;
        l1 = l1 * al1 + ps1;

        #pragma unroll
        for (int nf = 0; nf < 8; nf++) {
            o[nf][0] *= al0; o[nf][1] *= al0;
            o[nf][2] *= al1; o[nf][3] *= al1;
        }

        // ---- O += P @ V ----
        #pragma unroll
        for (int ks = 0; ks < 8; ks++) {
            uint32_t pa0 = packbf(sc[2*ks  ][1], sc[2*ks  ][0]);
            uint32_t pa1 = packbf(sc[2*ks  ][3], sc[2*ks  ][2]);
            uint32_t pa2 = packbf(sc[2*ks+1][1], sc[2*ks+1][0]);
            uint32_t pa3 = packbf(sc[2*ks+1][3], sc[2*ks+1][2]);
            #pragma unroll
            for (int nf = 0; nf < 8; nf++) {
                uint32_t b0 = V[(8 * ks + tg    ) * 72 + nf * 8 + gp];
                uint32_t b1 = V[(8 * ks + 4 + tg) * 72 + nf * 8 + gp];
                mma_bf16(o[nf], pa0, pa1, pa2, pa3, b0, b1);
            }
        }
        cur ^= 1;
    }

    float il0 = 1.0f / fmaxf(l0, 1e-30f);
    float il1 = 1.0f / fmaxf(l1, 1e-30f);
    #pragma unroll
    for (int nf = 0; nf < 8; nf++) {
        int col = h * HDIM + nf * 8 + 2 * tg;
        float2 v0; v0.x = to_tf32(o[nf][0] * il0); v0.y = to_tf32(o[nf][1] * il0);
        *(float2*)(y + (size_t)row0 * DM + col) = v0;
        float2 v1; v1.x = to_tf32(o[nf][2] * il1); v1.y = to_tf32(o[nf][3] * il1);
        *(float2*)(y + (size_t)row1 * DM + col) = v1;
    }
}

// ---------------- launcher ----------------
extern "C" void kernel_launch(void* const* d_in, const int* in_sizes, int n_in,
                              void* d_out, int out_size)
{
    const float* x     = (const float*)d_in[0];
    const int*   amask = (const int*)  d_in[1];
    const float* ln1g  = (const float*)d_in[2];
    const float* ln1b  = (const float*)d_in[3];
    const float* Wqkv  = (const float*)d_in[4];
    const float* bqkv  = (const float*)d_in[5];
    const float* Wo    = (const float*)d_in[6];
    const float* bo    = (const float*)d_in[7];
    const float* ln2g  = (const float*)d_in[8];
    const float* ln2b  = (const float*)d_in[9];
    const float* W1    = (const float*)d_in[10];
    const float* b1    = (const float*)d_in[11];
    const float* W2    = (const float*)d_in[12];
    const float* b2    = (const float*)d_in[13];
    float* out = (float*)d_out;

    void *p_ln, *p_y, *p_x2, *p_ff;
    void *p_wqkv, *p_wo, *p_w1, *p_w2;
    cudaGetSymbolAddress(&p_ln,   g_ln);
    cudaGetSymbolAddress(&p_y,    g_y);
    cudaGetSymbolAddress(&p_x2,   g_x2);
    cudaGetSymbolAddress(&p_ff,   g_ff);
    cudaGetSymbolAddress(&p_wqkv, g_wt_qkv);
    cudaGetSymbolAddress(&p_wo,   g_wt_o);
    cudaGetSymbolAddress(&p_w1,   g_wt_1);
    cudaGetSymbolAddress(&p_w2,   g_wt_2);

    cudaFuncSetAttribute(attn_kernel,
        cudaFuncAttributeMaxDynamicSharedMemorySize, ATTN_SMEM);
    cudaFuncSetAttribute(gemm_any<1>,
        cudaFuncAttributeMaxDynamicSharedMemorySize, G_SMEM);
    cudaFuncSetAttribute(gemm_any<2>,
        cudaFuncAttributeMaxDynamicSharedMemorySize, G_SMEM);
    cudaFuncSetAttribute(gemm_any<3>,
        cudaFuncAttributeMaxDynamicSharedMemorySize, G_SMEM);

    // 0. weight transposes (tf32-rounded, [N,K]) — single launch
    transpose_all<<<12288, 256>>>(Wqkv, Wo, W1, W2,
                                  (float*)p_wqkv, (float*)p_wo,
                                  (float*)p_w1, (float*)p_w2);

    // 1. LN1
    ln_kernel<<<T_SEQ, 256>>>(x, ln1g, ln1b, (float*)p_ln);
    // 2. QKV -> bf16 Q/K/V buffers (Q pre-scaled by log2e/8)
    gemm_any<3><<<dim3(12, 16), 256, G_SMEM>>>((float*)p_ln, (float*)p_wqkv, bqkv, nullptr,
                                               nullptr, T_SEQ, 3 * DM, DM);
    // 3. attention (bf16 mma, 128-key tiles, exp2 softmax)
    attn_kernel<<<dim3(32, 16), 256, ATTN_SMEM>>>(amask, (float*)p_y);
    // 4. x2 = x + y @ W_o + b_o
    gemm_any<1><<<dim3(4, 16), 256, G_SMEM>>>((float*)p_y, (float*)p_wo, bo, x,
                                              (float*)p_x2, T_SEQ, DM, DM);
    // 5. LN2
    ln_kernel<<<T_SEQ, 256>>>((float*)p_x2, ln2g, ln2b, (float*)p_ln);
    // 6. ff = gelu(h2 @ W1 + b1)
    gemm_any<2><<<dim3(16, 16), 256, G_SMEM>>>((float*)p_ln, (float*)p_w1, b1, nullptr,
                                               (float*)p_ff, T_SEQ, DFF, DM);
    // 7. out = x2 + ff @ W2 + b2
    gemm_any<1><<<dim3(4, 16), 256, G_SMEM>>>((float*)p_ff, (float*)p_w2, b2, (float*)p_x2,
                                              out, T_SEQ, DM, DFF);
}

// round 10
// speedup vs baseline: 1.0073x; 1.0073x over previous
#include <cuda_runtime.h>
#include <cuda_bf16.h>
#include <cstdint>
#include <math.h>

#define T_SEQ   4096
#define DM      1024
#define DFF     4096
#define NHEADS  16
#define HDIM    64
#define LN_EPS  1e-5f

// ---- arch-specific feature gate: tcgen05 only exists on sm_10xa/f targets ----
#if defined(__CUDA_ARCH__)
#  if defined(__CUDA_ARCH_FEAT_SM103_ALL) || defined(__CUDA_ARCH_FEAT_SM100_ALL) || defined(__CUDA_ARCH_FEAT_SM101_ALL)
#    define GEMM_TC 1
#  elif defined(__CUDA_ARCH_SPECIFIC__)
#    define GEMM_TC ((__CUDA_ARCH_SPECIFIC__ >= 1000) ? 1 : 0)
#  elif defined(__CUDA_ARCH_FAMILY_SPECIFIC__)
#    define GEMM_TC ((__CUDA_ARCH_FAMILY_SPECIFIC__ >= 1000) ? 1 : 0)
#  else
#    define GEMM_TC 0
#  endif
#else
#  define GEMM_TC 0
#endif

// ---------------- scratch (static device globals; no allocation) ----------------
static __device__ float g_ln [T_SEQ * DM];
static __device__ float g_y  [T_SEQ * DM];
static __device__ float g_x2 [T_SEQ * DM];
static __device__ float g_ff [T_SEQ * DFF];
// transposed (tf32-rounded) weights, [N, K] K-major
static __device__ float g_wt_qkv[3 * DM * DM];
static __device__ float g_wt_o  [DM * DM];
static __device__ float g_wt_1  [DFF * DM];
static __device__ float g_wt_2  [DM * DFF];
// bf16 attention operands written by the QKV GEMM epilogue
static __device__ __nv_bfloat16 g_q16[NHEADS * T_SEQ * HDIM];     // [h][t][d], scaled log2e/8
static __device__ __nv_bfloat16 g_k16[NHEADS * T_SEQ * HDIM];     // [h][t][d]
static __device__ uint32_t      g_v16[NHEADS * (T_SEQ/2) * HDIM]; // [h][t/2][d] pair-packed

#define QSCALE 0.18033688011112042f   // (1/8) * log2(e)

// ---------------- helpers ----------------
__device__ __forceinline__ float to_tf32(float x) {
    uint32_t u;
    asm("cvt.rna.tf32.f32 %0, %1;" : "=r"(u) : "f"(x));
    return __uint_as_float(u);
}

__device__ __forceinline__ uint32_t packbf(float hi, float lo) {
    uint32_t r;
    asm("cvt.rn.bf16x2.f32 %0, %1, %2;" : "=r"(r) : "f"(hi), "f"(lo));
    return r;
}

__device__ __forceinline__ float ex2(float x) {
    float r;
    asm("ex2.approx.f32 %0, %1;" : "=f"(r) : "f"(x));
    return r;
}

__device__ __forceinline__ void mma_tf32(float* c,
    uint32_t a0, uint32_t a1, uint32_t a2, uint32_t a3,
    uint32_t b0, uint32_t b1)
{
    asm volatile(
        "mma.sync.aligned.m16n8k8.row.col.f32.tf32.tf32.f32 "
        "{%0,%1,%2,%3}, {%4,%5,%6,%7}, {%8,%9}, {%0,%1,%2,%3};\n"
        : "+f"(c[0]), "+f"(c[1]), "+f"(c[2]), "+f"(c[3])
        : "r"(a0), "r"(a1), "r"(a2), "r"(a3), "r"(b0), "r"(b1));
}

__device__ __forceinline__ void mma_bf16(float* c,
    uint32_t a0, uint32_t a1, uint32_t a2, uint32_t a3,
    uint32_t b0, uint32_t b1)
{
    asm volatile(
        "mma.sync.aligned.m16n8k16.row.col.f32.bf16.bf16.f32 "
        "{%0,%1,%2,%3}, {%4,%5,%6,%7}, {%8,%9}, {%0,%1,%2,%3};\n"
        : "+f"(c[0]), "+f"(c[1]), "+f"(c[2]), "+f"(c[3])
        : "r"(a0), "r"(a1), "r"(a2), "r"(a3), "r"(b0), "r"(b1));
}

__device__ __forceinline__ void cp16(uint32_t dst, const void* src) {
    asm volatile("cp.async.ca.shared.global [%0], [%1], 16;\n"
                 :: "r"(dst), "l"(src));
}

__device__ __forceinline__ float gelu_exact(float v) {
    return 0.5f * v * (1.0f + erff(v * 0.70710678118654752440f));
}

// ---------------- merged weight transpose + tf32 round (one launch) ----------------
__global__ __launch_bounds__(256) void transpose_all(
    const float* __restrict__ Wqkv, const float* __restrict__ Wo,
    const float* __restrict__ W1,   const float* __restrict__ W2,
    float* __restrict__ oqkv, float* __restrict__ oo,
    float* __restrict__ o1,   float* __restrict__ o2)
{
    __shared__ float t[32][33];
    int tb = blockIdx.x;
    const float* in; float* out; int R, C, txw;
    if (tb < 3072)      { in = Wqkv; out = oqkv; R = 1024; C = 3072; txw = 96; }
    else if (tb < 4096) { tb -= 3072; in = Wo; out = oo; R = 1024; C = 1024; txw = 32; }
    else if (tb < 8192) { tb -= 4096; in = W1; out = o1; R = 1024; C = 4096; txw = 128; }
    else                { tb -= 8192; in = W2; out = o2; R = 4096; C = 1024; txw = 32; }
    int bx = (tb % txw) * 32, by = (tb / txw) * 32;
    int x = threadIdx.x & 31, y = threadIdx.x >> 5;
    #pragma unroll
    for (int i = 0; i < 32; i += 8)
        t[y + i][x] = in[(size_t)(by + y + i) * C + bx + x];
    __syncthreads();
    #pragma unroll
    for (int i = 0; i < 32; i += 8)
        out[(size_t)(bx + y + i) * R + by + x] = to_tf32(t[x][y + i]);
}

// ---------------- LayerNorm (writes tf32-rounded output) ----------------
__global__ __launch_bounds__(256) void ln_kernel(
    const float* __restrict__ x, const float* __restrict__ g,
    const float* __restrict__ b, float* __restrict__ out)
{
    int row = blockIdx.x;
    int tid = threadIdx.x;
    const float4 v = ((const float4*)(x + (size_t)row * DM))[tid];
    float s  = v.x + v.y + v.z + v.w;
    float sq = v.x * v.x + v.y * v.y + v.z * v.z + v.w * v.w;
    #pragma unroll
    for (int o = 16; o; o >>= 1) {
        s  += __shfl_xor_sync(0xffffffffu, s,  o);
        sq += __shfl_xor_sync(0xffffffffu, sq, o);
    }
    __shared__ float ss[8], ssq[8];
    __shared__ float mean_s, inv_s;
    int w = tid >> 5, l = tid & 31;
    if (l == 0) { ss[w] = s; ssq[w] = sq; }
    __syncthreads();
    if (tid == 0) {
        float st = 0.f, sqt = 0.f;
        #pragma unroll
        for (int i = 0; i < 8; i++) { st += ss[i]; sqt += ssq[i]; }
        float mean = st * (1.0f / DM);
        float var  = sqt * (1.0f / DM) - mean * mean;
        mean_s = mean;
        inv_s  = rsqrtf(var + LN_EPS);
    }
    __syncthreads();
    float mean = mean_s, inv = inv_s;
    const float4 gv = ((const float4*)g)[tid];
    const float4 bv = ((const float4*)b)[tid];
    float4 o;
    o.x = to_tf32((v.x - mean) * inv * gv.x + bv.x);
    o.y = to_tf32((v.y - mean) * inv * gv.y + bv.y);
    o.z = to_tf32((v.z - mean) * inv * gv.z + bv.z);
    o.w = to_tf32((v.w - mean) * inv * gv.w + bv.w);
    ((float4*)(out + (size_t)row * DM))[tid] = o;
}

// ---------------- unified GEMM: C[M,N] = A[M,K] @ Bt[N,K]^T + epilogue --------
// Tile 256x256, 256 threads. grid = (N/256, M/256).
// TC path: tcgen05 SS tf32, BK=32, 3-slot ring, mbarrier dataflow:
//   producers: cp.async + cp.async.mbarrier.arrive.NOINC (init count=256);
//   consumer warp0: wait fill-mbar -> fence.proxy.async -> UTCHMMA + commit.
//   No __syncthreads / wait_group in the mainloop. Slot reuse gated by mma mbar.
// Fallback: proven mma.sync 128x128 body, 2x2 subtiles.
#define GS        3
#define G_TILE_AB 32768
#define G_STAGE   (2 * G_TILE_AB)
#define G_BASE    1024
#define G_SMEM    (G_BASE + GS * G_STAGE)   // 197632

#if GEMM_TC
__device__ __forceinline__ bool elect_one() {
    uint32_t pred;
    asm volatile(
        "{\n\t.reg .pred p;\n\t"
        "elect.sync _|p, 0xFFFFFFFF;\n\t"
        "selp.b32 %0, 1, 0, p;\n\t}"
        : "=r"(pred));
    return pred != 0;
}
__device__ __forceinline__ uint64_t make_desc(uint32_t addr) {
    const uint64_t base = (2ULL << 61) | (1ULL << 46) | (64ULL << 32) | (1ULL << 16);
    return base | ((uint64_t)(addr >> 4) & 0x3FFF);
}
__device__ __forceinline__ void tc_mma_tf32_ss(uint32_t d, uint64_t ad, uint64_t bd,
                                               uint32_t idesc, bool acc)
{
    uint32_t en = acc ? 1u : 0u;
    asm volatile(
        "{\n\t.reg .pred p;\n\t"
        "setp.ne.u32 p, %4, 0;\n\t"
        "tcgen05.mma.cta_group::1.kind::tf32 [%0], %1, %2, %3, {%5, %5, %5, %5}, p;\n\t}"
        :: "r"(d), "l"(ad), "l"(bd), "r"(idesc), "r"(en), "r"(0u)
        : "memory");
}
#define MBAR_INIT(a, c) \
    asm volatile("mbarrier.init.shared.b64 [%0], %1;" :: "r"(a), "r"(c) : "memory")
#define MBAR_WAIT(a, par) do { \
    uint32_t _m = (a), _p = (par), _d; \
    asm volatile("{\n\t.reg .pred p;\n\t" \
        "mbarrier.try_wait.parity.acquire.cta.shared::cta.b64 p, [%1], %2;\n\t" \
        "selp.b32 %0, 1, 0, p;\n\t}" : "=r"(_d) : "r"(_m), "r"(_p) : "memory"); \
    if (!_d) { \
        asm volatile("{\n\t.reg .pred P1;\n\t" \
            "WL_%=:\n\t" \
            "mbarrier.try_wait.parity.acquire.cta.shared::cta.b64 P1, [%0], %1, 0x989680;\n\t" \
            "@P1 bra.uni WD_%=;\n\t" \
            "bra.uni WL_%=;\n\t" \
            "WD_%=:\n\t}" :: "r"(_m), "r"(_p) : "memory"); \
    } \
} while (0)
// NOINC: async arrive only — the init count (256) is consumed purely by the
// async completions. The non-noinc form pre-increments the pending count and
// nets to zero arrivals, which deadlocks a count-N barrier (R9 hang).
#define CPASYNC_MBAR_ARRIVE_NOINC(a) \
    asm volatile("cp.async.mbarrier.arrive.noinc.shared.b64 [%0];" :: "r"(a) : "memory")
#endif  // GEMM_TC

// epilogue write helper for MODE 3 (pair of adjacent columns, one row)
__device__ __forceinline__ void qkv_write_pair(int n, int row, float v0, float v1) {
    if (n < 1024) {
        int hd = n >> 6, d = n & 63;
        ((uint32_t*)g_q16)[(((size_t)hd * T_SEQ + row) * 64 + d) >> 1]
            = packbf(v1 * QSCALE, v0 * QSCALE);
    } else if (n < 2048) {
        int hd = (n - 1024) >> 6, d = (n - 1024) & 63;
        ((uint32_t*)g_k16)[(((size_t)hd * T_SEQ + row) * 64 + d) >> 1]
            = packbf(v1, v0);
    } else {
        int hd = (n - 2048) >> 6, d = (n - 2048) & 63;
        __nv_bfloat16* vp = (__nv_bfloat16*)g_v16;
        size_t wi = ((size_t)hd * (T_SEQ / 2) + (row >> 1)) * 64 + d;
        vp[wi * 2 + (row & 1)]       = __float2bfloat16(v0);
        vp[(wi + 1) * 2 + (row & 1)] = __float2bfloat16(v1);
    }
}

template<int MODE>
__global__ __launch_bounds__(256)
void gemm_any(const float* __restrict__ A, const float* __restrict__ Bt,
              const float* __restrict__ bias, const float* __restrict__ res,
              float* __restrict__ C, int M, int N, int K)
{
    extern __shared__ __align__(1024) char gsm[];
    const int tid = threadIdx.x, wid = tid >> 5, lane = tid & 31;

#if GEMM_TC
    // ================= tcgen05 path (256x256 tile, mbarrier dataflow) =========
    const int m0 = blockIdx.y * 256, n0 = blockIdx.x * 256;
    const uint32_t sb = (uint32_t)__cvta_generic_to_shared(gsm);
    const uint32_t mb0 = sb + 16, mb1 = sb + 24;
    const uint32_t fmb = sb + 32;      // 3 fill mbars at +32, +40, +48

    if (wid == 0) {
        asm volatile("tcgen05.alloc.cta_group::1.sync.aligned.shared::cta.b32 [%0], %1;"
                     :: "r"(sb), "r"(512u) : "memory");
        asm volatile("tcgen05.relinquish_alloc_permit.cta_group::1.sync.aligned;");
    }
    if (tid == 0) {
        MBAR_INIT(mb0, 1); MBAR_INIT(mb1, 1);
        MBAR_INIT(fmb + 0, 256); MBAR_INIT(fmb + 8, 256); MBAR_INIT(fmb + 16, 256);
    }
    __syncthreads();
    uint32_t tb;
    asm volatile("ld.shared.b32 %0, [%1];" : "=r"(tb) : "r"(sb));

    const int KT = K >> 5;

    auto fill = [&](int slot, int ktile) {
        uint32_t s = sb + G_BASE + slot * G_STAGE;
        const float* Ap = A  + (size_t)m0 * K + ktile * 32;
        const float* Bp = Bt + (size_t)n0 * K + ktile * 32;
        #pragma unroll
        for (int i = 0; i < 8; i++) {
            int idx = tid + i * 256;
            int r = idx >> 3, ch = (idx & 7) * 16;
            uint32_t byte = (uint32_t)(r * 128 + ch);
            uint32_t sw = byte ^ ((byte >> 3) & 0x70);
            cp16(s + sw,             Ap + (size_t)r * K + (ch >> 2));
            cp16(s + G_TILE_AB + sw, Bp + (size_t)r * K + (ch >> 2));
        }
        CPASYNC_MBAR_ARRIVE_NOINC(fmb + slot * 8);
    };

    // prologue: fill slots 0..GS-2
    #pragma unroll
    for (int st = 0; st < GS - 1; st++) fill(st, st);

    const uint32_t idesc = (1u << 4) | (2u << 7) | (2u << 10)
                         | (32u << 17) | (8u << 24);

    int ph0 = 0, ph1 = 0;
    for (int kt = 0; kt < KT; kt++) {
        // consumer: wait slot's fill complete, issue mma, commit
        if (wid == 0) {
            int slot = kt % GS;
            int fph = (kt / GS) & 1;
            MBAR_WAIT(fmb + slot * 8, fph);
            asm volatile("fence.proxy.async.shared::cta;" ::: "memory");
            if (elect_one()) {
                uint32_t s = sb + G_BASE + slot * G_STAGE;
                uint64_t ad = make_desc(s);
                uint64_t bd = make_desc(s + G_TILE_AB);
                #pragma unroll
                for (int ks = 0; ks < 4; ks++) {
                    bool acc = (kt > 0) || (ks > 0);
                    tc_mma_tf32_ss(tb,       ad + ks * 2,        bd + ks * 2, idesc, acc);
                    tc_mma_tf32_ss(tb + 256, ad + 1024 + ks * 2, bd + ks * 2, idesc, acc);
                }
                uint32_t mb = (kt & 1) ? mb1 : mb0;
                asm volatile(
                    "tcgen05.commit.cta_group::1.mbarrier::arrive::one.shared::cluster.b64 [%0];"
                    :: "r"(mb) : "memory");
            }
        }

        // producers: before refilling the slot mma(kt-1) read, wait its completion
        if (kt >= 1) {
            if ((kt - 1) & 1) { MBAR_WAIT(mb1, ph1); ph1 ^= 1; }
            else              { MBAR_WAIT(mb0, ph0); ph0 ^= 1; }
        }
        if (kt + GS - 1 < KT) fill((kt + GS - 1) % GS, kt + GS - 1);
    }

    if ((KT - 1) & 1) { MBAR_WAIT(mb1, ph1); }
    else              { MBAR_WAIT(mb0, ph0); }
    asm volatile("tcgen05.fence::after_thread_sync;" ::: "memory");

    {
        const int row = m0 + ((wid < 4) ? wid * 32 : 128 + (wid - 4) * 32) + lane;
        const uint32_t dbase = tb + ((wid < 4) ? 0u : 256u);
        #pragma unroll
        for (int c0 = 0; c0 < 256; c0 += 32) {
            float d[32];
            asm volatile(
                "tcgen05.ld.sync.aligned.32x32b.x32.b32 "
                "{%0,%1,%2,%3,%4,%5,%6,%7,%8,%9,%10,%11,%12,%13,%14,%15,"
                "%16,%17,%18,%19,%20,%21,%22,%23,%24,%25,%26,%27,%28,%29,%30,%31}, [%32];"
                : "=f"(d[0]),  "=f"(d[1]),  "=f"(d[2]),  "=f"(d[3]),
                  "=f"(d[4]),  "=f"(d[5]),  "=f"(d[6]),  "=f"(d[7]),
                  "=f"(d[8]),  "=f"(d[9]),  "=f"(d[10]), "=f"(d[11]),
                  "=f"(d[12]), "=f"(d[13]), "=f"(d[14]), "=f"(d[15]),
                  "=f"(d[16]), "=f"(d[17]), "=f"(d[18]), "=f"(d[19]),
                  "=f"(d[20]), "=f"(d[21]), "=f"(d[22]), "=f"(d[23]),
                  "=f"(d[24]), "=f"(d[25]), "=f"(d[26]), "=f"(d[27]),
                  "=f"(d[28]), "=f"(d[29]), "=f"(d[30]), "=f"(d[31])
                : "r"(dbase + c0));
            asm volatile("tcgen05.wait::ld.sync.aligned;" ::: "memory");

            #pragma unroll
            for (int c = 0; c < 32; c += 4) {
                const int n = n0 + c0 + c;
                const float4 bv = *(const float4*)(bias + n);
                float4 v;
                v.x = d[c + 0] + bv.x; v.y = d[c + 1] + bv.y;
                v.z = d[c + 2] + bv.z; v.w = d[c + 3] + bv.w;
                if (MODE == 3) {
                    qkv_write_pair(n,     row, v.x, v.y);
                    qkv_write_pair(n + 2, row, v.z, v.w);
                } else {
                    if (MODE == 1) {
                        const float4 rv = *(const float4*)(res + (size_t)row * N + n);
                        v.x += rv.x; v.y += rv.y; v.z += rv.z; v.w += rv.w;
                    }
                    if (MODE == 2) {
                        v.x = to_tf32(gelu_exact(v.x)); v.y = to_tf32(gelu_exact(v.y));
                        v.z = to_tf32(gelu_exact(v.z)); v.w = to_tf32(gelu_exact(v.w));
                    }
                    *(float4*)(C + (size_t)row * N + n) = v;
                }
            }
        }
    }

    __syncthreads();
    if (tid == 0) {
        asm volatile("mbarrier.inval.shared.b64 [%0];" :: "r"(mb0) : "memory");
        asm volatile("mbarrier.inval.shared.b64 [%0];" :: "r"(mb1) : "memory");
        asm volatile("mbarrier.inval.shared.b64 [%0];" :: "r"(fmb + 0) : "memory");
        asm volatile("mbarrier.inval.shared.b64 [%0];" :: "r"(fmb + 8) : "memory");
        asm volatile("mbarrier.inval.shared.b64 [%0];" :: "r"(fmb + 16) : "memory");
    }
    __syncthreads();
    if (wid == 0)
        asm volatile("tcgen05.dealloc.cta_group::1.sync.aligned.b32 %0, %1;"
                     :: "r"(tb), "r"(512u));

#else
    // ================= mma.sync fallback: 2x2 subtiles of 128x128 =================
    float* As = (float*)gsm;
    float* Bs = As + 2 * 16 * 132;
    #define AS(buf, k, m) As[((buf) * 16 + (k)) * 132 + (m)]
    #define BS(buf, k, n) Bs[((buf) * 16 + (k)) * 132 + (n)]

    const int wm = wid >> 2, wn = wid & 3;
    const int gp = lane >> 2, tg = lane & 3;

    for (int mi = 0; mi < 2; mi++)
    for (int ni = 0; ni < 2; ni++) {
        const int m0 = blockIdx.y * 256 + mi * 128;
        const int n0 = blockIdx.x * 256 + ni * 128;

        float c[4][4][4];
        #pragma unroll
        for (int i = 0; i < 4; i++)
            #pragma unroll
            for (int j = 0; j < 4; j++)
                #pragma unroll
                for (int r = 0; r < 4; r++) c[i][j][r] = 0.f;

        const int KT = K >> 4;
        float4 va[2], vb[2];

        __syncthreads();
        #pragma unroll
        for (int i = 0; i < 2; i++) {
            int idx = tid + i * 256;
            int r = idx >> 2, c4 = (idx & 3) << 2;
            va[i] = *(const float4*)(A  + (size_t)(m0 + r) * K + c4);
            vb[i] = *(const float4*)(Bt + (size_t)(n0 + r) * K + c4);
        }
        #pragma unroll
        for (int i = 0; i < 2; i++) {
            int idx = tid + i * 256;
            int r = idx >> 2, c4 = (idx & 3) << 2;
            AS(0, c4 + 0, r) = to_tf32(va[i].x);
            AS(0, c4 + 1, r) = to_tf32(va[i].y);
            AS(0, c4 + 2, r) = to_tf32(va[i].z);
            AS(0, c4 + 3, r) = to_tf32(va[i].w);
            BS(0, c4 + 0, r) = to_tf32(vb[i].x);
            BS(0, c4 + 1, r) = to_tf32(vb[i].y);
            BS(0, c4 + 2, r) = to_tf32(vb[i].z);
            BS(0, c4 + 3, r) = to_tf32(vb[i].w);
        }
        __syncthreads();

        int cur = 0;
        for (int kt = 0; kt < KT; kt++) {
            if (kt + 1 < KT) {
                #pragma unroll
                for (int i = 0; i < 2; i++) {
                    int idx = tid + i * 256;
                    int r = idx >> 2, c4 = (idx & 3) << 2;
                    va[i] = *(const float4*)(A  + (size_t)(m0 + r) * K + (kt + 1) * 16 + c4);
                    vb[i] = *(const float4*)(Bt + (size_t)(n0 + r) * K + (kt + 1) * 16 + c4);
                }
            }
            #pragma unroll
            for (int ks = 0; ks < 2; ks++) {
                const int k = ks * 8;
                uint32_t a[4][4], b[4][2];
                #pragma unroll
                for (int mf = 0; mf < 4; mf++) {
                    int r0 = wm * 64 + mf * 16;
                    a[mf][0] = __float_as_uint(AS(cur, k + tg,     r0 + gp));
                    a[mf][1] = __float_as_uint(AS(cur, k + tg,     r0 + gp + 8));
                    a[mf][2] = __float_as_uint(AS(cur, k + tg + 4, r0 + gp));
                    a[mf][3] = __float_as_uint(AS(cur, k + tg + 4, r0 + gp + 8));
                }
                #pragma unroll
                for (int nf = 0; nf < 4; nf++) {
                    int c0 = wn * 32 + nf * 8;
                    b[nf][0] = __float_as_uint(BS(cur, k + tg,     c0 + gp));
                    b[nf][1] = __float_as_uint(BS(cur, k + tg + 4, c0 + gp));
                }
                #pragma unroll
                for (int mf = 0; mf < 4; mf++)
                    #pragma unroll
                    for (int nf = 0; nf < 4; nf++)
                        mma_tf32(c[mf][nf], a[mf][0], a[mf][1], a[mf][2], a[mf][3],
                                 b[nf][0], b[nf][1]);
            }
            if (kt + 1 < KT) {
                int nxt = cur ^ 1;
                #pragma unroll
                for (int i = 0; i < 2; i++) {
                    int idx = tid + i * 256;
                    int r = idx >> 2, c4 = (idx & 3) << 2;
                    AS(nxt, c4 + 0, r) = to_tf32(va[i].x);
                    AS(nxt, c4 + 1, r) = to_tf32(va[i].y);
                    AS(nxt, c4 + 2, r) = to_tf32(va[i].z);
                    AS(nxt, c4 + 3, r) = to_tf32(va[i].w);
                    BS(nxt, c4 + 0, r) = to_tf32(vb[i].x);
                    BS(nxt, c4 + 1, r) = to_tf32(vb[i].y);
                    BS(nxt, c4 + 2, r) = to_tf32(vb[i].z);
                    BS(nxt, c4 + 3, r) = to_tf32(vb[i].w);
                }
                __syncthreads();
                cur = nxt;
            }
        }

        #pragma unroll
        for (int mf = 0; mf < 4; mf++) {
            #pragma unroll
            for (int nf = 0; nf < 4; nf++) {
                int col = n0 + wn * 32 + nf * 8 + 2 * tg;
                float bi0 = bias[col], bi1 = bias[col + 1];
                #pragma unroll
                for (int hh = 0; hh < 2; hh++) {
                    int row = m0 + wm * 64 + mf * 16 + gp + hh * 8;
                    float v0 = c[mf][nf][hh * 2 + 0] + bi0;
                    float v1 = c[mf][nf][hh * 2 + 1] + bi1;
                    if (MODE == 3) {
                        qkv_write_pair(col, row, v0, v1);
                    } else {
                        if (MODE == 1) {
                            const float2 rv = *(const float2*)(res + (size_t)row * N + col);
                            v0 += rv.x; v1 += rv.y;
                        }
                        if (MODE == 2) {
                            v0 = to_tf32(gelu_exact(v0));
                            v1 = to_tf32(gelu_exact(v1));
                        }
                        float2 o; o.x = v0; o.y = v1;
                        *(float2*)(C + (size_t)row * N + col) = o;
                    }
                }
            }
        }
    }
    #undef AS
    #undef BS
#endif
}

// ---------------- causal flash attention (unchanged from R8) -------
#define AQ_OFF  0
#define AK_OFF  4608
#define AV_OFF  13824
#define AM_OFF  23040
#define ATTN_SMEM ((23040 + 256) * 4)   // 93184

__global__ __launch_bounds__(256) void attn_kernel(
    const int* __restrict__ amask, float* __restrict__ y)
{
    extern __shared__ uint32_t shw[];
    uint32_t* Qs = shw + AQ_OFF;
    uint32_t* Ks = shw + AK_OFF;
    uint32_t* Vs = shw + AV_OFF;
    int*      mk = (int*)(shw + AM_OFF);

    const int tid = threadIdx.x, lane = tid & 31, w = tid >> 5;
    const int gp = lane >> 2, tg = lane & 3;
    const int h = blockIdx.y;
    const int q0 = (gridDim.x - 1 - blockIdx.x) * 128;
    const int qw = q0 + w * 16;

    {
        const __nv_bfloat16* qb = g_q16 + ((size_t)h * T_SEQ + q0) * 64;
        #pragma unroll
        for (int i = 0; i < 4; i++) {
            int idx = tid + i * 256;
            int r = idx >> 3, ch = idx & 7;
            cp16((uint32_t)__cvta_generic_to_shared(Qs + r * 36 + ch * 4),
                 qb + (size_t)r * 64 + ch * 8);
        }
    }
    asm volatile("cp.async.commit_group;" ::: "memory");

    auto fill_kv = [&](int buf, int kt) {
        const __nv_bfloat16* kbs = g_k16 + ((size_t)h * T_SEQ + kt * 128) * 64;
        #pragma unroll
        for (int i = 0; i < 4; i++) {
            int idx = tid + i * 256;
            int r = idx >> 3, ch = idx & 7;
            cp16((uint32_t)__cvta_generic_to_shared(Ks + buf * 4608 + r * 36 + ch * 4),
                 kbs + (size_t)r * 64 + ch * 8);
        }
        const uint32_t* vbs = g_v16 + ((size_t)h * (T_SEQ / 2) + kt * 64) * 64;
        #pragma unroll
        for (int i = 0; i < 4; i++) {
            int idx = tid + i * 256;
            int pr = idx >> 4, ch = idx & 15;
            cp16((uint32_t)__cvta_generic_to_shared(Vs + buf * 4608 + pr * 72 + ch * 4),
                 vbs + (size_t)pr * 64 + ch * 4);
        }
        if (tid < 32)
            cp16((uint32_t)__cvta_generic_to_shared(mk + buf * 128 + tid * 4),
                 amask + kt * 128 + tid * 4);
    };

    fill_kv(0, 0);
    asm volatile("cp.async.commit_group;" ::: "memory");
    asm volatile("cp.async.wait_group 0;" ::: "memory");
    __syncthreads();

    uint32_t qa[4][4];
    {
        int r0 = w * 16;
        #pragma unroll
        for (int ks = 0; ks < 4; ks++) {
            qa[ks][0] = Qs[(r0 + gp    ) * 36 + 8 * ks + tg    ];
            qa[ks][1] = Qs[(r0 + gp + 8) * 36 + 8 * ks + tg    ];
            qa[ks][2] = Qs[(r0 + gp    ) * 36 + 8 * ks + 4 + tg];
            qa[ks][3] = Qs[(r0 + gp + 8) * 36 + 8 * ks + 4 + tg];
        }
    }

    float m0 = -INFINITY, m1 = -INFINITY, l0 = 0.f, l1 = 0.f;
    float o[8][4];
    #pragma unroll
    for (int nf = 0; nf < 8; nf++)
        #pragma unroll
        for (int r = 0; r < 4; r++) o[nf][r] = 0.f;

    const int ktmax = q0 >> 7;
    const int row0 = qw + gp, row1 = qw + gp + 8;
    int cur = 0;

    for (int kt = 0; kt <= ktmax; kt++) {
        asm volatile("cp.async.wait_group 0;" ::: "memory");
        __syncthreads();

        if (kt < ktmax) {
            fill_kv(cur ^ 1, kt + 1);
            asm volatile("cp.async.commit_group;" ::: "memory");
        }

        const uint32_t* K = Ks + cur * 4608;
        const uint32_t* V = Vs + cur * 4608;
        const int*      M = mk + cur * 128;
        const bool diag = (kt == ktmax);

        float sc[16][4];
        #pragma unroll
        for (int nf = 0; nf < 16; nf++)
            #pragma unroll
            for (int r = 0; r < 4; r++) sc[nf][r] = 0.f;

        #pragma unroll
        for (int ks = 0; ks < 4; ks++) {
            #pragma unroll
            for (int nf = 0; nf < 16; nf++) {
                uint32_t b0 = K[(nf * 8 + gp) * 36 + 8 * ks + tg    ];
                uint32_t b1 = K[(nf * 8 + gp) * 36 + 8 * ks + 4 + tg];
                mma_bf16(sc[nf], qa[ks][0], qa[ks][1], qa[ks][2], qa[ks][3], b0, b1);
            }
        }

        float tm0 = -INFINITY, tm1 = -INFINITY;
        if (diag) {
            #pragma unroll
            for (int nf = 0; nf < 16; nf++) {
                int cl = nf * 8 + 2 * tg;
                int c  = kt * 128 + cl;
                bool mk0 = M[cl] != 0, mk1 = M[cl + 1] != 0;
                float s0 = sc[nf][0], s1 = sc[nf][1];
                float s2 = sc[nf][2], s3 = sc[nf][3];
                s0 = (c     <= row0 && mk0) ? s0 : -INFINITY;
                s1 = (c + 1 <= row0 && mk1) ? s1 : -INFINITY;
                s2 = (c     <= row1 && mk0) ? s2 : -INFINITY;
                s3 = (c + 1 <= row1 && mk1) ? s3 : -INFINITY;
                sc[nf][0] = s0; sc[nf][1] = s1; sc[nf][2] = s2; sc[nf][3] = s3;
                tm0 = fmaxf(tm0, fmaxf(s0, s1));
                tm1 = fmaxf(tm1, fmaxf(s2, s3));
            }
        } else {
            #pragma unroll
            for (int nf = 0; nf < 16; nf++) {
                int cl = nf * 8 + 2 * tg;
                bool mk0 = M[cl] != 0, mk1 = M[cl + 1] != 0;
                float s0 = mk0 ? sc[nf][0] : -INFINITY;
                float s1 = mk1 ? sc[nf][1] : -INFINITY;
                float s2 = mk0 ? sc[nf][2] : -INFINITY;
                float s3 = mk1 ? sc[nf][3] : -INFINITY;
                sc[nf][0] = s0; sc[nf][1] = s1; sc[nf][2] = s2; sc[nf][3] = s3;
                tm0 = fmaxf(tm0, fmaxf(s0, s1));
                tm1 = fmaxf(tm1, fmaxf(s2, s3));
            }
        }
        tm0 = fmaxf(tm0, __shfl_xor_sync(0xffffffffu, tm0, 1));
        tm0 = fmaxf(tm0, __shfl_xor_sync(0xffffffffu, tm0, 2));
        tm1 = fmaxf(tm1, __shfl_xor_sync(0xffffffffu, tm1, 1));
        tm1 = fmaxf(tm1, __shfl_xor_sync(0xffffffffu, tm1, 2));

        float nm0 = fmaxf(m0, tm0), nm1 = fmaxf(m1, tm1);
        float ne0 = fmaxf(nm0, -1e30f), ne1 = fmaxf(nm1, -1e30f);
        float al0 = ex2(m0 - ne0), al1 = ex2(m1 - ne1);
        m0 = nm0; m1 = nm1;

        float ps0 = 0.f, ps1 = 0.f;
        #pragma unroll
        for (int nf = 0; nf < 16; nf++) {
            float p0 = ex2(sc[nf][0] - ne0);
            float p1 = ex2(sc[nf][1] - ne0);
            float p2 = ex2(sc[nf][2] - ne1);
            float p3 = ex2(sc[nf][3] - ne1);
            sc[nf][0] = p0; sc[nf][1] = p1; sc[nf][2] = p2; sc[nf][3] = p3;
            ps0 += p0 + p1; ps1 += p2 + p3;
        }
        ps0 += __shfl_xor_sync(0xffffffffu, ps0, 1);
        ps0 += __shfl_xor_sync(0xffffffffu, ps0, 2);
        ps1 += __shfl_xor_sync(0xffffffffu, ps1, 1);
        ps1 += __shfl_xor_sync(0xffffffffu, ps1, 2);
        l0 = l0 * al0 + ps0;
        l1 = l1 * al1 + ps1;

        #pragma unroll
        for (int nf = 0; nf < 8; nf++) {
            o[nf][0] *= al0; o[nf][1] *= al0;
            o[nf][2] *= al1; o[nf][3] *= al1;
        }

        #pragma unroll
        for (int ks = 0; ks < 8; ks++) {
            uint32_t pa0 = packbf(sc[2*ks  ][1], sc[2*ks  ][0]);
            uint32_t pa1 = packbf(sc[2*ks  ][3], sc[2*ks  ][2]);
            uint32_t pa2 = packbf(sc[2*ks+1][1], sc[2*ks+1][0]);
            uint32_t pa3 = packbf(sc[2*ks+1][3], sc[2*ks+1][2]);
            #pragma unroll
            for (int nf = 0; nf < 8; nf++) {
                uint32_t b0 = V[(8 * ks + tg    ) * 72 + nf * 8 + gp];
                uint32_t b1 = V[(8 * ks + 4 + tg) * 72 + nf * 8 + gp];
                mma_bf16(o[nf], pa0, pa1, pa2, pa3, b0, b1);
            }
        }
        cur ^= 1;
    }

    float il0 = 1.0f / fmaxf(l0, 1e-30f);
    float il1 = 1.0f / fmaxf(l1, 1e-30f);
    #pragma unroll
    for (int nf = 0; nf < 8; nf++) {
        int col = h * HDIM + nf * 8 + 2 * tg;
        float2 v0; v0.x = to_tf32(o[nf][0] * il0); v0.y = to_tf32(o[nf][1] * il0);
        *(float2*)(y + (size_t)row0 * DM + col) = v0;
        float2 v1; v1.x = to_tf32(o[nf][2] * il1); v1.y = to_tf32(o[nf][3] * il1);
        *(float2*)(y + (size_t)row1 * DM + col) = v1;
    }
}

// ---------------- launcher ----------------
extern "C" void kernel_launch(void* const* d_in, const int* in_sizes, int n_in,
                              void* d_out, int out_size)
{
    const float* x     = (const float*)d_in[0];
    const int*   amask = (const int*)  d_in[1];
    const float* ln1g  = (const float*)d_in[2];
    const float* ln1b  = (const float*)d_in[3];
    const float* Wqkv  = (const float*)d_in[4];
    const float* bqkv  = (const float*)d_in[5];
    const float* Wo    = (const float*)d_in[6];
    const float* bo    = (const float*)d_in[7];
    const float* ln2g  = (const float*)d_in[8];
    const float* ln2b  = (const float*)d_in[9];
    const float* W1    = (const float*)d_in[10];
    const float* b1    = (const float*)d_in[11];
    const float* W2    = (const float*)d_in[12];
    const float* b2    = (const float*)d_in[13];
    float* out = (float*)d_out;

    void *p_ln, *p_y, *p_x2, *p_ff;
    void *p_wqkv, *p_wo, *p_w1, *p_w2;
    cudaGetSymbolAddress(&p_ln,   g_ln);
    cudaGetSymbolAddress(&p_y,    g_y);
    cudaGetSymbolAddress(&p_x2,   g_x2);
    cudaGetSymbolAddress(&p_ff,   g_ff);
    cudaGetSymbolAddress(&p_wqkv, g_wt_qkv);
    cudaGetSymbolAddress(&p_wo,   g_wt_o);
    cudaGetSymbolAddress(&p_w1,   g_wt_1);
    cudaGetSymbolAddress(&p_w2,   g_wt_2);

    cudaFuncSetAttribute(attn_kernel,
        cudaFuncAttributeMaxDynamicSharedMemorySize, ATTN_SMEM);
    cudaFuncSetAttribute(gemm_any<1>,
        cudaFuncAttributeMaxDynamicSharedMemorySize, G_SMEM);
    cudaFuncSetAttribute(gemm_any<2>,
        cudaFuncAttributeMaxDynamicSharedMemorySize, G_SMEM);
    cudaFuncSetAttribute(gemm_any<3>,
        cudaFuncAttributeMaxDynamicSharedMemorySize, G_SMEM);

    // 0. weight transposes (tf32-rounded, [N,K]) — single launch
    transpose_all<<<12288, 256>>>(Wqkv, Wo, W1, W2,
                                  (float*)p_wqkv, (float*)p_wo,
                                  (float*)p_w1, (float*)p_w2);

    // 1. LN1
    ln_kernel<<<T_SEQ, 256>>>(x, ln1g, ln1b, (float*)p_ln);
    // 2. QKV -> bf16 Q/K/V buffers (Q pre-scaled by log2e/8)
    gemm_any<3><<<dim3(12, 16), 256, G_SMEM>>>((float*)p_ln, (float*)p_wqkv, bqkv, nullptr,
                                               nullptr, T_SEQ, 3 * DM, DM);
    // 3. attention (bf16 mma, 128-key tiles, exp2 softmax)
    attn_kernel<<<dim3(32, 16), 256, ATTN_SMEM>>>(amask, (float*)p_y);
    // 4. x2 = x + y @ W_o + b_o
    gemm_any<1><<<dim3(4, 16), 256, G_SMEM>>>((float*)p_y, (float*)p_wo, bo, x,
                                              (float*)p_x2, T_SEQ, DM, DM);
    // 5. LN2
    ln_kernel<<<T_SEQ, 256>>>((float*)p_x2, ln2g, ln2b, (float*)p_ln);
    // 6. ff = gelu(h2 @ W1 + b1)
    gemm_any<2><<<dim3(16, 16), 256, G_SMEM>>>((float*)p_ln, (float*)p_w1, b1, nullptr,
                                               (float*)p_ff, T_SEQ, DFF, DM);
    // 7. out = x2 + ff @ W2 + b2
    gemm_any<1><<<dim3(4, 16), 256, G_SMEM>>>((float*)p_ff, (float*)p_w2, b2, (float*)p_x2,
                                              out, T_SEQ, DM, DFF);
}

// round 11
// speedup vs baseline: 1.1996x; 1.1909x over previous
#include <cuda_runtime.h>
#include <cuda_bf16.h>
#include <cstdint>
#include <math.h>

#define T_SEQ   4096
#define DM      1024
#define DFF     4096
#define NHEADS  16
#define HDIM    64
#define LN_EPS  1e-5f

// ---- arch-specific feature gate: tcgen05 only exists on sm_10xa/f targets ----
#if defined(__CUDA_ARCH__)
#  if defined(__CUDA_ARCH_FEAT_SM103_ALL) || defined(__CUDA_ARCH_FEAT_SM100_ALL) || defined(__CUDA_ARCH_FEAT_SM101_ALL)
#    define GEMM_TC 1
#  elif defined(__CUDA_ARCH_SPECIFIC__)
#    define GEMM_TC ((__CUDA_ARCH_SPECIFIC__ >= 1000) ? 1 : 0)
#  elif defined(__CUDA_ARCH_FAMILY_SPECIFIC__)
#    define GEMM_TC ((__CUDA_ARCH_FAMILY_SPECIFIC__ >= 1000) ? 1 : 0)
#  else
#    define GEMM_TC 0
#  endif
#else
#  define GEMM_TC 0
#endif

// ---------------- scratch (static device globals; no allocation) ----------------
static __device__ float g_ln [T_SEQ * DM];
static __device__ float g_y  [T_SEQ * DM];
static __device__ float g_x2 [T_SEQ * DM];
static __device__ float g_ff [T_SEQ * DFF];
// transposed (tf32-rounded) weights, [N, K] K-major
static __device__ float g_wt_qkv[3 * DM * DM];
static __device__ float g_wt_o  [DM * DM];
static __device__ float g_wt_1  [DFF * DM];
static __device__ float g_wt_2  [DM * DFF];
// bf16 attention operands written by the QKV GEMM epilogue
static __device__ __nv_bfloat16 g_q16[NHEADS * T_SEQ * HDIM];     // [h][t][d], scaled log2e/8
static __device__ __nv_bfloat16 g_k16[NHEADS * T_SEQ * HDIM];     // [h][t][d]
static __device__ uint32_t      g_v16[NHEADS * (T_SEQ/2) * HDIM]; // [h][t/2][d] pair-packed

#define QSCALE 0.18033688011112042f   // (1/8) * log2(e)

// ---------------- helpers ----------------
__device__ __forceinline__ float to_tf32(float x) {
    uint32_t u;
    asm("cvt.rna.tf32.f32 %0, %1;" : "=r"(u) : "f"(x));
    return __uint_as_float(u);
}

__device__ __forceinline__ uint32_t packbf(float hi, float lo) {
    uint32_t r;
    asm("cvt.rn.bf16x2.f32 %0, %1, %2;" : "=r"(r) : "f"(hi), "f"(lo));
    return r;
}

__device__ __forceinline__ float ex2(float x) {
    float r;
    asm("ex2.approx.f32 %0, %1;" : "=f"(r) : "f"(x));
    return r;
}

__device__ __forceinline__ void mma_tf32(float* c,
    uint32_t a0, uint32_t a1, uint32_t a2, uint32_t a3,
    uint32_t b0, uint32_t b1)
{
    asm volatile(
        "mma.sync.aligned.m16n8k8.row.col.f32.tf32.tf32.f32 "
        "{%0,%1,%2,%3}, {%4,%5,%6,%7}, {%8,%9}, {%0,%1,%2,%3};\n"
        : "+f"(c[0]), "+f"(c[1]), "+f"(c[2]), "+f"(c[3])
        : "r"(a0), "r"(a1), "r"(a2), "r"(a3), "r"(b0), "r"(b1));
}

__device__ __forceinline__ void mma_bf16(float* c,
    uint32_t a0, uint32_t a1, uint32_t a2, uint32_t a3,
    uint32_t b0, uint32_t b1)
{
    asm volatile(
        "mma.sync.aligned.m16n8k16.row.col.f32.bf16.bf16.f32 "
        "{%0,%1,%2,%3}, {%4,%5,%6,%7}, {%8,%9}, {%0,%1,%2,%3};\n"
        : "+f"(c[0]), "+f"(c[1]), "+f"(c[2]), "+f"(c[3])
        : "r"(a0), "r"(a1), "r"(a2), "r"(a3), "r"(b0), "r"(b1));
}

__device__ __forceinline__ void cp16(uint32_t dst, const void* src) {
    asm volatile("cp.async.ca.shared.global [%0], [%1], 16;\n"
                 :: "r"(dst), "l"(src));
}

__device__ __forceinline__ float gelu_exact(float v) {
    return 0.5f * v * (1.0f + erff(v * 0.70710678118654752440f));
}

// ---------------- merged weight transpose + tf32 round (one launch) ----------------
__global__ __launch_bounds__(256) void transpose_all(
    const float* __restrict__ Wqkv, const float* __restrict__ Wo,
    const float* __restrict__ W1,   const float* __restrict__ W2,
    float* __restrict__ oqkv, float* __restrict__ oo,
    float* __restrict__ o1,   float* __restrict__ o2)
{
    __shared__ float t[32][33];
    int tb = blockIdx.x;
    const float* in; float* out; int R, C, txw;
    if (tb < 3072)      { in = Wqkv; out = oqkv; R = 1024; C = 3072; txw = 96; }
    else if (tb < 4096) { tb -= 3072; in = Wo; out = oo; R = 1024; C = 1024; txw = 32; }
    else if (tb < 8192) { tb -= 4096; in = W1; out = o1; R = 1024; C = 4096; txw = 128; }
    else                { tb -= 8192; in = W2; out = o2; R = 4096; C = 1024; txw = 32; }
    int bx = (tb % txw) * 32, by = (tb / txw) * 32;
    int x = threadIdx.x & 31, y = threadIdx.x >> 5;
    #pragma unroll
    for (int i = 0; i < 32; i += 8)
        t[y + i][x] = in[(size_t)(by + y + i) * C + bx + x];
    __syncthreads();
    #pragma unroll
    for (int i = 0; i < 32; i += 8)
        out[(size_t)(bx + y + i) * R + by + x] = to_tf32(t[x][y + i]);
}

// ---------------- LayerNorm (writes tf32-rounded output) ----------------
__global__ __launch_bounds__(256) void ln_kernel(
    const float* __restrict__ x, const float* __restrict__ g,
    const float* __restrict__ b, float* __restrict__ out)
{
    int row = blockIdx.x;
    int tid = threadIdx.x;
    const float4 v = ((const float4*)(x + (size_t)row * DM))[tid];
    float s  = v.x + v.y + v.z + v.w;
    float sq = v.x * v.x + v.y * v.y + v.z * v.z + v.w * v.w;
    #pragma unroll
    for (int o = 16; o; o >>= 1) {
        s  += __shfl_xor_sync(0xffffffffu, s,  o);
        sq += __shfl_xor_sync(0xffffffffu, sq, o);
    }
    __shared__ float ss[8], ssq[8];
    __shared__ float mean_s, inv_s;
    int w = tid >> 5, l = tid & 31;
    if (l == 0) { ss[w] = s; ssq[w] = sq; }
    __syncthreads();
    if (tid == 0) {
        float st = 0.f, sqt = 0.f;
        #pragma unroll
        for (int i = 0; i < 8; i++) { st += ss[i]; sqt += ssq[i]; }
        float mean = st * (1.0f / DM);
        float var  = sqt * (1.0f / DM) - mean * mean;
        mean_s = mean;
        inv_s  = rsqrtf(var + LN_EPS);
    }
    __syncthreads();
    float mean = mean_s, inv = inv_s;
    const float4 gv = ((const float4*)g)[tid];
    const float4 bv = ((const float4*)b)[tid];
    float4 o;
    o.x = to_tf32((v.x - mean) * inv * gv.x + bv.x);
    o.y = to_tf32((v.y - mean) * inv * gv.y + bv.y);
    o.z = to_tf32((v.z - mean) * inv * gv.z + bv.z);
    o.w = to_tf32((v.w - mean) * inv * gv.w + bv.w);
    ((float4*)(out + (size_t)row * DM))[tid] = o;
}

// ---------------- unified GEMM: C[M,N] = A[M,K] @ Bt[N,K]^T + epilogue --------
// Tile TM x 256 (TM = 128 or 256), 256 threads. grid = (N/256, M/TM).
// TC path: tcgen05 SS tf32, BK=32, 3-slot ring, mbarrier dataflow (noinc arrive).
// Fallback: proven mma.sync 128x128 body, (TM/128)x2 subtiles.
#define GS        3
#define G_BASE    1024
#define G_SMEM_T(TM) (G_BASE + GS * ((TM) * 128 + 32768))

#if GEMM_TC
__device__ __forceinline__ bool elect_one() {
    uint32_t pred;
    asm volatile(
        "{\n\t.reg .pred p;\n\t"
        "elect.sync _|p, 0xFFFFFFFF;\n\t"
        "selp.b32 %0, 1, 0, p;\n\t}"
        : "=r"(pred));
    return pred != 0;
}
__device__ __forceinline__ uint64_t make_desc(uint32_t addr) {
    const uint64_t base = (2ULL << 61) | (1ULL << 46) | (64ULL << 32) | (1ULL << 16);
    return base | ((uint64_t)(addr >> 4) & 0x3FFF);
}
__device__ __forceinline__ void tc_mma_tf32_ss(uint32_t d, uint64_t ad, uint64_t bd,
                                               uint32_t idesc, bool acc)
{
    uint32_t en = acc ? 1u : 0u;
    asm volatile(
        "{\n\t.reg .pred p;\n\t"
        "setp.ne.u32 p, %4, 0;\n\t"
        "tcgen05.mma.cta_group::1.kind::tf32 [%0], %1, %2, %3, {%5, %5, %5, %5}, p;\n\t}"
        :: "r"(d), "l"(ad), "l"(bd), "r"(idesc), "r"(en), "r"(0u)
        : "memory");
}
#define MBAR_INIT(a, c) \
    asm volatile("mbarrier.init.shared.b64 [%0], %1;" :: "r"(a), "r"(c) : "memory")
#define MBAR_WAIT(a, par) do { \
    uint32_t _m = (a), _p = (par), _d; \
    asm volatile("{\n\t.reg .pred p;\n\t" \
        "mbarrier.try_wait.parity.acquire.cta.shared::cta.b64 p, [%1], %2;\n\t" \
        "selp.b32 %0, 1, 0, p;\n\t}" : "=r"(_d) : "r"(_m), "r"(_p) : "memory"); \
    if (!_d) { \
        asm volatile("{\n\t.reg .pred P1;\n\t" \
            "WL_%=:\n\t" \
            "mbarrier.try_wait.parity.acquire.cta.shared::cta.b64 P1, [%0], %1, 0x989680;\n\t" \
            "@P1 bra.uni WD_%=;\n\t" \
            "bra.uni WL_%=;\n\t" \
            "WD_%=:\n\t}" :: "r"(_m), "r"(_p) : "memory"); \
    } \
} while (0)
#define CPASYNC_MBAR_ARRIVE_NOINC(a) \
    asm volatile("cp.async.mbarrier.arrive.noinc.shared.b64 [%0];" :: "r"(a) : "memory")
#endif  // GEMM_TC

// epilogue write helper for MODE 3 (pair of adjacent columns, one row)
__device__ __forceinline__ void qkv_write_pair(int n, int row, float v0, float v1) {
    if (n < 1024) {
        int hd = n >> 6, d = n & 63;
        ((uint32_t*)g_q16)[(((size_t)hd * T_SEQ + row) * 64 + d) >> 1]
            = packbf(v1 * QSCALE, v0 * QSCALE);
    } else if (n < 2048) {
        int hd = (n - 1024) >> 6, d = (n - 1024) & 63;
        ((uint32_t*)g_k16)[(((size_t)hd * T_SEQ + row) * 64 + d) >> 1]
            = packbf(v1, v0);
    } else {
        int hd = (n - 2048) >> 6, d = (n - 2048) & 63;
        __nv_bfloat16* vp = (__nv_bfloat16*)g_v16;
        size_t wi = ((size_t)hd * (T_SEQ / 2) + (row >> 1)) * 64 + d;
        vp[wi * 2 + (row & 1)]       = __float2bfloat16(v0);
        vp[(wi + 1) * 2 + (row & 1)] = __float2bfloat16(v1);
    }
}

template<int MODE, int TM>
__global__ __launch_bounds__(256)
void gemm_any(const float* __restrict__ A, const float* __restrict__ Bt,
              const float* __restrict__ bias, const float* __restrict__ res,
              float* __restrict__ C, int M, int N, int K)
{
    extern __shared__ __align__(1024) char gsm[];
    const int tid = threadIdx.x, wid = tid >> 5, lane = tid & 31;

#if GEMM_TC
    // ================= tcgen05 path (TM x 256 tile, mbarrier dataflow) ========
    constexpr int A_TILE = TM * 128;              // bytes per A stage
    constexpr int STAGE  = A_TILE + 32768;
    constexpr int TCOLS  = (TM == 256) ? 512 : 256;
    const int m0 = blockIdx.y * TM, n0 = blockIdx.x * 256;
    const uint32_t sb = (uint32_t)__cvta_generic_to_shared(gsm);
    const uint32_t mb0 = sb + 16, mb1 = sb + 24;
    const uint32_t fmb = sb + 32;      // 3 fill mbars at +32, +40, +48

    if (wid == 0) {
        asm volatile("tcgen05.alloc.cta_group::1.sync.aligned.shared::cta.b32 [%0], %1;"
                     :: "r"(sb), "r"((uint32_t)TCOLS) : "memory");
        asm volatile("tcgen05.relinquish_alloc_permit.cta_group::1.sync.aligned;");
    }
    if (tid == 0) {
        MBAR_INIT(mb0, 1); MBAR_INIT(mb1, 1);
        MBAR_INIT(fmb + 0, 256); MBAR_INIT(fmb + 8, 256); MBAR_INIT(fmb + 16, 256);
    }
    __syncthreads();
    uint32_t tb;
    asm volatile("ld.shared.b32 %0, [%1];" : "=r"(tb) : "r"(sb));

    const int KT = K >> 5;

    auto fill = [&](int slot, int ktile) {
        uint32_t s = sb + G_BASE + slot * STAGE;
        const float* Ap = A  + (size_t)m0 * K + ktile * 32;
        const float* Bp = Bt + (size_t)n0 * K + ktile * 32;
        #pragma unroll
        for (int i = 0; i < TM / 32; i++) {
            int idx = tid + i * 256;
            int r = idx >> 3, ch = (idx & 7) * 16;
            uint32_t byte = (uint32_t)(r * 128 + ch);
            uint32_t sw = byte ^ ((byte >> 3) & 0x70);
            cp16(s + sw, Ap + (size_t)r * K + (ch >> 2));
        }
        #pragma unroll
        for (int i = 0; i < 8; i++) {
            int idx = tid + i * 256;
            int r = idx >> 3, ch = (idx & 7) * 16;
            uint32_t byte = (uint32_t)(r * 128 + ch);
            uint32_t sw = byte ^ ((byte >> 3) & 0x70);
            cp16(s + A_TILE + sw, Bp + (size_t)r * K + (ch >> 2));
        }
        CPASYNC_MBAR_ARRIVE_NOINC(fmb + slot * 8);
    };

    #pragma unroll
    for (int st = 0; st < GS - 1; st++) fill(st, st);

    const uint32_t idesc = (1u << 4) | (2u << 7) | (2u << 10)
                         | (32u << 17) | (8u << 24);

    int ph0 = 0, ph1 = 0;
    for (int kt = 0; kt < KT; kt++) {
        if (wid == 0) {
            int slot = kt % GS;
            int fph = (kt / GS) & 1;
            MBAR_WAIT(fmb + slot * 8, fph);
            asm volatile("fence.proxy.async.shared::cta;" ::: "memory");
            if (elect_one()) {
                uint32_t s = sb + G_BASE + slot * STAGE;
                uint64_t ad = make_desc(s);
                uint64_t bd = make_desc(s + A_TILE);
                #pragma unroll
                for (int ks = 0; ks < 4; ks++) {
                    bool acc = (kt > 0) || (ks > 0);
                    tc_mma_tf32_ss(tb, ad + ks * 2, bd + ks * 2, idesc, acc);
                    if (TM == 256)
                        tc_mma_tf32_ss(tb + 256, ad + 1024 + ks * 2, bd + ks * 2, idesc, acc);
                }
                uint32_t mb = (kt & 1) ? mb1 : mb0;
                asm volatile(
                    "tcgen05.commit.cta_group::1.mbarrier::arrive::one.shared::cluster.b64 [%0];"
                    :: "r"(mb) : "memory");
            }
        }

        if (kt >= 1) {
            if ((kt - 1) & 1) { MBAR_WAIT(mb1, ph1); ph1 ^= 1; }
            else              { MBAR_WAIT(mb0, ph0); ph0 ^= 1; }
        }
        if (kt + GS - 1 < KT) fill((kt + GS - 1) % GS, kt + GS - 1);
    }

    if ((KT - 1) & 1) { MBAR_WAIT(mb1, ph1); }
    else              { MBAR_WAIT(mb0, ph0); }
    asm volatile("tcgen05.fence::after_thread_sync;" ::: "memory");

    {
        int row; uint32_t dbase; int cstart;
        if (TM == 256) {
            row = m0 + ((wid < 4) ? wid * 32 : 128 + (wid - 4) * 32) + lane;
            dbase = tb + ((wid < 4) ? 0u : 256u);
            cstart = 0;
        } else {
            row = m0 + (wid & 3) * 32 + lane;
            dbase = tb;
            cstart = (wid < 4) ? 0 : 128;
        }
        const int cspan = (TM == 256) ? 256 : 128;
        #pragma unroll
        for (int ci = 0; ci < 256; ci += 32) {
            if (ci >= cspan) break;
            const int c0 = cstart + ci;
            float d[32];
            asm volatile(
                "tcgen05.ld.sync.aligned.32x32b.x32.b32 "
                "{%0,%1,%2,%3,%4,%5,%6,%7,%8,%9,%10,%11,%12,%13,%14,%15,"
                "%16,%17,%18,%19,%20,%21,%22,%23,%24,%25,%26,%27,%28,%29,%30,%31}, [%32];"
                : "=f"(d[0]),  "=f"(d[1]),  "=f"(d[2]),  "=f"(d[3]),
                  "=f"(d[4]),  "=f"(d[5]),  "=f"(d[6]),  "=f"(d[7]),
                  "=f"(d[8]),  "=f"(d[9]),  "=f"(d[10]), "=f"(d[11]),
                  "=f"(d[12]), "=f"(d[13]), "=f"(d[14]), "=f"(d[15]),
                  "=f"(d[16]), "=f"(d[17]), "=f"(d[18]), "=f"(d[19]),
                  "=f"(d[20]), "=f"(d[21]), "=f"(d[22]), "=f"(d[23]),
                  "=f"(d[24]), "=f"(d[25]), "=f"(d[26]), "=f"(d[27]),
                  "=f"(d[28]), "=f"(d[29]), "=f"(d[30]), "=f"(d[31])
                : "r"(dbase + c0));
            asm volatile("tcgen05.wait::ld.sync.aligned;" ::: "memory");

            #pragma unroll
            for (int c = 0; c < 32; c += 4) {
                const int n = n0 + c0 + c;
                const float4 bv = *(const float4*)(bias + n);
                float4 v;
                v.x = d[c + 0] + bv.x; v.y = d[c + 1] + bv.y;
                v.z = d[c + 2] + bv.z; v.w = d[c + 3] + bv.w;
                if (MODE == 3) {
                    qkv_write_pair(n,     row, v.x, v.y);
                    qkv_write_pair(n + 2, row, v.z, v.w);
                } else {
                    if (MODE == 1) {
                        const float4 rv = *(const float4*)(res + (size_t)row * N + n);
                        v.x += rv.x; v.y += rv.y; v.z += rv.z; v.w += rv.w;
                    }
                    if (MODE == 2) {
                        v.x = to_tf32(gelu_exact(v.x)); v.y = to_tf32(gelu_exact(v.y));
                        v.z = to_tf32(gelu_exact(v.z)); v.w = to_tf32(gelu_exact(v.w));
                    }
                    *(float4*)(C + (size_t)row * N + n) = v;
                }
            }
        }
    }

    __syncthreads();
    if (tid == 0) {
        asm volatile("mbarrier.inval.shared.b64 [%0];" :: "r"(mb0) : "memory");
        asm volatile("mbarrier.inval.shared.b64 [%0];" :: "r"(mb1) : "memory");
        asm volatile("mbarrier.inval.shared.b64 [%0];" :: "r"(fmb + 0) : "memory");
        asm volatile("mbarrier.inval.shared.b64 [%0];" :: "r"(fmb + 8) : "memory");
        asm volatile("mbarrier.inval.shared.b64 [%0];" :: "r"(fmb + 16) : "memory");
    }
    __syncthreads();
    if (wid == 0)
        asm volatile("tcgen05.dealloc.cta_group::1.sync.aligned.b32 %0, %1;"
                     :: "r"(tb), "r"((uint32_t)TCOLS));

#else
    // ================= mma.sync fallback: (TM/128)x2 subtiles of 128x128 ==========
    float* As = (float*)gsm;
    float* Bs = As + 2 * 16 * 132;
    #define AS(buf, k, m) As[((buf) * 16 + (k)) * 132 + (m)]
    #define BS(buf, k, n) Bs[((buf) * 16 + (k)) * 132 + (n)]

    const int wm = wid >> 2, wn = wid & 3;
    const int gp = lane >> 2, tg = lane & 3;

    for (int mi = 0; mi < TM / 128; mi++)
    for (int ni = 0; ni < 2; ni++) {
        const int m0 = blockIdx.y * TM + mi * 128;
        const int n0 = blockIdx.x * 256 + ni * 128;

        float c[4][4][4];
        #pragma unroll
        for (int i = 0; i < 4; i++)
            #pragma unroll
            for (int j = 0; j < 4; j++)
                #pragma unroll
                for (int r = 0; r < 4; r++) c[i][j][r] = 0.f;

        const int KT = K >> 4;
        float4 va[2], vb[2];

        __syncthreads();
        #pragma unroll
        for (int i = 0; i < 2; i++) {
            int idx = tid + i * 256;
            int r = idx >> 2, c4 = (idx & 3) << 2;
            va[i] = *(const float4*)(A  + (size_t)(m0 + r) * K + c4);
            vb[i] = *(const float4*)(Bt + (size_t)(n0 + r) * K + c4);
        }
        #pragma unroll
        for (int i = 0; i < 2; i++) {
            int idx = tid + i * 256;
            int r = idx >> 2, c4 = (idx & 3) << 2;
            AS(0, c4 + 0, r) = to_tf32(va[i].x);
            AS(0, c4 + 1, r) = to_tf32(va[i].y);
            AS(0, c4 + 2, r) = to_tf32(va[i].z);
            AS(0, c4 + 3, r) = to_tf32(va[i].w);
            BS(0, c4 + 0, r) = to_tf32(vb[i].x);
            BS(0, c4 + 1, r) = to_tf32(vb[i].y);
            BS(0, c4 + 2, r) = to_tf32(vb[i].z);
            BS(0, c4 + 3, r) = to_tf32(vb[i].w);
        }
        __syncthreads();

        int cur = 0;
        for (int kt = 0; kt < KT; kt++) {
            if (kt + 1 < KT) {
                #pragma unroll
                for (int i = 0; i < 2; i++) {
                    int idx = tid + i * 256;
                    int r = idx >> 2, c4 = (idx & 3) << 2;
                    va[i] = *(const float4*)(A  + (size_t)(m0 + r) * K + (kt + 1) * 16 + c4);
                    vb[i] = *(const float4*)(Bt + (size_t)(n0 + r) * K + (kt + 1) * 16 + c4);
                }
            }
            #pragma unroll
            for (int ks = 0; ks < 2; ks++) {
                const int k = ks * 8;
                uint32_t a[4][4], b[4][2];
                #pragma unroll
                for (int mf = 0; mf < 4; mf++) {
                    int r0 = wm * 64 + mf * 16;
                    a[mf][0] = __float_as_uint(AS(cur, k + tg,     r0 + gp));
                    a[mf][1] = __float_as_uint(AS(cur, k + tg,     r0 + gp + 8));
                    a[mf][2] = __float_as_uint(AS(cur, k + tg + 4, r0 + gp));
                    a[mf][3] = __float_as_uint(AS(cur, k + tg + 4, r0 + gp + 8));
                }
                #pragma unroll
                for (int nf = 0; nf < 4; nf++) {
                    int c0 = wn * 32 + nf * 8;
                    b[nf][0] = __float_as_uint(BS(cur, k + tg,     c0 + gp));
                    b[nf][1] = __float_as_uint(BS(cur, k + tg + 4, c0 + gp));
                }
                #pragma unroll
                for (int mf = 0; mf < 4; mf++)
                    #pragma unroll
                    for (int nf = 0; nf < 4; nf++)
                        mma_tf32(c[mf][nf], a[mf][0], a[mf][1], a[mf][2], a[mf][3],
                                 b[nf][0], b[nf][1]);
            }
            if (kt + 1 < KT) {
                int nxt = cur ^ 1;
                #pragma unroll
                for (int i = 0; i < 2; i++) {
                    int idx = tid + i * 256;
                    int r = idx >> 2, c4 = (idx & 3) << 2;
                    AS(nxt, c4 + 0, r) = to_tf32(va[i].x);
                    AS(nxt, c4 + 1, r) = to_tf32(va[i].y);
                    AS(nxt, c4 + 2, r) = to_tf32(va[i].z);
                    AS(nxt, c4 + 3, r) = to_tf32(va[i].w);
                    BS(nxt, c4 + 0, r) = to_tf32(vb[i].x);
                    BS(nxt, c4 + 1, r) = to_tf32(vb[i].y);
                    BS(nxt, c4 + 2, r) = to_tf32(vb[i].z);
                    BS(nxt, c4 + 3, r) = to_tf32(vb[i].w);
                }
                __syncthreads();
                cur = nxt;
            }
        }

        #pragma unroll
        for (int mf = 0; mf < 4; mf++) {
            #pragma unroll
            for (int nf = 0; nf < 4; nf++) {
                int col = n0 + wn * 32 + nf * 8 + 2 * tg;
                float bi0 = bias[col], bi1 = bias[col + 1];
                #pragma unroll
                for (int hh = 0; hh < 2; hh++) {
                    int row = m0 + wm * 64 + mf * 16 + gp + hh * 8;
                    float v0 = c[mf][nf][hh * 2 + 0] + bi0;
                    float v1 = c[mf][nf][hh * 2 + 1] + bi1;
                    if (MODE == 3) {
                        qkv_write_pair(col, row, v0, v1);
                    } else {
                        if (MODE == 1) {
                            const float2 rv = *(const float2*)(res + (size_t)row * N + col);
                            v0 += rv.x; v1 += rv.y;
                        }
                        if (MODE == 2) {
                            v0 = to_tf32(gelu_exact(v0));
                            v1 = to_tf32(gelu_exact(v1));
                        }
                        float2 o; o.x = v0; o.y = v1;
                        *(float2*)(C + (size_t)row * N + col) = o;
                    }
                }
            }
        }
    }
    #undef AS
    #undef BS
#endif
}

// ---------------- causal flash attention, bf16 m16n8k16, 64-key tiles --------
// grid (32 qtiles, 16 heads), 256 threads, 128-q x 64-key tiles, 2 CTAs/SM.
// smem words: Qs[128][36]=4608 | Ks 2x[64][36]=4608 | Vs 2x[32][72]=4608 | msk 2x64
#define AQ_OFF  0
#define AK_OFF  4608
#define AV_OFF  9216
#define AM_OFF  13824
#define ATTN_SMEM ((13824 + 128) * 4)   // 55808

__global__ __launch_bounds__(256, 2) void attn_kernel(
    const int* __restrict__ amask, float* __restrict__ y)
{
    extern __shared__ uint32_t shw[];
    uint32_t* Qs = shw + AQ_OFF;
    uint32_t* Ks = shw + AK_OFF;
    uint32_t* Vs = shw + AV_OFF;
    int*      mk = (int*)(shw + AM_OFF);

    const int tid = threadIdx.x, lane = tid & 31, w = tid >> 5;
    const int gp = lane >> 2, tg = lane & 3;
    const int h = blockIdx.y;
    const int q0 = (gridDim.x - 1 - blockIdx.x) * 128;
    const int qw = q0 + w * 16;

    // ---- stage Q (bf16, pre-scaled) ----
    {
        const __nv_bfloat16* qb = g_q16 + ((size_t)h * T_SEQ + q0) * 64;
        #pragma unroll
        for (int i = 0; i < 4; i++) {
            int idx = tid + i * 256;
            int r = idx >> 3, ch = idx & 7;
            cp16((uint32_t)__cvta_generic_to_shared(Qs + r * 36 + ch * 4),
                 qb + (size_t)r * 64 + ch * 8);
        }
    }
    asm volatile("cp.async.commit_group;" ::: "memory");

    auto fill_kv = [&](int buf, int kt) {
        const __nv_bfloat16* kbs = g_k16 + ((size_t)h * T_SEQ + kt * 64) * 64;
        #pragma unroll
        for (int i = 0; i < 2; i++) {
            int idx = tid + i * 256;
            int r = idx >> 3, ch = idx & 7;
            cp16((uint32_t)__cvta_generic_to_shared(Ks + buf * 2304 + r * 36 + ch * 4),
                 kbs + (size_t)r * 64 + ch * 8);
        }
        const uint32_t* vbs = g_v16 + ((size_t)h * (T_SEQ / 2) + kt * 32) * 64;
        #pragma unroll
        for (int i = 0; i < 2; i++) {
            int idx = tid + i * 256;
            int pr = idx >> 4, ch = idx & 15;
            cp16((uint32_t)__cvta_generic_to_shared(Vs + buf * 2304 + pr * 72 + ch * 4),
                 vbs + (size_t)pr * 64 + ch * 4);
        }
        if (tid < 16)
            cp16((uint32_t)__cvta_generic_to_shared(mk + buf * 64 + tid * 4),
                 amask + kt * 64 + tid * 4);
    };

    fill_kv(0, 0);
    asm volatile("cp.async.commit_group;" ::: "memory");
    asm volatile("cp.async.wait_group 0;" ::: "memory");
    __syncthreads();

    // ---- Q fragments ----
    uint32_t qa[4][4];
    {
        int r0 = w * 16;
        #pragma unroll
        for (int ks = 0; ks < 4; ks++) {
            qa[ks][0] = Qs[(r0 + gp    ) * 36 + 8 * ks + tg    ];
            qa[ks][1] = Qs[(r0 + gp + 8) * 36 + 8 * ks + tg    ];
            qa[ks][2] = Qs[(r0 + gp    ) * 36 + 8 * ks + 4 + tg];
            qa[ks][3] = Qs[(r0 + gp + 8) * 36 + 8 * ks + 4 + tg];
        }
    }

    float m0 = -INFINITY, m1 = -INFINITY, l0 = 0.f, l1 = 0.f;
    float o[8][4];
    #pragma unroll
    for (int nf = 0; nf < 8; nf++)
        #pragma unroll
        for (int r = 0; r < 4; r++) o[nf][r] = 0.f;

    const int ktmax = (q0 + 127) >> 6;      // last keytile index
    const int kdiag = q0 >> 6;              // first keytile needing causal mask
    const int row0 = qw + gp, row1 = qw + gp + 8;
    int cur = 0;

    for (int kt = 0; kt <= ktmax; kt++) {
        asm volatile("cp.async.wait_group 0;" ::: "memory");
        __syncthreads();

        if (kt < ktmax) {
            fill_kv(cur ^ 1, kt + 1);
            asm volatile("cp.async.commit_group;" ::: "memory");
        }

        const uint32_t* K = Ks + cur * 2304;
        const uint32_t* V = Vs + cur * 2304;
        const int*      M = mk + cur * 64;
        const bool diag = (kt >= kdiag);

        // ---- S = Q @ K^T (16 x 64 per warp) ----
        float sc[8][4];
        #pragma unroll
        for (int nf = 0; nf < 8; nf++)
            #pragma unroll
            for (int r = 0; r < 4; r++) sc[nf][r] = 0.f;

        #pragma unroll
        for (int ks = 0; ks < 4; ks++) {
            #pragma unroll
            for (int nf = 0; nf < 8; nf++) {
                uint32_t b0 = K[(nf * 8 + gp) * 36 + 8 * ks + tg    ];
                uint32_t b1 = K[(nf * 8 + gp) * 36 + 8 * ks + 4 + tg];
                mma_bf16(sc[nf], qa[ks][0], qa[ks][1], qa[ks][2], qa[ks][3], b0, b1);
            }
        }

        // ---- mask (causal only near the diagonal) ----
        float tm0 = -INFINITY, tm1 = -INFINITY;
        if (diag) {
            #pragma unroll
            for (int nf = 0; nf < 8; nf++) {
                int cl = nf * 8 + 2 * tg;
                int c  = kt * 64 + cl;
                bool mk0 = M[cl] != 0, mk1 = M[cl + 1] != 0;
                float s0 = sc[nf][0], s1 = sc[nf][1];
                float s2 = sc[nf][2], s3 = sc[nf][3];
                s0 = (c     <= row0 && mk0) ? s0 : -INFINITY;
                s1 = (c + 1 <= row0 && mk1) ? s1 : -INFINITY;
                s2 = (c     <= row1 && mk0) ? s2 : -INFINITY;
                s3 = (c + 1 <= row1 && mk1) ? s3 : -INFINITY;
                sc[nf][0] = s0; sc[nf][1] = s1; sc[nf][2] = s2; sc[nf][3] = s3;
                tm0 = fmaxf(tm0, fmaxf(s0, s1));
                tm1 = fmaxf(tm1, fmaxf(s2, s3));
            }
        } else {
            #pragma unroll
            for (int nf = 0; nf < 8; nf++) {
                int cl = nf * 8 + 2 * tg;
                bool mk0 = M[cl] != 0, mk1 = M[cl + 1] != 0;
                float s0 = mk0 ? sc[nf][0] : -INFINITY;
                float s1 = mk1 ? sc[nf][1] : -INFINITY;
                float s2 = mk0 ? sc[nf][2] : -INFINITY;
                float s3 = mk1 ? sc[nf][3] : -INFINITY;
                sc[nf][0] = s0; sc[nf][1] = s1; sc[nf][2] = s2; sc[nf][3] = s3;
                tm0 = fmaxf(tm0, fmaxf(s0, s1));
                tm1 = fmaxf(tm1, fmaxf(s2, s3));
            }
        }
        tm0 = fmaxf(tm0, __shfl_xor_sync(0xffffffffu, tm0, 1));
        tm0 = fmaxf(tm0, __shfl_xor_sync(0xffffffffu, tm0, 2));
        tm1 = fmaxf(tm1, __shfl_xor_sync(0xffffffffu, tm1, 1));
        tm1 = fmaxf(tm1, __shfl_xor_sync(0xffffffffu, tm1, 2));

        float nm0 = fmaxf(m0, tm0), nm1 = fmaxf(m1, tm1);
        float ne0 = fmaxf(nm0, -1e30f), ne1 = fmaxf(nm1, -1e30f);
        float al0 = ex2(m0 - ne0), al1 = ex2(m1 - ne1);
        m0 = nm0; m1 = nm1;

        float ps0 = 0.f, ps1 = 0.f;
        #pragma unroll
        for (int nf = 0; nf < 8; nf++) {
            float p0 = ex2(sc[nf][0] - ne0);
            float p1 = ex2(sc[nf][1] - ne0);
            float p2 = ex2(sc[nf][2] - ne1);
            float p3 = ex2(sc[nf][3] - ne1);
            sc[nf][0] = p0; sc[nf][1] = p1; sc[nf][2] = p2; sc[nf][3] = p3;
            ps0 += p0 + p1; ps1 += p2 + p3;
        }
        ps0 += __shfl_xor_sync(0xffffffffu, ps0, 1);
        ps0 += __shfl_xor_sync(0xffffffffu, ps0, 2);
        ps1 += __shfl_xor_sync(0xffffffffu, ps1, 1);
        ps1 += __shfl_xor_sync(0xffffffffu, ps1, 2);
        l0 = l0 * al0 + ps0;
        l1 = l1 * al1 + ps1;

        #pragma unroll
        for (int nf = 0; nf < 8; nf++) {
            o[nf][0] *= al0; o[nf][1] *= al0;
            o[nf][2] *= al1; o[nf][3] *= al1;
        }

        // ---- O += P @ V ----
        #pragma unroll
        for (int ks = 0; ks < 4; ks++) {
            uint32_t pa0 = packbf(sc[2*ks  ][1], sc[2*ks  ][0]);
            uint32_t pa1 = packbf(sc[2*ks  ][3], sc[2*ks  ][2]);
            uint32_t pa2 = packbf(sc[2*ks+1][1], sc[2*ks+1][0]);
            uint32_t pa3 = packbf(sc[2*ks+1][3], sc[2*ks+1][2]);
            #pragma unroll
            for (int nf = 0; nf < 8; nf++) {
                uint32_t b0 = V[(8 * ks + tg    ) * 72 + nf * 8 + gp];
                uint32_t b1 = V[(8 * ks + 4 + tg) * 72 + nf * 8 + gp];
                mma_bf16(o[nf], pa0, pa1, pa2, pa3, b0, b1);
            }
        }
        cur ^= 1;
    }

    float il0 = 1.0f / fmaxf(l0, 1e-30f);
    float il1 = 1.0f / fmaxf(l1, 1e-30f);
    #pragma unroll
    for (int nf = 0; nf < 8; nf++) {
        int col = h * HDIM + nf * 8 + 2 * tg;
        float2 v0; v0.x = to_tf32(o[nf][0] * il0); v0.y = to_tf32(o[nf][1] * il0);
        *(float2*)(y + (size_t)row0 * DM + col) = v0;
        float2 v1; v1.x = to_tf32(o[nf][2] * il1); v1.y = to_tf32(o[nf][3] * il1);
        *(float2*)(y + (size_t)row1 * DM + col) = v1;
    }
}

// ---------------- launcher ----------------
extern "C" void kernel_launch(void* const* d_in, const int* in_sizes, int n_in,
                              void* d_out, int out_size)
{
    const float* x     = (const float*)d_in[0];
    const int*   amask = (const int*)  d_in[1];
    const float* ln1g  = (const float*)d_in[2];
    const float* ln1b  = (const float*)d_in[3];
    const float* Wqkv  = (const float*)d_in[4];
    const float* bqkv  = (const float*)d_in[5];
    const float* Wo    = (const float*)d_in[6];
    const float* bo    = (const float*)d_in[7];
    const float* ln2g  = (const float*)d_in[8];
    const float* ln2b  = (const float*)d_in[9];
    const float* W1    = (const float*)d_in[10];
    const float* b1    = (const float*)d_in[11];
    const float* W2    = (const float*)d_in[12];
    const float* b2    = (const float*)d_in[13];
    float* out = (float*)d_out;

    void *p_ln, *p_y, *p_x2, *p_ff;
    void *p_wqkv, *p_wo, *p_w1, *p_w2;
    cudaGetSymbolAddress(&p_ln,   g_ln);
    cudaGetSymbolAddress(&p_y,    g_y);
    cudaGetSymbolAddress(&p_x2,   g_x2);
    cudaGetSymbolAddress(&p_ff,   g_ff);
    cudaGetSymbolAddress(&p_wqkv, g_wt_qkv);
    cudaGetSymbolAddress(&p_wo,   g_wt_o);
    cudaGetSymbolAddress(&p_w1,   g_wt_1);
    cudaGetSymbolAddress(&p_w2,   g_wt_2);

    cudaFuncSetAttribute(attn_kernel,
        cudaFuncAttributeMaxDynamicSharedMemorySize, ATTN_SMEM);
    cudaFuncSetAttribute(gemm_any<3, 256>,
        cudaFuncAttributeMaxDynamicSharedMemorySize, G_SMEM_T(256));
    cudaFuncSetAttribute(gemm_any<2, 256>,
        cudaFuncAttributeMaxDynamicSharedMemorySize, G_SMEM_T(256));
    cudaFuncSetAttribute(gemm_any<1, 128>,
        cudaFuncAttributeMaxDynamicSharedMemorySize, G_SMEM_T(128));

    // 0. weight transposes (tf32-rounded, [N,K]) — single launch
    transpose_all<<<12288, 256>>>(Wqkv, Wo, W1, W2,
                                  (float*)p_wqkv, (float*)p_wo,
                                  (float*)p_w1, (float*)p_w2);

    // 1. LN1
    ln_kernel<<<T_SEQ, 256>>>(x, ln1g, ln1b, (float*)p_ln);
    // 2. QKV -> bf16 Q/K/V buffers (Q pre-scaled by log2e/8)
    gemm_any<3, 256><<<dim3(12, 16), 256, G_SMEM_T(256)>>>(
        (float*)p_ln, (float*)p_wqkv, bqkv, nullptr, nullptr, T_SEQ, 3 * DM, DM);
    // 3. attention (bf16 mma, 64-key tiles, 2 CTAs/SM)
    attn_kernel<<<dim3(32, 16), 256, ATTN_SMEM>>>(amask, (float*)p_y);
    // 4. x2 = x + y @ W_o + b_o   (128-row tiles -> 128 CTAs)
    gemm_any<1, 128><<<dim3(4, 32), 256, G_SMEM_T(128)>>>(
        (float*)p_y, (float*)p_wo, bo, x, (float*)p_x2, T_SEQ, DM, DM);
    // 5. LN2
    ln_kernel<<<T_SEQ, 256>>>((float*)p_x2, ln2g, ln2b, (float*)p_ln);
    // 6. ff = gelu(h2 @ W1 + b1)
    gemm_any<2, 256><<<dim3(16, 16), 256, G_SMEM_T(256)>>>(
        (float*)p_ln, (float*)p_w1, b1, nullptr, (float*)p_ff, T_SEQ, DFF, DM);
    // 7. out = x2 + ff @ W2 + b2  (128-row tiles -> 128 CTAs)
    gemm_any<1, 128><<<dim3(4, 32), 256, G_SMEM_T(128)>>>(
        (float*)p_ff, (float*)p_w2, b2, (float*)p_x2, out, T_SEQ, DM, DFF);
}

// round 13
// speedup vs baseline: 1.3309x; 1.1094x over previous
#include <cuda_runtime.h>
#include <cuda_bf16.h>
#include <cuda_fp16.h>
#include <cstdint>
#include <math.h>

#define T_SEQ   4096
#define DM      1024
#define DFF     4096
#define NHEADS  16
#define HDIM    64
#define LN_EPS  1e-5f

// ---- arch-specific feature gate: tcgen05 only exists on sm_10xa/f targets ----
#if defined(__CUDA_ARCH__)
#  if defined(__CUDA_ARCH_FEAT_SM103_ALL) || defined(__CUDA_ARCH_FEAT_SM100_ALL) || defined(__CUDA_ARCH_FEAT_SM101_ALL)
#    define GEMM_TC 1
#  elif defined(__CUDA_ARCH_SPECIFIC__)
#    define GEMM_TC ((__CUDA_ARCH_SPECIFIC__ >= 1000) ? 1 : 0)
#  elif defined(__CUDA_ARCH_FAMILY_SPECIFIC__)
#    define GEMM_TC ((__CUDA_ARCH_FAMILY_SPECIFIC__ >= 1000) ? 1 : 0)
#  else
#    define GEMM_TC 0
#  endif
#else
#  define GEMM_TC 0
#endif

// ---------------- scratch (static device globals; no allocation) ----------------
static __device__ float g_ln [T_SEQ * DM];          // LN1 out (tf32-rounded fp32)
static __device__ float g_y  [T_SEQ * DM];          // attention out
static __device__ float g_x2 [T_SEQ * DM];          // residual after attn
// tf32 weights [N,K] K-major (QKV, O)
static __device__ float g_wt_qkv[3 * DM * DM];
static __device__ float g_wt_o  [DM * DM];
// fp16 weights [N,K] K-major (FF1, FF2)
static __device__ __half g_wt1_16[DFF * DM];
static __device__ __half g_wt2_16[DM * DFF];
// fp16 activations for FF path
static __device__ __half g_ln16[T_SEQ * DM];   // LN2 out
static __device__ __half g_ff16[T_SEQ * DFF];  // gelu out
// bf16 attention operands written by the QKV GEMM epilogue
static __device__ __nv_bfloat16 g_q16[NHEADS * T_SEQ * HDIM];     // [h][t][d], scaled log2e/8
static __device__ __nv_bfloat16 g_k16[NHEADS * T_SEQ * HDIM];     // [h][t][d]
static __device__ uint32_t      g_v16[NHEADS * (T_SEQ/2) * HDIM]; // [h][t/2][d] pair-packed

#define QSCALE 0.18033688011112042f   // (1/8) * log2(e)

// ---------------- helpers ----------------
__device__ __forceinline__ float to_tf32(float x) {
    uint32_t u;
    asm("cvt.rna.tf32.f32 %0, %1;" : "=r"(u) : "f"(x));
    return __uint_as_float(u);
}

__device__ __forceinline__ uint32_t packbf(float hi, float lo) {
    uint32_t r;
    asm("cvt.rn.bf16x2.f32 %0, %1, %2;" : "=r"(r) : "f"(hi), "f"(lo));
    return r;
}

__device__ __forceinline__ uint32_t packh(float hi, float lo) {
    uint32_t r;
    asm("cvt.rn.f16x2.f32 %0, %1, %2;" : "=r"(r) : "f"(hi), "f"(lo));
    return r;
}

__device__ __forceinline__ float ex2(float x) {
    float r;
    asm("ex2.approx.f32 %0, %1;" : "=f"(r) : "f"(x));
    return r;
}

__device__ __forceinline__ void mma_tf32(float* c,
    uint32_t a0, uint32_t a1, uint32_t a2, uint32_t a3,
    uint32_t b0, uint32_t b1)
{
    asm volatile(
        "mma.sync.aligned.m16n8k8.row.col.f32.tf32.tf32.f32 "
        "{%0,%1,%2,%3}, {%4,%5,%6,%7}, {%8,%9}, {%0,%1,%2,%3};\n"
        : "+f"(c[0]), "+f"(c[1]), "+f"(c[2]), "+f"(c[3])
        : "r"(a0), "r"(a1), "r"(a2), "r"(a3), "r"(b0), "r"(b1));
}

__device__ __forceinline__ void mma_bf16(float* c,
    uint32_t a0, uint32_t a1, uint32_t a2, uint32_t a3,
    uint32_t b0, uint32_t b1)
{
    asm volatile(
        "mma.sync.aligned.m16n8k16.row.col.f32.bf16.bf16.f32 "
        "{%0,%1,%2,%3}, {%4,%5,%6,%7}, {%8,%9}, {%0,%1,%2,%3};\n"
        : "+f"(c[0]), "+f"(c[1]), "+f"(c[2]), "+f"(c[3])
        : "r"(a0), "r"(a1), "r"(a2), "r"(a3), "r"(b0), "r"(b1));
}

__device__ __forceinline__ void cp16(uint32_t dst, const void* src) {
    asm volatile("cp.async.ca.shared.global [%0], [%1], 16;\n"
                 :: "r"(dst), "l"(src));
}

__device__ __forceinline__ float gelu_exact(float v) {
    return 0.5f * v * (1.0f + erff(v * 0.70710678118654752440f));
}

// load 4 consecutive K-elements as floats from fp32 or fp16 source
template<bool H>
__device__ __forceinline__ float4 ld4f(const void* p, size_t elem) {
    float4 v;
    if (H) {
        uint2 t = *(const uint2*)((const __half*)p + elem);
        float2 a = __half22float2(*(__half2*)&t.x);
        float2 b = __half22float2(*(__half2*)&t.y);
        v.x = a.x; v.y = a.y; v.z = b.x; v.w = b.y;
    } else {
        v = *(const float4*)((const float*)p + elem);
    }
    return v;
}

// ---------------- merged weight transpose (one launch) ----------------
// QKV/O -> tf32 fp32 [N,K]; W1/W2 -> fp16 [N,K]
__global__ __launch_bounds__(256) void transpose_all(
    const float* __restrict__ Wqkv, const float* __restrict__ Wo,
    const float* __restrict__ W1,   const float* __restrict__ W2,
    float* __restrict__ oqkv, float* __restrict__ oo,
    __half* __restrict__ o1, __half* __restrict__ o2)
{
    __shared__ float t[32][33];
    int tb = blockIdx.x;
    const float* in; int R, C, txw, which;
    if (tb < 3072)      { in = Wqkv; R = 1024; C = 3072; txw = 96;  which = 0; }
    else if (tb < 4096) { tb -= 3072; in = Wo; R = 1024; C = 1024; txw = 32;  which = 1; }
    else if (tb < 8192) { tb -= 4096; in = W1; R = 1024; C = 4096; txw = 128; which = 2; }
    else                { tb -= 8192; in = W2; R = 4096; C = 1024; txw = 32;  which = 3; }
    int bx = (tb % txw) * 32, by = (tb / txw) * 32;
    int x = threadIdx.x & 31, y = threadIdx.x >> 5;
    #pragma unroll
    for (int i = 0; i < 32; i += 8)
        t[y + i][x] = in[(size_t)(by + y + i) * C + bx + x];
    __syncthreads();
    #pragma unroll
    for (int i = 0; i < 32; i += 8) {
        size_t idx = (size_t)(bx + y + i) * R + by + x;
        float v = t[x][y + i];
        if (which == 0)      oqkv[idx] = to_tf32(v);
        else if (which == 1) oo[idx]   = to_tf32(v);
        else if (which == 2) o1[idx]   = __float2half_rn(v);
        else                 o2[idx]   = __float2half_rn(v);
    }
}

// ---------------- LayerNorm: H=false -> tf32 fp32 out, H=true -> fp16 out ----
template<bool H>
__global__ __launch_bounds__(256) void ln_kernel(
    const float* __restrict__ x, const float* __restrict__ g,
    const float* __restrict__ b, void* __restrict__ outp)
{
    int row = blockIdx.x;
    int tid = threadIdx.x;
    const float4 v = ((const float4*)(x + (size_t)row * DM))[tid];
    float s  = v.x + v.y + v.z + v.w;
    float sq = v.x * v.x + v.y * v.y + v.z * v.z + v.w * v.w;
    #pragma unroll
    for (int o = 16; o; o >>= 1) {
        s  += __shfl_xor_sync(0xffffffffu, s,  o);
        sq += __shfl_xor_sync(0xffffffffu, sq, o);
    }
    __shared__ float ss[8], ssq[8];
    __shared__ float mean_s, inv_s;
    int w = tid >> 5, l = tid & 31;
    if (l == 0) { ss[w] = s; ssq[w] = sq; }
    __syncthreads();
    if (tid == 0) {
        float st = 0.f, sqt = 0.f;
        #pragma unroll
        for (int i = 0; i < 8; i++) { st += ss[i]; sqt += ssq[i]; }
        float mean = st * (1.0f / DM);
        float var  = sqt * (1.0f / DM) - mean * mean;
        mean_s = mean;
        inv_s  = rsqrtf(var + LN_EPS);
    }
    __syncthreads();
    float mean = mean_s, inv = inv_s;
    const float4 gv = ((const float4*)g)[tid];
    const float4 bv = ((const float4*)b)[tid];
    float o0 = (v.x - mean) * inv * gv.x + bv.x;
    float o1 = (v.y - mean) * inv * gv.y + bv.y;
    float o2 = (v.z - mean) * inv * gv.z + bv.z;
    float o3 = (v.w - mean) * inv * gv.w + bv.w;
    if (H) {
        uint32_t* o16 = (uint32_t*)outp;
        size_t wi = ((size_t)row * DM + tid * 4) >> 1;
        o16[wi]     = packh(o1, o0);
        o16[wi + 1] = packh(o3, o2);
    } else {
        float4 o;
        o.x = to_tf32(o0); o.y = to_tf32(o1);
        o.z = to_tf32(o2); o.w = to_tf32(o3);
        ((float4*)((float*)outp + (size_t)row * DM))[tid] = o;
    }
}

// ---------------- unified GEMM: C[M,N] = A[M,K] @ Bt[N,K]^T + epilogue --------
// Tile TM x 256, 256 threads. grid = (N/256, M/TM). One 128B-row stage per kt.
// MODE 1: tf32, +bias+res, fp32 out      MODE 3: tf32, QKV -> bf16 q/k/v bufs
// MODE 4: fp16, gelu(+bias) -> fp16 out  MODE 5: fp16, +bias+res, fp32 out
#define GS        3
#define G_BASE    1024
#define G_SMEM_T(TM) (G_BASE + GS * ((TM) * 128 + 32768))

#if GEMM_TC
__device__ __forceinline__ bool elect_one() {
    uint32_t pred;
    asm volatile(
        "{\n\t.reg .pred p;\n\t"
        "elect.sync _|p, 0xFFFFFFFF;\n\t"
        "selp.b32 %0, 1, 0, p;\n\t}"
        : "=r"(pred));
    return pred != 0;
}
__device__ __forceinline__ uint64_t make_desc(uint32_t addr) {
    const uint64_t base = (2ULL << 61) | (1ULL << 46) | (64ULL << 32) | (1ULL << 16);
    return base | ((uint64_t)(addr >> 4) & 0x3FFF);
}
__device__ __forceinline__ void tc_mma_tf32_ss(uint32_t d, uint64_t ad, uint64_t bd,
                                               uint32_t idesc, bool acc)
{
    uint32_t en = acc ? 1u : 0u;
    asm volatile(
        "{\n\t.reg .pred p;\n\t"
        "setp.ne.u32 p, %4, 0;\n\t"
        "tcgen05.mma.cta_group::1.kind::tf32 [%0], %1, %2, %3, {%5, %5, %5, %5}, p;\n\t}"
        :: "r"(d), "l"(ad), "l"(bd), "r"(idesc), "r"(en), "r"(0u)
        : "memory");
}
__device__ __forceinline__ void tc_mma_f16_ss(uint32_t d, uint64_t ad, uint64_t bd,
                                              uint32_t idesc, bool acc)
{
    uint32_t en = acc ? 1u : 0u;
    asm volatile(
        "{\n\t.reg .pred p;\n\t"
        "setp.ne.u32 p, %4, 0;\n\t"
        "tcgen05.mma.cta_group::1.kind::f16 [%0], %1, %2, %3, {%5, %5, %5, %5}, p;\n\t}"
        :: "r"(d), "l"(ad), "l"(bd), "r"(idesc), "r"(en), "r"(0u)
        : "memory");
}
#define MBAR_INIT(a, c) \
    asm volatile("mbarrier.init.shared.b64 [%0], %1;" :: "r"(a), "r"(c) : "memory")
#define MBAR_WAIT(a, par) do { \
    uint32_t _m = (a), _p = (par), _d; \
    asm volatile("{\n\t.reg .pred p;\n\t" \
        "mbarrier.try_wait.parity.acquire.cta.shared::cta.b64 p, [%1], %2;\n\t" \
        "selp.b32 %0, 1, 0, p;\n\t}" : "=r"(_d) : "r"(_m), "r"(_p) : "memory"); \
    if (!_d) { \
        asm volatile("{\n\t.reg .pred P1;\n\t" \
            "WL_%=:\n\t" \
            "mbarrier.try_wait.parity.acquire.cta.shared::cta.b64 P1, [%0], %1, 0x989680;\n\t" \
            "@P1 bra.uni WD_%=;\n\t" \
            "bra.uni WL_%=;\n\t" \
            "WD_%=:\n\t}" :: "r"(_m), "r"(_p) : "memory"); \
    } \
} while (0)
#define CPASYNC_MBAR_ARRIVE_NOINC(a) \
    asm volatile("cp.async.mbarrier.arrive.noinc.shared.b64 [%0];" :: "r"(a) : "memory")
#endif  // GEMM_TC

// epilogue write helper for MODE 3 (pair of adjacent columns, one row)
__device__ __forceinline__ void qkv_write_pair(int n, int row, float v0, float v1) {
    if (n < 1024) {
        int hd = n >> 6, d = n & 63;
        ((uint32_t*)g_q16)[(((size_t)hd * T_SEQ + row) * 64 + d) >> 1]
            = packbf(v1 * QSCALE, v0 * QSCALE);
    } else if (n < 2048) {
        int hd = (n - 1024) >> 6, d = (n - 1024) & 63;
        ((uint32_t*)g_k16)[(((size_t)hd * T_SEQ + row) * 64 + d) >> 1]
            = packbf(v1, v0);
    } else {
        int hd = (n - 2048) >> 6, d = (n - 2048) & 63;
        __nv_bfloat16* vp = (__nv_bfloat16*)g_v16;
        size_t wi = ((size_t)hd * (T_SEQ / 2) + (row >> 1)) * 64 + d;
        vp[wi * 2 + (row & 1)]       = __float2bfloat16(v0);
        vp[(wi + 1) * 2 + (row & 1)] = __float2bfloat16(v1);
    }
}

template<int MODE, int TM>
__global__ __launch_bounds__(256)
void gemm_any(const void* __restrict__ A, const void* __restrict__ Bt,
              const float* __restrict__ bias, const float* __restrict__ res,
              float* __restrict__ C, int M, int N, int K)
{
    constexpr bool H16 = (MODE >= 4);
    constexpr int  EB = H16 ? 2 : 4;         // element bytes
    constexpr int  KELEM = 128 / EB;         // K-elements per 128B stage row
    extern __shared__ __align__(1024) char gsm[];
    const int tid = threadIdx.x, wid = tid >> 5, lane = tid & 31;

#if GEMM_TC
    // ================= tcgen05 path (TM x 256 tile, mbarrier dataflow) ========
    constexpr int A_TILE = TM * 128;
    constexpr int STAGE  = A_TILE + 32768;
    constexpr int TCOLS  = (TM == 256) ? 512 : 256;
    const int m0 = blockIdx.y * TM, n0 = blockIdx.x * 256;
    const uint32_t sb = (uint32_t)__cvta_generic_to_shared(gsm);
    const uint32_t mb0 = sb + 16, mb1 = sb + 24;
    const uint32_t fmb = sb + 32;

    if (wid == 0) {
        asm volatile("tcgen05.alloc.cta_group::1.sync.aligned.shared::cta.b32 [%0], %1;"
                     :: "r"(sb), "r"((uint32_t)TCOLS) : "memory");
        asm volatile("tcgen05.relinquish_alloc_permit.cta_group::1.sync.aligned;");
    }
    if (tid == 0) {
        MBAR_INIT(mb0, 1); MBAR_INIT(mb1, 1);
        MBAR_INIT(fmb + 0, 256); MBAR_INIT(fmb + 8, 256); MBAR_INIT(fmb + 16, 256);
    }
    __syncthreads();
    uint32_t tb;
    asm volatile("ld.shared.b32 %0, [%1];" : "=r"(tb) : "r"(sb));

    const int KT = K / KELEM;
    const size_t rowB = (size_t)K * EB;      // bytes per gmem row

    auto fill = [&](int slot, int ktile) {
        uint32_t s = sb + G_BASE + slot * STAGE;
        const char* Ab = (const char*)A + ((size_t)m0 * K + (size_t)ktile * KELEM) * EB;
        const char* Bb = (const char*)Bt + ((size_t)n0 * K + (size_t)ktile * KELEM) * EB;
        #pragma unroll
        for (int i = 0; i < TM / 32; i++) {
            int idx = tid + i * 256;
            int r = idx >> 3, ch = (idx & 7) * 16;
            uint32_t byte = (uint32_t)(r * 128 + ch);
            uint32_t sw = byte ^ ((byte >> 3) & 0x70);
            cp16(s + sw, Ab + (size_t)r * rowB + ch);
        }
        #pragma unroll
        for (int i = 0; i < 8; i++) {
            int idx = tid + i * 256;
            int r = idx >> 3, ch = (idx & 7) * 16;
            uint32_t byte = (uint32_t)(r * 128 + ch);
            uint32_t sw = byte ^ ((byte >> 3) & 0x70);
            cp16(s + A_TILE + sw, Bb + (size_t)r * rowB + ch);
        }
        CPASYNC_MBAR_ARRIVE_NOINC(fmb + slot * 8);
    };

    #pragma unroll
    for (int st = 0; st < GS - 1; st++) fill(st, st);

    // idesc: accum F32; tf32 path types=2/2; f16 path types=0/0 (fp16)
    const uint32_t idesc = H16
        ? ((1u << 4) | (0u << 7) | (0u << 10) | (32u << 17) | (8u << 24))
        : ((1u << 4) | (2u << 7) | (2u << 10) | (32u << 17) | (8u << 24));

    int ph0 = 0, ph1 = 0;
    for (int kt = 0; kt < KT; kt++) {
        if (wid == 0) {
            int slot = kt % GS;
            int fph = (kt / GS) & 1;
            MBAR_WAIT(fmb + slot * 8, fph);
            asm volatile("fence.proxy.async.shared::cta;" ::: "memory");
            if (elect_one()) {
                uint32_t s = sb + G_BASE + slot * STAGE;
                uint64_t ad = make_desc(s);
                uint64_t bd = make_desc(s + A_TILE);
                #pragma unroll
                for (int ks = 0; ks < 4; ks++) {
                    bool acc = (kt > 0) || (ks > 0);
                    if (H16) {
                        tc_mma_f16_ss(tb, ad + ks * 2, bd + ks * 2, idesc, acc);
                        if (TM == 256)
                            tc_mma_f16_ss(tb + 256, ad + 1024 + ks * 2, bd + ks * 2, idesc, acc);
                    } else {
                        tc_mma_tf32_ss(tb, ad + ks * 2, bd + ks * 2, idesc, acc);
                        if (TM == 256)
                            tc_mma_tf32_ss(tb + 256, ad + 1024 + ks * 2, bd + ks * 2, idesc, acc);
                    }
                }
                uint32_t mb = (kt & 1) ? mb1 : mb0;
                asm volatile(
                    "tcgen05.commit.cta_group::1.mbarrier::arrive::one.shared::cluster.b64 [%0];"
                    :: "r"(mb) : "memory");
            }
        }

        if (kt >= 1) {
            if ((kt - 1) & 1) { MBAR_WAIT(mb1, ph1); ph1 ^= 1; }
            else              { MBAR_WAIT(mb0, ph0); ph0 ^= 1; }
        }
        if (kt + GS - 1 < KT) fill((kt + GS - 1) % GS, kt + GS - 1);
    }

    if ((KT - 1) & 1) { MBAR_WAIT(mb1, ph1); }
    else              { MBAR_WAIT(mb0, ph0); }
    asm volatile("tcgen05.fence::after_thread_sync;" ::: "memory");

    {
        int row; uint32_t dbase; int cstart;
        if (TM == 256) {
            row = m0 + ((wid < 4) ? wid * 32 : 128 + (wid - 4) * 32) + lane;
            dbase = tb + ((wid < 4) ? 0u : 256u);
            cstart = 0;
        } else {
            row = m0 + (wid & 3) * 32 + lane;
            dbase = tb;
            cstart = (wid < 4) ? 0 : 128;
        }
        const int cspan = (TM == 256) ? 256 : 128;
        #pragma unroll
        for (int ci = 0; ci < 256; ci += 32) {
            if (ci >= cspan) break;
            const int c0 = cstart + ci;
            float d[32];
            asm volatile(
                "tcgen05.ld.sync.aligned.32x32b.x32.b32 "
                "{%0,%1,%2,%3,%4,%5,%6,%7,%8,%9,%10,%11,%12,%13,%14,%15,"
                "%16,%17,%18,%19,%20,%21,%22,%23,%24,%25,%26,%27,%28,%29,%30,%31}, [%32];"
                : "=f"(d[0]),  "=f"(d[1]),  "=f"(d[2]),  "=f"(d[3]),
                  "=f"(d[4]),  "=f"(d[5]),  "=f"(d[6]),  "=f"(d[7]),
                  "=f"(d[8]),  "=f"(d[9]),  "=f"(d[10]), "=f"(d[11]),
                  "=f"(d[12]), "=f"(d[13]), "=f"(d[14]), "=f"(d[15]),
                  "=f"(d[16]), "=f"(d[17]), "=f"(d[18]), "=f"(d[19]),
                  "=f"(d[20]), "=f"(d[21]), "=f"(d[22]), "=f"(d[23]),
                  "=f"(d[24]), "=f"(d[25]), "=f"(d[26]), "=f"(d[27]),
                  "=f"(d[28]), "=f"(d[29]), "=f"(d[30]), "=f"(d[31])
                : "r"(dbase + c0));
            asm volatile("tcgen05.wait::ld.sync.aligned;" ::: "memory");

            #pragma unroll
            for (int c = 0; c < 32; c += 4) {
                const int n = n0 + c0 + c;
                const float4 bv = *(const float4*)(bias + n);
                float4 v;
                v.x = d[c + 0] + bv.x; v.y = d[c + 1] + bv.y;
                v.z = d[c + 2] + bv.z; v.w = d[c + 3] + bv.w;
                if (MODE == 3) {
                    qkv_write_pair(n,     row, v.x, v.y);
                    qkv_write_pair(n + 2, row, v.z, v.w);
                } else if (MODE == 4) {
                    uint32_t* o16 = (uint32_t*)g_ff16;
                    size_t wi = ((size_t)row * N + n) >> 1;
                    o16[wi]     = packh(gelu_exact(v.y), gelu_exact(v.x));
                    o16[wi + 1] = packh(gelu_exact(v.w), gelu_exact(v.z));
                } else {
                    const float4 rv = *(const float4*)(res + (size_t)row * N + n);
                    v.x += rv.x; v.y += rv.y; v.z += rv.z; v.w += rv.w;
                    *(float4*)(C + (size_t)row * N + n) = v;
                }
            }
        }
    }

    __syncthreads();
    if (tid == 0) {
        asm volatile("mbarrier.inval.shared.b64 [%0];" :: "r"(mb0) : "memory");
        asm volatile("mbarrier.inval.shared.b64 [%0];" :: "r"(mb1) : "memory");
        asm volatile("mbarrier.inval.shared.b64 [%0];" :: "r"(fmb + 0) : "memory");
        asm volatile("mbarrier.inval.shared.b64 [%0];" :: "r"(fmb + 8) : "memory");
        asm volatile("mbarrier.inval.shared.b64 [%0];" :: "r"(fmb + 16) : "memory");
    }
    __syncthreads();
    if (wid == 0)
        asm volatile("tcgen05.dealloc.cta_group::1.sync.aligned.b32 %0, %1;"
                     :: "r"(tb), "r"((uint32_t)TCOLS));

#else
    // ================= mma.sync fallback: (TM/128)x2 subtiles of 128x128 ==========
    float* As = (float*)gsm;
    float* Bs = As + 2 * 16 * 132;
    #define AS(buf, k, m) As[((buf) * 16 + (k)) * 132 + (m)]
    #define BS(buf, k, n) Bs[((buf) * 16 + (k)) * 132 + (n)]

    const int wm = wid >> 2, wn = wid & 3;
    const int gp = lane >> 2, tg = lane & 3;

    for (int mi = 0; mi < TM / 128; mi++)
    for (int ni = 0; ni < 2; ni++) {
        const int m0 = blockIdx.y * TM + mi * 128;
        const int n0 = blockIdx.x * 256 + ni * 128;

        float c[4][4][4];
        #pragma unroll
        for (int i = 0; i < 4; i++)
            #pragma unroll
            for (int j = 0; j < 4; j++)
                #pragma unroll
                for (int r = 0; r < 4; r++) c[i][j][r] = 0.f;

        const int KT = K >> 4;
        float4 va[2], vb[2];

        __syncthreads();
        #pragma unroll
        for (int i = 0; i < 2; i++) {
            int idx = tid + i * 256;
            int r = idx >> 2, c4 = (idx & 3) << 2;
            va[i] = ld4f<H16>(A,  (size_t)(m0 + r) * K + c4);
            vb[i] = ld4f<H16>(Bt, (size_t)(n0 + r) * K + c4);
        }
        #pragma unroll
        for (int i = 0; i < 2; i++) {
            int idx = tid + i * 256;
            int r = idx >> 2, c4 = (idx & 3) << 2;
            AS(0, c4 + 0, r) = to_tf32(va[i].x);
            AS(0, c4 + 1, r) = to_tf32(va[i].y);
            AS(0, c4 + 2, r) = to_tf32(va[i].z);
            AS(0, c4 + 3, r) = to_tf32(va[i].w);
            BS(0, c4 + 0, r) = to_tf32(vb[i].x);
            BS(0, c4 + 1, r) = to_tf32(vb[i].y);
            BS(0, c4 + 2, r) = to_tf32(vb[i].z);
            BS(0, c4 + 3, r) = to_tf32(vb[i].w);
        }
        __syncthreads();

        int cur = 0;
        for (int kt = 0; kt < KT; kt++) {
            if (kt + 1 < KT) {
                #pragma unroll
                for (int i = 0; i < 2; i++) {
                    int idx = tid + i * 256;
                    int r = idx >> 2, c4 = (idx & 3) << 2;
                    va[i] = ld4f<H16>(A,  (size_t)(m0 + r) * K + (kt + 1) * 16 + c4);
                    vb[i] = ld4f<H16>(Bt, (size_t)(n0 + r) * K + (kt + 1) * 16 + c4);
                }
            }
            #pragma unroll
            for (int ks = 0; ks < 2; ks++) {
                const int k = ks * 8;
                uint32_t a[4][4], b[4][2];
                #pragma unroll
                for (int mf = 0; mf < 4; mf++) {
                    int r0 = wm * 64 + mf * 16;
                    a[mf][0] = __float_as_uint(AS(cur, k + tg,     r0 + gp));
                    a[mf][1] = __float_as_uint(AS(cur, k + tg,     r0 + gp + 8));
                    a[mf][2] = __float_as_uint(AS(cur, k + tg + 4, r0 + gp));
                    a[mf][3] = __float_as_uint(AS(cur, k + tg + 4, r0 + gp + 8));
                }
                #pragma unroll
                for (int nf = 0; nf < 4; nf++) {
                    int c0 = wn * 32 + nf * 8;
                    b[nf][0] = __float_as_uint(BS(cur, k + tg,     c0 + gp));
                    b[nf][1] = __float_as_uint(BS(cur, k + tg + 4, c0 + gp));
                }
                #pragma unroll
                for (int mf = 0; mf < 4; mf++)
                    #pragma unroll
                    for (int nf = 0; nf < 4; nf++)
                        mma_tf32(c[mf][nf], a[mf][0], a[mf][1], a[mf][2], a[mf][3],
                                 b[nf][0], b[nf][1]);
            }
            if (kt + 1 < KT) {
                int nxt = cur ^ 1;
                #pragma unroll
                for (int i = 0; i < 2; i++) {
                    int idx = tid + i * 256;
                    int r = idx >> 2, c4 = (idx & 3) << 2;
                    AS(nxt, c4 + 0, r) = to_tf32(va[i].x);
                    AS(nxt, c4 + 1, r) = to_tf32(va[i].y);
                    AS(nxt, c4 + 2, r) = to_tf32(va[i].z);
                    AS(nxt, c4 + 3, r) = to_tf32(va[i].w);
                    BS(nxt, c4 + 0, r) = to_tf32(vb[i].x);
                    BS(nxt, c4 + 1, r) = to_tf32(vb[i].y);
                    BS(nxt, c4 + 2, r) = to_tf32(vb[i].z);
                    BS(nxt, c4 + 3, r) = to_tf32(vb[i].w);
                }
                __syncthreads();
                cur = nxt;
            }
        }

        #pragma unroll
        for (int mf = 0; mf < 4; mf++) {
            #pragma unroll
            for (int nf = 0; nf < 4; nf++) {
                int col = n0 + wn * 32 + nf * 8 + 2 * tg;
                float bi0 = bias[col], bi1 = bias[col + 1];
                #pragma unroll
                for (int hh = 0; hh < 2; hh++) {
                    int row = m0 + wm * 64 + mf * 16 + gp + hh * 8;
                    float v0 = c[mf][nf][hh * 2 + 0] + bi0;
                    float v1 = c[mf][nf][hh * 2 + 1] + bi1;
                    if (MODE == 3) {
                        qkv_write_pair(col, row, v0, v1);
                    } else if (MODE == 4) {
                        ((uint32_t*)g_ff16)[((size_t)row * N + col) >> 1]
                            = packh(gelu_exact(v1), gelu_exact(v0));
                    } else {
                        const float2 rv = *(const float2*)(res + (size_t)row * N + col);
                        v0 += rv.x; v1 += rv.y;
                        float2 o; o.x = v0; o.y = v1;
                        *(float2*)(C + (size_t)row * N + col) = o;
                    }
                }
            }
        }
    }
    #undef AS
    #undef BS
#endif
}

// ---------------- causal flash attention (unchanged from R11 winner) --------
#define AQ_OFF  0
#define AK_OFF  4608
#define AV_OFF  9216
#define AM_OFF  13824
#define ATTN_SMEM ((13824 + 128) * 4)   // 55808

__global__ __launch_bounds__(256, 2) void attn_kernel(
    const int* __restrict__ amask, float* __restrict__ y)
{
    extern __shared__ uint32_t shw[];
    uint32_t* Qs = shw + AQ_OFF;
    uint32_t* Ks = shw + AK_OFF;
    uint32_t* Vs = shw + AV_OFF;
    int*      mk = (int*)(shw + AM_OFF);

    const int tid = threadIdx.x, lane = tid & 31, w = tid >> 5;
    const int gp = lane >> 2, tg = lane & 3;
    const int h = blockIdx.y;
    const int q0 = (gridDim.x - 1 - blockIdx.x) * 128;
    const int qw = q0 + w * 16;

    {
        const __nv_bfloat16* qb = g_q16 + ((size_t)h * T_SEQ + q0) * 64;
        #pragma unroll
        for (int i = 0; i < 4; i++) {
            int idx = tid + i * 256;
            int r = idx >> 3, ch = idx & 7;
            cp16((uint32_t)__cvta_generic_to_shared(Qs + r * 36 + ch * 4),
                 qb + (size_t)r * 64 + ch * 8);
        }
    }
    asm volatile("cp.async.commit_group;" ::: "memory");

    auto fill_kv = [&](int buf, int kt) {
        const __nv_bfloat16* kbs = g_k16 + ((size_t)h * T_SEQ + kt * 64) * 64;
        #pragma unroll
        for (int i = 0; i < 2; i++) {
            int idx = tid + i * 256;
            int r = idx >> 3, ch = idx & 7;
            cp16((uint32_t)__cvta_generic_to_shared(Ks + buf * 2304 + r * 36 + ch * 4),
                 kbs + (size_t)r * 64 + ch * 8);
        }
        const uint32_t* vbs = g_v16 + ((size_t)h * (T_SEQ / 2) + kt * 32) * 64;
        #pragma unroll
        for (int i = 0; i < 2; i++) {
            int idx = tid + i * 256;
            int pr = idx >> 4, ch = idx & 15;
            cp16((uint32_t)__cvta_generic_to_shared(Vs + buf * 2304 + pr * 72 + ch * 4),
                 vbs + (size_t)pr * 64 + ch * 4);
        }
        if (tid < 16)
            cp16((uint32_t)__cvta_generic_to_shared(mk + buf * 64 + tid * 4),
                 amask + kt * 64 + tid * 4);
    };

    fill_kv(0, 0);
    asm volatile("cp.async.commit_group;" ::: "memory");
    asm volatile("cp.async.wait_group 0;" ::: "memory");
    __syncthreads();

    uint32_t qa[4][4];
    {
        int r0 = w * 16;
        #pragma unroll
        for (int ks = 0; ks < 4; ks++) {
            qa[ks][0] = Qs[(r0 + gp    ) * 36 + 8 * ks + tg    ];
            qa[ks][1] = Qs[(r0 + gp + 8) * 36 + 8 * ks + tg    ];
            qa[ks][2] = Qs[(r0 + gp    ) * 36 + 8 * ks + 4 + tg];
            qa[ks][3] = Qs[(r0 + gp + 8) * 36 + 8 * ks + 4 + tg];
        }
    }

    float m0 = -INFINITY, m1 = -INFINITY, l0 = 0.f, l1 = 0.f;
    float o[8][4];
    #pragma unroll
    for (int nf = 0; nf < 8; nf++)
        #pragma unroll
        for (int r = 0; r < 4; r++) o[nf][r] = 0.f;

    const int ktmax = (q0 + 127) >> 6;
    const int kdiag = q0 >> 6;
    const int row0 = qw + gp, row1 = qw + gp + 8;
    int cur = 0;

    for (int kt = 0; kt <= ktmax; kt++) {
        asm volatile("cp.async.wait_group 0;" ::: "memory");
        __syncthreads();

        if (kt < ktmax) {
            fill_kv(cur ^ 1, kt + 1);
            asm volatile("cp.async.commit_group;" ::: "memory");
        }

        const uint32_t* K = Ks + cur * 2304;
        const uint32_t* V = Vs + cur * 2304;
        const int*      M = mk + cur * 64;
        const bool diag = (kt >= kdiag);

        float sc[8][4];
        #pragma unroll
        for (int nf = 0; nf < 8; nf++)
            #pragma unroll
            for (int r = 0; r < 4; r++) sc[nf][r] = 0.f;

        #pragma unroll
        for (int ks = 0; ks < 4; ks++) {
            #pragma unroll
            for (int nf = 0; nf < 8; nf++) {
                uint32_t b0 = K[(nf * 8 + gp) * 36 + 8 * ks + tg    ];
                uint32_t b1 = K[(nf * 8 + gp) * 36 + 8 * ks + 4 + tg];
                mma_bf16(sc[nf], qa[ks][0], qa[ks][1], qa[ks][2], qa[ks][3], b0, b1);
            }
        }

        float tm0 = -INFINITY, tm1 = -INFINITY;
        if (diag) {
            #pragma unroll
            for (int nf = 0; nf < 8; nf++) {
                int cl = nf * 8 + 2 * tg;
                int c  = kt * 64 + cl;
                bool mk0 = M[cl] != 0, mk1 = M[cl + 1] != 0;
                float s0 = sc[nf][0], s1 = sc[nf][1];
                float s2 = sc[nf][2], s3 = sc[nf][3];
                s0 = (c     <= row0 && mk0) ? s0 : -INFINITY;
                s1 = (c + 1 <= row0 && mk1) ? s1 : -INFINITY;
                s2 = (c     <= row1 && mk0) ? s2 : -INFINITY;
                s3 = (c + 1 <= row1 && mk1) ? s3 : -INFINITY;
                sc[nf][0] = s0; sc[nf][1] = s1; sc[nf][2] = s2; sc[nf][3] = s3;
                tm0 = fmaxf(tm0, fmaxf(s0, s1));
                tm1 = fmaxf(tm1, fmaxf(s2, s3));
            }
        } else {
            #pragma unroll
            for (int nf = 0; nf < 8; nf++) {
                int cl = nf * 8 + 2 * tg;
                bool mk0 = M[cl] != 0, mk1 = M[cl + 1] != 0;
                float s0 = mk0 ? sc[nf][0] : -INFINITY;
                float s1 = mk1 ? sc[nf][1] : -INFINITY;
                float s2 = mk0 ? sc[nf][2] : -INFINITY;
                float s3 = mk1 ? sc[nf][3] : -INFINITY;
                sc[nf][0] = s0; sc[nf][1] = s1; sc[nf][2] = s2; sc[nf][3] = s3;
                tm0 = fmaxf(tm0, fmaxf(s0, s1));
                tm1 = fmaxf(tm1, fmaxf(s2, s3));
            }
        }
        tm0 = fmaxf(tm0, __shfl_xor_sync(0xffffffffu, tm0, 1));
        tm0 = fmaxf(tm0, __shfl_xor_sync(0xffffffffu, tm0, 2));
        tm1 = fmaxf(tm1, __shfl_xor_sync(0xffffffffu, tm1, 1));
        tm1 = fmaxf(tm1, __shfl_xor_sync(0xffffffffu, tm1, 2));

        float nm0 = fmaxf(m0, tm0), nm1 = fmaxf(m1, tm1);
        float ne0 = fmaxf(nm0, -1e30f), ne1 = fmaxf(nm1, -1e30f);
        float al0 = ex2(m0 - ne0), al1 = ex2(m1 - ne1);
        m0 = nm0; m1 = nm1;

        float ps0 = 0.f, ps1 = 0.f;
        #pragma unroll
        for (int nf = 0; nf < 8; nf++) {
            float p0 = ex2(sc[nf][0] - ne0);
            float p1 = ex2(sc[nf][1] - ne0);
            float p2 = ex2(sc[nf][2] - ne1);
            float p3 = ex2(sc[nf][3] - ne1);
            sc[nf][0] = p0; sc[nf][1] = p1; sc[nf][2] = p2; sc[nf][3] = p3;
            ps0 += p0 + p1; ps1 += p2 + p3;
        }
        ps0 += __shfl_xor_sync(0xffffffffu, ps0, 1);
        ps0 += __shfl_xor_sync(0xffffffffu, ps0, 2);
        ps1 += __shfl_xor_sync(0xffffffffu, ps1, 1);
        ps1 += __shfl_xor_sync(0xffffffffu, ps1, 2);
        l0 = l0 * al0 + ps0;
        l1 = l1 * al1 + ps1;

        #pragma unroll
        for (int nf = 0; nf < 8; nf++) {
            o[nf][0] *= al0; o[nf][1] *= al0;
            o[nf][2] *= al1; o[nf][3] *= al1;
        }

        #pragma unroll
        for (int ks = 0; ks < 4; ks++) {
            uint32_t pa0 = packbf(sc[2*ks  ][1], sc[2*ks  ][0]);
            uint32_t pa1 = packbf(sc[2*ks  ][3], sc[2*ks  ][2]);
            uint32_t pa2 = packbf(sc[2*ks+1][1], sc[2*ks+1][0]);
            uint32_t pa3 = packbf(sc[2*ks+1][3], sc[2*ks+1][2]);
            #pragma unroll
            for (int nf = 0; nf < 8; nf++) {
                uint32_t b0 = V[(8 * ks + tg    ) * 72 + nf * 8 + gp];
                uint32_t b1 = V[(8 * ks + 4 + tg) * 72 + nf * 8 + gp];
                mma_bf16(o[nf], pa0, pa1, pa2, pa3, b0, b1);
            }
        }
        cur ^= 1;
    }

    float il0 = 1.0f / fmaxf(l0, 1e-30f);
    float il1 = 1.0f / fmaxf(l1, 1e-30f);
    #pragma unroll
    for (int nf = 0; nf < 8; nf++) {
        int col = h * HDIM + nf * 8 + 2 * tg;
        float2 v0; v0.x = to_tf32(o[nf][0] * il0); v0.y = to_tf32(o[nf][1] * il0);
        *(float2*)(y + (size_t)row0 * DM + col) = v0;
        float2 v1; v1.x = to_tf32(o[nf][2] * il1); v1.y = to_tf32(o[nf][3] * il1);
        *(float2*)(y + (size_t)row1 * DM + col) = v1;
    }
}

// ---------------- launcher ----------------
extern "C" void kernel_launch(void* const* d_in, const int* in_sizes, int n_in,
                              void* d_out, int out_size)
{
    const float* x     = (const float*)d_in[0];
    const int*   amask = (const int*)  d_in[1];
    const float* ln1g  = (const float*)d_in[2];
    const float* ln1b  = (const float*)d_in[3];
    const float* Wqkv  = (const float*)d_in[4];
    const float* bqkv  = (const float*)d_in[5];
    const float* Wo    = (const float*)d_in[6];
    const float* bo    = (const float*)d_in[7];
    const float* ln2g  = (const float*)d_in[8];
    const float* ln2b  = (const float*)d_in[9];
    const float* W1    = (const float*)d_in[10];
    const float* b1    = (const float*)d_in[11];
    const float* W2    = (const float*)d_in[12];
    const float* b2    = (const float*)d_in[13];
    float* out = (float*)d_out;

    void *p_ln, *p_y, *p_x2, *p_wqkv, *p_wo, *p_w1, *p_w2, *p_ln16, *p_ff16;
    cudaGetSymbolAddress(&p_ln,   g_ln);
    cudaGetSymbolAddress(&p_y,    g_y);
    cudaGetSymbolAddress(&p_x2,   g_x2);
    cudaGetSymbolAddress(&p_wqkv, g_wt_qkv);
    cudaGetSymbolAddress(&p_wo,   g_wt_o);
    cudaGetSymbolAddress(&p_w1,   g_wt1_16);
    cudaGetSymbolAddress(&p_w2,   g_wt2_16);
    cudaGetSymbolAddress(&p_ln16, g_ln16);
    cudaGetSymbolAddress(&p_ff16, g_ff16);

    cudaFuncSetAttribute(attn_kernel,
        cudaFuncAttributeMaxDynamicSharedMemorySize, ATTN_SMEM);
    cudaFuncSetAttribute(gemm_any<3, 256>,
        cudaFuncAttributeMaxDynamicSharedMemorySize, G_SMEM_T(256));
    cudaFuncSetAttribute(gemm_any<1, 128>,
        cudaFuncAttributeMaxDynamicSharedMemorySize, G_SMEM_T(128));
    cudaFuncSetAttribute(gemm_any<4, 256>,
        cudaFuncAttributeMaxDynamicSharedMemorySize, G_SMEM_T(256));
    cudaFuncSetAttribute(gemm_any<5, 128>,
        cudaFuncAttributeMaxDynamicSharedMemorySize, G_SMEM_T(128));

    // 0. weight transposes — single launch (QKV/O -> tf32, W1/W2 -> fp16)
    transpose_all<<<12288, 256>>>(Wqkv, Wo, W1, W2,
                                  (float*)p_wqkv, (float*)p_wo,
                                  (__half*)p_w1, (__half*)p_w2);

    // 1. LN1 (tf32 fp32 out)
    ln_kernel<false><<<T_SEQ, 256>>>(x, ln1g, ln1b, p_ln);
    // 2. QKV (tf32) -> bf16 q/k/v buffers
    gemm_any<3, 256><<<dim3(12, 16), 256, G_SMEM_T(256)>>>(
        p_ln, p_wqkv, bqkv, nullptr, nullptr, T_SEQ, 3 * DM, DM);
    // 3. attention
    attn_kernel<<<dim3(32, 16), 256, ATTN_SMEM>>>(amask, (float*)p_y);
    // 4. x2 = x + y @ W_o + b_o  (tf32)
    gemm_any<1, 128><<<dim3(4, 32), 256, G_SMEM_T(128)>>>(
        p_y, p_wo, bo, x, (float*)p_x2, T_SEQ, DM, DM);
    // 5. LN2 (fp16 out)
    ln_kernel<true><<<T_SEQ, 256>>>((float*)p_x2, ln2g, ln2b, p_ln16);
    // 6. FF1 (fp16): gelu -> fp16 g_ff16
    gemm_any<4, 256><<<dim3(16, 16), 256, G_SMEM_T(256)>>>(
        p_ln16, p_w1, b1, nullptr, nullptr, T_SEQ, DFF, DM);
    // 7. FF2 (fp16): out = x2 + ff @ W2 + b2
    gemm_any<5, 128><<<dim3(4, 32), 256, G_SMEM_T(128)>>>(
        p_ff16, p_w2, b2, (float*)p_x2, out, T_SEQ, DM, DFF);
}

// round 14
// speedup vs baseline: 1.4105x; 1.0598x over previous
#include <cuda_runtime.h>
#include <cuda_bf16.h>
#include <cuda_fp16.h>
#include <cstdint>
#include <math.h>

#define T_SEQ   4096
#define DM      1024
#define DFF     4096
#define NHEADS  16
#define HDIM    64
#define LN_EPS  1e-5f

// ---- arch-specific feature gate: tcgen05 only exists on sm_10xa/f targets ----
#if defined(__CUDA_ARCH__)
#  if defined(__CUDA_ARCH_FEAT_SM103_ALL) || defined(__CUDA_ARCH_FEAT_SM100_ALL) || defined(__CUDA_ARCH_FEAT_SM101_ALL)
#    define GEMM_TC 1
#  elif defined(__CUDA_ARCH_SPECIFIC__)
#    define GEMM_TC ((__CUDA_ARCH_SPECIFIC__ >= 1000) ? 1 : 0)
#  elif defined(__CUDA_ARCH_FAMILY_SPECIFIC__)
#    define GEMM_TC ((__CUDA_ARCH_FAMILY_SPECIFIC__ >= 1000) ? 1 : 0)
#  else
#    define GEMM_TC 0
#  endif
#else
#  define GEMM_TC 0
#endif

// ---------------- scratch (static device globals; no allocation) ----------------
static __device__ float g_x2 [T_SEQ * DM];           // residual after attn (fp32)
// fp16 weights [N,K] K-major
static __device__ __half g_wqkv16[3 * DM * DM];
static __device__ __half g_wo16  [DM * DM];
static __device__ __half g_w1_16 [DFF * DM];
static __device__ __half g_w2_16 [DM * DFF];
// fp16 activations
static __device__ __half g_ln16[T_SEQ * DM];   // LN1 out, then LN2 out (sequential reuse)
static __device__ __half g_y16 [T_SEQ * DM];   // attention out
static __device__ __half g_ff16[T_SEQ * DFF];  // gelu out
// bf16 attention operands written by the QKV GEMM epilogue
static __device__ __nv_bfloat16 g_q16[NHEADS * T_SEQ * HDIM];     // [h][t][d], scaled log2e/8
static __device__ __nv_bfloat16 g_k16[NHEADS * T_SEQ * HDIM];     // [h][t][d]
static __device__ uint32_t      g_v16[NHEADS * (T_SEQ/2) * HDIM]; // [h][t/2][d] pair-packed

#define QSCALE 0.18033688011112042f   // (1/8) * log2(e)

// ---------------- helpers ----------------
__device__ __forceinline__ uint32_t packbf(float hi, float lo) {
    uint32_t r;
    asm("cvt.rn.bf16x2.f32 %0, %1, %2;" : "=r"(r) : "f"(hi), "f"(lo));
    return r;
}

__device__ __forceinline__ uint32_t packh(float hi, float lo) {
    uint32_t r;
    asm("cvt.rn.f16x2.f32 %0, %1, %2;" : "=r"(r) : "f"(hi), "f"(lo));
    return r;
}

__device__ __forceinline__ float ex2(float x) {
    float r;
    asm("ex2.approx.f32 %0, %1;" : "=f"(r) : "f"(x));
    return r;
}

__device__ __forceinline__ void mma_f16(float* c,
    uint32_t a0, uint32_t a1, uint32_t a2, uint32_t a3,
    uint32_t b0, uint32_t b1)
{
    asm volatile(
        "mma.sync.aligned.m16n8k16.row.col.f32.f16.f16.f32 "
        "{%0,%1,%2,%3}, {%4,%5,%6,%7}, {%8,%9}, {%0,%1,%2,%3};\n"
        : "+f"(c[0]), "+f"(c[1]), "+f"(c[2]), "+f"(c[3])
        : "r"(a0), "r"(a1), "r"(a2), "r"(a3), "r"(b0), "r"(b1));
}

__device__ __forceinline__ void mma_bf16(float* c,
    uint32_t a0, uint32_t a1, uint32_t a2, uint32_t a3,
    uint32_t b0, uint32_t b1)
{
    asm volatile(
        "mma.sync.aligned.m16n8k16.row.col.f32.bf16.bf16.f32 "
        "{%0,%1,%2,%3}, {%4,%5,%6,%7}, {%8,%9}, {%0,%1,%2,%3};\n"
        : "+f"(c[0]), "+f"(c[1]), "+f"(c[2]), "+f"(c[3])
        : "r"(a0), "r"(a1), "r"(a2), "r"(a3), "r"(b0), "r"(b1));
}

__device__ __forceinline__ void cp16(uint32_t dst, const void* src) {
    asm volatile("cp.async.ca.shared.global [%0], [%1], 16;\n"
                 :: "r"(dst), "l"(src));
}

__device__ __forceinline__ float gelu_exact(float v) {
    return 0.5f * v * (1.0f + erff(v * 0.70710678118654752440f));
}

__device__ __forceinline__ float4 ld4h(const void* p, size_t elem) {
    uint2 t = *(const uint2*)((const __half*)p + elem);
    float2 a = __half22float2(*(__half2*)&t.x);
    float2 b = __half22float2(*(__half2*)&t.y);
    float4 v; v.x = a.x; v.y = a.y; v.z = b.x; v.w = b.y;
    return v;
}

// ---------------- merged weight transpose (one launch): all -> fp16 [N,K] ----
__global__ __launch_bounds__(256) void transpose_all(
    const float* __restrict__ Wqkv, const float* __restrict__ Wo,
    const float* __restrict__ W1,   const float* __restrict__ W2,
    __half* __restrict__ oqkv, __half* __restrict__ oo,
    __half* __restrict__ o1,   __half* __restrict__ o2)
{
    __shared__ float t[32][33];
    int tb = blockIdx.x;
    const float* in; __half* out; int R, C, txw;
    if (tb < 3072)      { in = Wqkv; out = oqkv; R = 1024; C = 3072; txw = 96; }
    else if (tb < 4096) { tb -= 3072; in = Wo; out = oo; R = 1024; C = 1024; txw = 32; }
    else if (tb < 8192) { tb -= 4096; in = W1; out = o1; R = 1024; C = 4096; txw = 128; }
    else                { tb -= 8192; in = W2; out = o2; R = 4096; C = 1024; txw = 32; }
    int bx = (tb % txw) * 32, by = (tb / txw) * 32;
    int x = threadIdx.x & 31, y = threadIdx.x >> 5;
    #pragma unroll
    for (int i = 0; i < 32; i += 8)
        t[y + i][x] = in[(size_t)(by + y + i) * C + bx + x];
    __syncthreads();
    #pragma unroll
    for (int i = 0; i < 32; i += 8)
        out[(size_t)(bx + y + i) * R + by + x] = __float2half_rn(t[x][y + i]);
}

// ---------------- LayerNorm -> fp16 out ----------------
__global__ __launch_bounds__(256) void ln_kernel(
    const float* __restrict__ x, const float* __restrict__ g,
    const float* __restrict__ b, __half* __restrict__ outp)
{
    int row = blockIdx.x;
    int tid = threadIdx.x;
    const float4 v = ((const float4*)(x + (size_t)row * DM))[tid];
    float s  = v.x + v.y + v.z + v.w;
    float sq = v.x * v.x + v.y * v.y + v.z * v.z + v.w * v.w;
    #pragma unroll
    for (int o = 16; o; o >>= 1) {
        s  += __shfl_xor_sync(0xffffffffu, s,  o);
        sq += __shfl_xor_sync(0xffffffffu, sq, o);
    }
    __shared__ float ss[8], ssq[8];
    __shared__ float mean_s, inv_s;
    int w = tid >> 5, l = tid & 31;
    if (l == 0) { ss[w] = s; ssq[w] = sq; }
    __syncthreads();
    if (tid == 0) {
        float st = 0.f, sqt = 0.f;
        #pragma unroll
        for (int i = 0; i < 8; i++) { st += ss[i]; sqt += ssq[i]; }
        float mean = st * (1.0f / DM);
        float var  = sqt * (1.0f / DM) - mean * mean;
        mean_s = mean;
        inv_s  = rsqrtf(var + LN_EPS);
    }
    __syncthreads();
    float mean = mean_s, inv = inv_s;
    const float4 gv = ((const float4*)g)[tid];
    const float4 bv = ((const float4*)b)[tid];
    float o0 = (v.x - mean) * inv * gv.x + bv.x;
    float o1 = (v.y - mean) * inv * gv.y + bv.y;
    float o2 = (v.z - mean) * inv * gv.z + bv.z;
    float o3 = (v.w - mean) * inv * gv.w + bv.w;
    uint32_t* o16 = (uint32_t*)outp;
    size_t wi = ((size_t)row * DM + tid * 4) >> 1;
    o16[wi]     = packh(o1, o0);
    o16[wi + 1] = packh(o3, o2);
}

// ---------------- unified fp16 GEMM: C[M,N] = A[M,K] @ Bt[N,K]^T + epilogue --
// Tile TM x 256, 256 threads. grid = (N/256, M/TM). 128B rows = 64 fp16 K-elems.
// MODE 3: QKV -> bf16 q/k/v bufs   MODE 4: gelu(+bias) -> fp16
// MODE 5: +bias+res(fp32) -> fp32
#define GS        3
#define G_BASE    1024
#define G_SMEM_T(TM) (G_BASE + GS * ((TM) * 128 + 32768))

#if GEMM_TC
__device__ __forceinline__ bool elect_one() {
    uint32_t pred;
    asm volatile(
        "{\n\t.reg .pred p;\n\t"
        "elect.sync _|p, 0xFFFFFFFF;\n\t"
        "selp.b32 %0, 1, 0, p;\n\t}"
        : "=r"(pred));
    return pred != 0;
}
__device__ __forceinline__ uint64_t make_desc(uint32_t addr) {
    const uint64_t base = (2ULL << 61) | (1ULL << 46) | (64ULL << 32) | (1ULL << 16);
    return base | ((uint64_t)(addr >> 4) & 0x3FFF);
}
__device__ __forceinline__ void tc_mma_f16_ss(uint32_t d, uint64_t ad, uint64_t bd,
                                              uint32_t idesc, bool acc)
{
    uint32_t en = acc ? 1u : 0u;
    asm volatile(
        "{\n\t.reg .pred p;\n\t"
        "setp.ne.u32 p, %4, 0;\n\t"
        "tcgen05.mma.cta_group::1.kind::f16 [%0], %1, %2, %3, {%5, %5, %5, %5}, p;\n\t}"
        :: "r"(d), "l"(ad), "l"(bd), "r"(idesc), "r"(en), "r"(0u)
        : "memory");
}
#define MBAR_INIT(a, c) \
    asm volatile("mbarrier.init.shared.b64 [%0], %1;" :: "r"(a), "r"(c) : "memory")
#define MBAR_WAIT(a, par) do { \
    uint32_t _m = (a), _p = (par), _d; \
    asm volatile("{\n\t.reg .pred p;\n\t" \
        "mbarrier.try_wait.parity.acquire.cta.shared::cta.b64 p, [%1], %2;\n\t" \
        "selp.b32 %0, 1, 0, p;\n\t}" : "=r"(_d) : "r"(_m), "r"(_p) : "memory"); \
    if (!_d) { \
        asm volatile("{\n\t.reg .pred P1;\n\t" \
            "WL_%=:\n\t" \
            "mbarrier.try_wait.parity.acquire.cta.shared::cta.b64 P1, [%0], %1, 0x989680;\n\t" \
            "@P1 bra.uni WD_%=;\n\t" \
            "bra.uni WL_%=;\n\t" \
            "WD_%=:\n\t}" :: "r"(_m), "r"(_p) : "memory"); \
    } \
} while (0)
#define CPASYNC_MBAR_ARRIVE_NOINC(a) \
    asm volatile("cp.async.mbarrier.arrive.noinc.shared.b64 [%0];" :: "r"(a) : "memory")
#endif  // GEMM_TC

// epilogue write helper for MODE 3 (pair of adjacent columns, one row)
__device__ __forceinline__ void qkv_write_pair(int n, int row, float v0, float v1) {
    if (n < 1024) {
        int hd = n >> 6, d = n & 63;
        ((uint32_t*)g_q16)[(((size_t)hd * T_SEQ + row) * 64 + d) >> 1]
            = packbf(v1 * QSCALE, v0 * QSCALE);
    } else if (n < 2048) {
        int hd = (n - 1024) >> 6, d = (n - 1024) & 63;
        ((uint32_t*)g_k16)[(((size_t)hd * T_SEQ + row) * 64 + d) >> 1]
            = packbf(v1, v0);
    } else {
        int hd = (n - 2048) >> 6, d = (n - 2048) & 63;
        __nv_bfloat16* vp = (__nv_bfloat16*)g_v16;
        size_t wi = ((size_t)hd * (T_SEQ / 2) + (row >> 1)) * 64 + d;
        vp[wi * 2 + (row & 1)]       = __float2bfloat16(v0);
        vp[(wi + 1) * 2 + (row & 1)] = __float2bfloat16(v1);
    }
}

template<int MODE, int TM>
__global__ __launch_bounds__(256)
void gemm_any(const __half* __restrict__ A, const __half* __restrict__ Bt,
              const float* __restrict__ bias, const float* __restrict__ res,
              float* __restrict__ C, int M, int N, int K)
{
    extern __shared__ __align__(1024) char gsm[];
    const int tid = threadIdx.x, wid = tid >> 5, lane = tid & 31;

#if GEMM_TC
    // ================= tcgen05 kind::f16 path (TM x 256 tile) ================
    constexpr int A_TILE = TM * 128;
    constexpr int STAGE  = A_TILE + 32768;
    constexpr int TCOLS  = (TM == 256) ? 512 : 256;
    const int m0 = blockIdx.y * TM, n0 = blockIdx.x * 256;
    const uint32_t sb = (uint32_t)__cvta_generic_to_shared(gsm);
    const uint32_t mb0 = sb + 16, mb1 = sb + 24;
    const uint32_t fmb = sb + 32;

    if (wid == 0) {
        asm volatile("tcgen05.alloc.cta_group::1.sync.aligned.shared::cta.b32 [%0], %1;"
                     :: "r"(sb), "r"((uint32_t)TCOLS) : "memory");
        asm volatile("tcgen05.relinquish_alloc_permit.cta_group::1.sync.aligned;");
    }
    if (tid == 0) {
        MBAR_INIT(mb0, 1); MBAR_INIT(mb1, 1);
        MBAR_INIT(fmb + 0, 256); MBAR_INIT(fmb + 8, 256); MBAR_INIT(fmb + 16, 256);
    }
    __syncthreads();
    uint32_t tb;
    asm volatile("ld.shared.b32 %0, [%1];" : "=r"(tb) : "r"(sb));

    const int KT = K >> 6;                   // 64 fp16 elems per 128B stage row
    const size_t rowB = (size_t)K * 2;

    auto fill = [&](int slot, int ktile) {
        uint32_t s = sb + G_BASE + slot * STAGE;
        const char* Ab = (const char*)A + ((size_t)m0 * K + (size_t)ktile * 64) * 2;
        const char* Bb = (const char*)Bt + ((size_t)n0 * K + (size_t)ktile * 64) * 2;
        #pragma unroll
        for (int i = 0; i < TM / 32; i++) {
            int idx = tid + i * 256;
            int r = idx >> 3, ch = (idx & 7) * 16;
            uint32_t byte = (uint32_t)(r * 128 + ch);
            uint32_t sw = byte ^ ((byte >> 3) & 0x70);
            cp16(s + sw, Ab + (size_t)r * rowB + ch);
        }
        #pragma unroll
        for (int i = 0; i < 8; i++) {
            int idx = tid + i * 256;
            int r = idx >> 3, ch = (idx & 7) * 16;
            uint32_t byte = (uint32_t)(r * 128 + ch);
            uint32_t sw = byte ^ ((byte >> 3) & 0x70);
            cp16(s + A_TILE + sw, Bb + (size_t)r * rowB + ch);
        }
        CPASYNC_MBAR_ARRIVE_NOINC(fmb + slot * 8);
    };

    #pragma unroll
    for (int st = 0; st < GS - 1; st++) fill(st, st);

    // idesc: accum F32, atype=btype=F16(0), N=256, M=128
    const uint32_t idesc = (1u << 4) | (0u << 7) | (0u << 10)
                         | (32u << 17) | (8u << 24);

    int ph0 = 0, ph1 = 0;
    for (int kt = 0; kt < KT; kt++) {
        if (wid == 0) {
            int slot = kt % GS;
            int fph = (kt / GS) & 1;
            MBAR_WAIT(fmb + slot * 8, fph);
            asm volatile("fence.proxy.async.shared::cta;" ::: "memory");
            if (elect_one()) {
                uint32_t s = sb + G_BASE + slot * STAGE;
                uint64_t ad = make_desc(s);
                uint64_t bd = make_desc(s + A_TILE);
                #pragma unroll
                for (int ks = 0; ks < 4; ks++) {
                    bool acc = (kt > 0) || (ks > 0);
                    tc_mma_f16_ss(tb, ad + ks * 2, bd + ks * 2, idesc, acc);
                    if (TM == 256)
                        tc_mma_f16_ss(tb + 256, ad + 1024 + ks * 2, bd + ks * 2, idesc, acc);
                }
                uint32_t mb = (kt & 1) ? mb1 : mb0;
                asm volatile(
                    "tcgen05.commit.cta_group::1.mbarrier::arrive::one.shared::cluster.b64 [%0];"
                    :: "r"(mb) : "memory");
            }
        }

        if (kt >= 1) {
            if ((kt - 1) & 1) { MBAR_WAIT(mb1, ph1); ph1 ^= 1; }
            else              { MBAR_WAIT(mb0, ph0); ph0 ^= 1; }
        }
        if (kt + GS - 1 < KT) fill((kt + GS - 1) % GS, kt + GS - 1);
    }

    if ((KT - 1) & 1) { MBAR_WAIT(mb1, ph1); }
    else              { MBAR_WAIT(mb0, ph0); }
    asm volatile("tcgen05.fence::after_thread_sync;" ::: "memory");

    {
        int row; uint32_t dbase; int cstart;
        if (TM == 256) {
            row = m0 + ((wid < 4) ? wid * 32 : 128 + (wid - 4) * 32) + lane;
            dbase = tb + ((wid < 4) ? 0u : 256u);
            cstart = 0;
        } else {
            row = m0 + (wid & 3) * 32 + lane;
            dbase = tb;
            cstart = (wid < 4) ? 0 : 128;
        }
        const int cspan = (TM == 256) ? 256 : 128;
        #pragma unroll
        for (int ci = 0; ci < 256; ci += 32) {
            if (ci >= cspan) break;
            const int c0 = cstart + ci;
            float d[32];
            asm volatile(
                "tcgen05.ld.sync.aligned.32x32b.x32.b32 "
                "{%0,%1,%2,%3,%4,%5,%6,%7,%8,%9,%10,%11,%12,%13,%14,%15,"
                "%16,%17,%18,%19,%20,%21,%22,%23,%24,%25,%26,%27,%28,%29,%30,%31}, [%32];"
                : "=f"(d[0]),  "=f"(d[1]),  "=f"(d[2]),  "=f"(d[3]),
                  "=f"(d[4]),  "=f"(d[5]),  "=f"(d[6]),  "=f"(d[7]),
                  "=f"(d[8]),  "=f"(d[9]),  "=f"(d[10]), "=f"(d[11]),
                  "=f"(d[12]), "=f"(d[13]), "=f"(d[14]), "=f"(d[15]),
                  "=f"(d[16]), "=f"(d[17]), "=f"(d[18]), "=f"(d[19]),
                  "=f"(d[20]), "=f"(d[21]), "=f"(d[22]), "=f"(d[23]),
                  "=f"(d[24]), "=f"(d[25]), "=f"(d[26]), "=f"(d[27]),
                  "=f"(d[28]), "=f"(d[29]), "=f"(d[30]), "=f"(d[31])
                : "r"(dbase + c0));
            asm volatile("tcgen05.wait::ld.sync.aligned;" ::: "memory");

            #pragma unroll
            for (int c = 0; c < 32; c += 4) {
                const int n = n0 + c0 + c;
                const float4 bv = *(const float4*)(bias + n);
                float4 v;
                v.x = d[c + 0] + bv.x; v.y = d[c + 1] + bv.y;
                v.z = d[c + 2] + bv.z; v.w = d[c + 3] + bv.w;
                if (MODE == 3) {
                    qkv_write_pair(n,     row, v.x, v.y);
                    qkv_write_pair(n + 2, row, v.z, v.w);
                } else if (MODE == 4) {
                    uint32_t* o16 = (uint32_t*)g_ff16;
                    size_t wi = ((size_t)row * N + n) >> 1;
                    o16[wi]     = packh(gelu_exact(v.y), gelu_exact(v.x));
                    o16[wi + 1] = packh(gelu_exact(v.w), gelu_exact(v.z));
                } else {
                    const float4 rv = *(const float4*)(res + (size_t)row * N + n);
                    v.x += rv.x; v.y += rv.y; v.z += rv.z; v.w += rv.w;
                    *(float4*)(C + (size_t)row * N + n) = v;
                }
            }
        }
    }

    __syncthreads();
    if (tid == 0) {
        asm volatile("mbarrier.inval.shared.b64 [%0];" :: "r"(mb0) : "memory");
        asm volatile("mbarrier.inval.shared.b64 [%0];" :: "r"(mb1) : "memory");
        asm volatile("mbarrier.inval.shared.b64 [%0];" :: "r"(fmb + 0) : "memory");
        asm volatile("mbarrier.inval.shared.b64 [%0];" :: "r"(fmb + 8) : "memory");
        asm volatile("mbarrier.inval.shared.b64 [%0];" :: "r"(fmb + 16) : "memory");
    }
    __syncthreads();
    if (wid == 0)
        asm volatile("tcgen05.dealloc.cta_group::1.sync.aligned.b32 %0, %1;"
                     :: "r"(tb), "r"((uint32_t)TCOLS));

#else
    // ================= mma.sync fp16 fallback: (TM/128)x2 subtiles ==============
    float* As = (float*)gsm;
    float* Bs = As + 2 * 16 * 132;
    #define AS(buf, k, m) As[((buf) * 16 + (k)) * 132 + (m)]
    #define BS(buf, k, n) Bs[((buf) * 16 + (k)) * 132 + (n)]

    const int wm = wid >> 2, wn = wid & 3;
    const int gp = lane >> 2, tg = lane & 3;

    for (int mi = 0; mi < TM / 128; mi++)
    for (int ni = 0; ni < 2; ni++) {
        const int m0 = blockIdx.y * TM + mi * 128;
        const int n0 = blockIdx.x * 256 + ni * 128;

        float c[4][4][4];
        #pragma unroll
        for (int i = 0; i < 4; i++)
            #pragma unroll
            for (int j = 0; j < 4; j++)
                #pragma unroll
                for (int r = 0; r < 4; r++) c[i][j][r] = 0.f;

        const int KT = K >> 4;
        float4 va[2], vb[2];

        __syncthreads();
        #pragma unroll
        for (int i = 0; i < 2; i++) {
            int idx = tid + i * 256;
            int r = idx >> 2, c4 = (idx & 3) << 2;
            va[i] = ld4h(A,  (size_t)(m0 + r) * K + c4);
            vb[i] = ld4h(Bt, (size_t)(n0 + r) * K + c4);
        }
        #pragma unroll
        for (int i = 0; i < 2; i++) {
            int idx = tid + i * 256;
            int r = idx >> 2, c4 = (idx & 3) << 2;
            AS(0, c4 + 0, r) = va[i].x; AS(0, c4 + 1, r) = va[i].y;
            AS(0, c4 + 2, r) = va[i].z; AS(0, c4 + 3, r) = va[i].w;
            BS(0, c4 + 0, r) = vb[i].x; BS(0, c4 + 1, r) = vb[i].y;
            BS(0, c4 + 2, r) = vb[i].z; BS(0, c4 + 3, r) = vb[i].w;
        }
        __syncthreads();

        int cur = 0;
        for (int kt = 0; kt < KT; kt++) {
            if (kt + 1 < KT) {
                #pragma unroll
                for (int i = 0; i < 2; i++) {
                    int idx = tid + i * 256;
                    int r = idx >> 2, c4 = (idx & 3) << 2;
                    va[i] = ld4h(A,  (size_t)(m0 + r) * K + (kt + 1) * 16 + c4);
                    vb[i] = ld4h(Bt, (size_t)(n0 + r) * K + (kt + 1) * 16 + c4);
                }
            }
            // pack smem floats -> fp16x2 fragments, one m16n8k16 step per 16 k
            {
                uint32_t a[4][4], b[4][2];
                #pragma unroll
                for (int mf = 0; mf < 4; mf++) {
                    int r0 = wm * 64 + mf * 16;
                    a[mf][0] = packh(AS(cur, 2*tg+1, r0 + gp    ), AS(cur, 2*tg,   r0 + gp    ));
                    a[mf][1] = packh(AS(cur, 2*tg+1, r0 + gp + 8), AS(cur, 2*tg,   r0 + gp + 8));
                    a[mf][2] = packh(AS(cur, 2*tg+9, r0 + gp    ), AS(cur, 2*tg+8, r0 + gp    ));
                    a[mf][3] = packh(AS(cur, 2*tg+9, r0 + gp + 8), AS(cur, 2*tg+8, r0 + gp + 8));
                }
                #pragma unroll
                for (int nf = 0; nf < 4; nf++) {
                    int c0 = wn * 32 + nf * 8;
                    b[nf][0] = packh(BS(cur, 2*tg+1, c0 + gp), BS(cur, 2*tg,   c0 + gp));
                    b[nf][1] = packh(BS(cur, 2*tg+9, c0 + gp), BS(cur, 2*tg+8, c0 + gp));
                }
                #pragma unroll
                for (int mf = 0; mf < 4; mf++)
                    #pragma unroll
                    for (int nf = 0; nf < 4; nf++)
                        mma_f16(c[mf][nf], a[mf][0], a[mf][1], a[mf][2], a[mf][3],
                                b[nf][0], b[nf][1]);
            }
            if (kt + 1 < KT) {
                int nxt = cur ^ 1;
                #pragma unroll
                for (int i = 0; i < 2; i++) {
                    int idx = tid + i * 256;
                    int r = idx >> 2, c4 = (idx & 3) << 2;
                    AS(nxt, c4 + 0, r) = va[i].x; AS(nxt, c4 + 1, r) = va[i].y;
                    AS(nxt, c4 + 2, r) = va[i].z; AS(nxt, c4 + 3, r) = va[i].w;
                    BS(nxt, c4 + 0, r) = vb[i].x; BS(nxt, c4 + 1, r) = vb[i].y;
                    BS(nxt, c4 + 2, r) = vb[i].z; BS(nxt, c4 + 3, r) = vb[i].w;
                }
                __syncthreads();
                cur = nxt;
            }
        }

        #pragma unroll
        for (int mf = 0; mf < 4; mf++) {
            #pragma unroll
            for (int nf = 0; nf < 4; nf++) {
                int col = n0 + wn * 32 + nf * 8 + 2 * tg;
                float bi0 = bias[col], bi1 = bias[col + 1];
                #pragma unroll
                for (int hh = 0; hh < 2; hh++) {
                    int row = m0 + wm * 64 + mf * 16 + gp + hh * 8;
                    float v0 = c[mf][nf][hh * 2 + 0] + bi0;
                    float v1 = c[mf][nf][hh * 2 + 1] + bi1;
                    if (MODE == 3) {
                        qkv_write_pair(col, row, v0, v1);
                    } else if (MODE == 4) {
                        ((uint32_t*)g_ff16)[((size_t)row * N + col) >> 1]
                            = packh(gelu_exact(v1), gelu_exact(v0));
                    } else {
                        const float2 rv = *(const float2*)(res + (size_t)row * N + col);
                        v0 += rv.x; v1 += rv.y;
                        float2 o; o.x = v0; o.y = v1;
                        *(float2*)(C + (size_t)row * N + col) = o;
                    }
                }
            }
        }
    }
    #undef AS
    #undef BS
#endif
}

// ---------------- causal flash attention (R11 winner; y -> fp16) --------
#define AQ_OFF  0
#define AK_OFF  4608
#define AV_OFF  9216
#define AM_OFF  13824
#define ATTN_SMEM ((13824 + 128) * 4)   // 55808

__global__ __launch_bounds__(256, 2) void attn_kernel(
    const int* __restrict__ amask, __half* __restrict__ y)
{
    extern __shared__ uint32_t shw[];
    uint32_t* Qs = shw + AQ_OFF;
    uint32_t* Ks = shw + AK_OFF;
    uint32_t* Vs = shw + AV_OFF;
    int*      mk = (int*)(shw + AM_OFF);

    const int tid = threadIdx.x, lane = tid & 31, w = tid >> 5;
    const int gp = lane >> 2, tg = lane & 3;
    const int h = blockIdx.y;
    const int q0 = (gridDim.x - 1 - blockIdx.x) * 128;
    const int qw = q0 + w * 16;

    {
        const __nv_bfloat16* qb = g_q16 + ((size_t)h * T_SEQ + q0) * 64;
        #pragma unroll
        for (int i = 0; i < 4; i++) {
            int idx = tid + i * 256;
            int r = idx >> 3, ch = idx & 7;
            cp16((uint32_t)__cvta_generic_to_shared(Qs + r * 36 + ch * 4),
                 qb + (size_t)r * 64 + ch * 8);
        }
    }
    asm volatile("cp.async.commit_group;" ::: "memory");

    auto fill_kv = [&](int buf, int kt) {
        const __nv_bfloat16* kbs = g_k16 + ((size_t)h * T_SEQ + kt * 64) * 64;
        #pragma unroll
        for (int i = 0; i < 2; i++) {
            int idx = tid + i * 256;
            int r = idx >> 3, ch = idx & 7;
            cp16((uint32_t)__cvta_generic_to_shared(Ks + buf * 2304 + r * 36 + ch * 4),
                 kbs + (size_t)r * 64 + ch * 8);
        }
        const uint32_t* vbs = g_v16 + ((size_t)h * (T_SEQ / 2) + kt * 32) * 64;
        #pragma unroll
        for (int i = 0; i < 2; i++) {
            int idx = tid + i * 256;
            int pr = idx >> 4, ch = idx & 15;
            cp16((uint32_t)__cvta_generic_to_shared(Vs + buf * 2304 + pr * 72 + ch * 4),
                 vbs + (size_t)pr * 64 + ch * 4);
        }
        if (tid < 16)
            cp16((uint32_t)__cvta_generic_to_shared(mk + buf * 64 + tid * 4),
                 amask + kt * 64 + tid * 4);
    };

    fill_kv(0, 0);
    asm volatile("cp.async.commit_group;" ::: "memory");
    asm volatile("cp.async.wait_group 0;" ::: "memory");
    __syncthreads();

    uint32_t qa[4][4];
    {
        int r0 = w * 16;
        #pragma unroll
        for (int ks = 0; ks < 4; ks++) {
            qa[ks][0] = Qs[(r0 + gp    ) * 36 + 8 * ks + tg    ];
            qa[ks][1] = Qs[(r0 + gp + 8) * 36 + 8 * ks + tg    ];
            qa[ks][2] = Qs[(r0 + gp    ) * 36 + 8 * ks + 4 + tg];
            qa[ks][3] = Qs[(r0 + gp + 8) * 36 + 8 * ks + 4 + tg];
        }
    }

    float m0 = -INFINITY, m1 = -INFINITY, l0 = 0.f, l1 = 0.f;
    float o[8][4];
    #pragma unroll
    for (int nf = 0; nf < 8; nf++)
        #pragma unroll
        for (int r = 0; r < 4; r++) o[nf][r] = 0.f;

    const int ktmax = (q0 + 127) >> 6;
    const int kdiag = q0 >> 6;
    const int row0 = qw + gp, row1 = qw + gp + 8;
    int cur = 0;

    for (int kt = 0; kt <= ktmax; kt++) {
        asm volatile("cp.async.wait_group 0;" ::: "memory");
        __syncthreads();

        if (kt < ktmax) {
            fill_kv(cur ^ 1, kt + 1);
            asm volatile("cp.async.commit_group;" ::: "memory");
        }

        const uint32_t* K = Ks + cur * 2304;
        const uint32_t* V = Vs + cur * 2304;
        const int*      M = mk + cur * 64;
        const bool diag = (kt >= kdiag);

        float sc[8][4];
        #pragma unroll
        for (int nf = 0; nf < 8; nf++)
            #pragma unroll
            for (int r = 0; r < 4; r++) sc[nf][r] = 0.f;

        #pragma unroll
        for (int ks = 0; ks < 4; ks++) {
            #pragma unroll
            for (int nf = 0; nf < 8; nf++) {
                uint32_t b0 = K[(nf * 8 + gp) * 36 + 8 * ks + tg    ];
                uint32_t b1 = K[(nf * 8 + gp) * 36 + 8 * ks + 4 + tg];
                mma_bf16(sc[nf], qa[ks][0], qa[ks][1], qa[ks][2], qa[ks][3], b0, b1);
            }
        }

        float tm0 = -INFINITY, tm1 = -INFINITY;
        if (diag) {
            #pragma unroll
            for (int nf = 0; nf < 8; nf++) {
                int cl = nf * 8 + 2 * tg;
                int c  = kt * 64 + cl;
                bool mk0 = M[cl] != 0, mk1 = M[cl + 1] != 0;
                float s0 = sc[nf][0], s1 = sc[nf][1];
                float s2 = sc[nf][2], s3 = sc[nf][3];
                s0 = (c     <= row0 && mk0) ? s0 : -INFINITY;
                s1 = (c + 1 <= row0 && mk1) ? s1 : -INFINITY;
                s2 = (c     <= row1 && mk0) ? s2 : -INFINITY;
                s3 = (c + 1 <= row1 && mk1) ? s3 : -INFINITY;
                sc[nf][0] = s0; sc[nf][1] = s1; sc[nf][2] = s2; sc[nf][3] = s3;
                tm0 = fmaxf(tm0, fmaxf(s0, s1));
                tm1 = fmaxf(tm1, fmaxf(s2, s3));
            }
        } else {
            #pragma unroll
            for (int nf = 0; nf < 8; nf++) {
                int cl = nf * 8 + 2 * tg;
                bool mk0 = M[cl] != 0, mk1 = M[cl + 1] != 0;
                float s0 = mk0 ? sc[nf][0] : -INFINITY;
                float s1 = mk1 ? sc[nf][1] : -INFINITY;
                float s2 = mk0 ? sc[nf][2] : -INFINITY;
                float s3 = mk1 ? sc[nf][3] : -INFINITY;
                sc[nf][0] = s0; sc[nf][1] = s1; sc[nf][2] = s2; sc[nf][3] = s3;
                tm0 = fmaxf(tm0, fmaxf(s0, s1));
                tm1 = fmaxf(tm1, fmaxf(s2, s3));
            }
        }
        tm0 = fmaxf(tm0, __shfl_xor_sync(0xffffffffu, tm0, 1));
        tm0 = fmaxf(tm0, __shfl_xor_sync(0xffffffffu, tm0, 2));
        tm1 = fmaxf(tm1, __shfl_xor_sync(0xffffffffu, tm1, 1));
        tm1 = fmaxf(tm1, __shfl_xor_sync(0xffffffffu, tm1, 2));

        float nm0 = fmaxf(m0, tm0), nm1 = fmaxf(m1, tm1);
        float ne0 = fmaxf(nm0, -1e30f), ne1 = fmaxf(nm1, -1e30f);
        float al0 = ex2(m0 - ne0), al1 = ex2(m1 - ne1);
        m0 = nm0; m1 = nm1;

        float ps0 = 0.f, ps1 = 0.f;
        #pragma unroll
        for (int nf = 0; nf < 8; nf++) {
            float p0 = ex2(sc[nf][0] - ne0);
            float p1 = ex2(sc[nf][1] - ne0);
            float p2 = ex2(sc[nf][2] - ne1);
            float p3 = ex2(sc[nf][3] - ne1);
            sc[nf][0] = p0; sc[nf][1] = p1; sc[nf][2] = p2; sc[nf][3] = p3;
            ps0 += p0 + p1; ps1 += p2 + p3;
        }
        ps0 += __shfl_xor_sync(0xffffffffu, ps0, 1);
        ps0 += __shfl_xor_sync(0xffffffffu, ps0, 2);
        ps1 += __shfl_xor_sync(0xffffffffu, ps1, 1);
        ps1 += __shfl_xor_sync(0xffffffffu, ps1, 2);
        l0 = l0 * al0 + ps0;
        l1 = l1 * al1 + ps1;

        #pragma unroll
        for (int nf = 0; nf < 8; nf++) {
            o[nf][0] *= al0; o[nf][1] *= al0;
            o[nf][2] *= al1; o[nf][3] *= al1;
        }

        #pragma unroll
        for (int ks = 0; ks < 4; ks++) {
            uint32_t pa0 = packbf(sc[2*ks  ][1], sc[2*ks  ][0]);
            uint32_t pa1 = packbf(sc[2*ks  ][3], sc[2*ks  ][2]);
            uint32_t pa2 = packbf(sc[2*ks+1][1], sc[2*ks+1][0]);
            uint32_t pa3 = packbf(sc[2*ks+1][3], sc[2*ks+1][2]);
            #pragma unroll
            for (int nf = 0; nf < 8; nf++) {
                uint32_t b0 = V[(8 * ks + tg    ) * 72 + nf * 8 + gp];
                uint32_t b1 = V[(8 * ks + 4 + tg) * 72 + nf * 8 + gp];
                mma_bf16(o[nf], pa0, pa1, pa2, pa3, b0, b1);
            }
        }
        cur ^= 1;
    }

    float il0 = 1.0f / fmaxf(l0, 1e-30f);
    float il1 = 1.0f / fmaxf(l1, 1e-30f);
    uint32_t* yw = (uint32_t*)y;
    #pragma unroll
    for (int nf = 0; nf < 8; nf++) {
        int col = h * HDIM + nf * 8 + 2 * tg;
        yw[((size_t)row0 * DM + col) >> 1] = packh(o[nf][1] * il0, o[nf][0] * il0);
        yw[((size_t)row1 * DM + col) >> 1] = packh(o[nf][3] * il1, o[nf][2] * il1);
    }
}

// ---------------- launcher ----------------
extern "C" void kernel_launch(void* const* d_in, const int* in_sizes, int n_in,
                              void* d_out, int out_size)
{
    const float* x     = (const float*)d_in[0];
    const int*   amask = (const int*)  d_in[1];
    const float* ln1g  = (const float*)d_in[2];
    const float* ln1b  = (const float*)d_in[3];
    const float* Wqkv  = (const float*)d_in[4];
    const float* bqkv  = (const float*)d_in[5];
    const float* Wo    = (const float*)d_in[6];
    const float* bo    = (const float*)d_in[7];
    const float* ln2g  = (const float*)d_in[8];
    const float* ln2b  = (const float*)d_in[9];
    const float* W1    = (const float*)d_in[10];
    const float* b1    = (const float*)d_in[11];
    const float* W2    = (const float*)d_in[12];
    const float* b2    = (const float*)d_in[13];
    float* out = (float*)d_out;

    void *p_x2, *p_wqkv, *p_wo, *p_w1, *p_w2, *p_ln16, *p_y16, *p_ff16;
    cudaGetSymbolAddress(&p_x2,   g_x2);
    cudaGetSymbolAddress(&p_wqkv, g_wqkv16);
    cudaGetSymbolAddress(&p_wo,   g_wo16);
    cudaGetSymbolAddress(&p_w1,   g_w1_16);
    cudaGetSymbolAddress(&p_w2,   g_w2_16);
    cudaGetSymbolAddress(&p_ln16, g_ln16);
    cudaGetSymbolAddress(&p_y16,  g_y16);
    cudaGetSymbolAddress(&p_ff16, g_ff16);

    cudaFuncSetAttribute(attn_kernel,
        cudaFuncAttributeMaxDynamicSharedMemorySize, ATTN_SMEM);
    cudaFuncSetAttribute(gemm_any<3, 256>,
        cudaFuncAttributeMaxDynamicSharedMemorySize, G_SMEM_T(256));
    cudaFuncSetAttribute(gemm_any<4, 256>,
        cudaFuncAttributeMaxDynamicSharedMemorySize, G_SMEM_T(256));
    cudaFuncSetAttribute(gemm_any<5, 128>,
        cudaFuncAttributeMaxDynamicSharedMemorySize, G_SMEM_T(128));

    // 0. weight transposes — single launch (all -> fp16 [N,K])
    transpose_all<<<12288, 256>>>(Wqkv, Wo, W1, W2,
                                  (__half*)p_wqkv, (__half*)p_wo,
                                  (__half*)p_w1, (__half*)p_w2);

    // 1. LN1 -> fp16
    ln_kernel<<<T_SEQ, 256>>>(x, ln1g, ln1b, (__half*)p_ln16);
    // 2. QKV (fp16) -> bf16 q/k/v buffers
    gemm_any<3, 256><<<dim3(12, 16), 256, G_SMEM_T(256)>>>(
        (__half*)p_ln16, (__half*)p_wqkv, bqkv, nullptr, nullptr, T_SEQ, 3 * DM, DM);
    // 3. attention -> fp16 y
    attn_kernel<<<dim3(32, 16), 256, ATTN_SMEM>>>(amask, (__half*)p_y16);
    // 4. x2 = x + y @ W_o + b_o  (fp16 in, fp32 out)
    gemm_any<5, 128><<<dim3(4, 32), 256, G_SMEM_T(128)>>>(
        (__half*)p_y16, (__half*)p_wo, bo, x, (float*)p_x2, T_SEQ, DM, DM);
    // 5. LN2 -> fp16 (reuses g_ln16; QKV GEMM already consumed it)
    ln_kernel<<<T_SEQ, 256>>>((float*)p_x2, ln2g, ln2b, (__half*)p_ln16);
    // 6. FF1 (fp16): gelu -> fp16 g_ff16
    gemm_any<4, 256><<<dim3(16, 16), 256, G_SMEM_T(256)>>>(
        (__half*)p_ln16, (__half*)p_w1, b1, nullptr, nullptr, T_SEQ, DFF, DM);
    // 7. FF2 (fp16): out = x2 + ff @ W2 + b2
    gemm_any<5, 128><<<dim3(4, 32), 256, G_SMEM_T(128)>>>(
        (__half*)p_ff16, (__half*)p_w2, b2, (float*)p_x2, out, T_SEQ, DM, DFF);
}

// round 15
// speedup vs baseline: 1.5193x; 1.0771x over previous
#include <cuda_runtime.h>
#include <cuda_fp16.h>
#include <cstdint>
#include <math.h>

#define T_SEQ   4096
#define DM      1024
#define DFF     4096
#define NHEADS  16
#define HDIM    64
#define LN_EPS  1e-5f

// ---- arch-specific feature gate: tcgen05 only exists on sm_10xa/f targets ----
#if defined(__CUDA_ARCH__)
#  if defined(__CUDA_ARCH_FEAT_SM103_ALL) || defined(__CUDA_ARCH_FEAT_SM100_ALL) || defined(__CUDA_ARCH_FEAT_SM101_ALL)
#    define GEMM_TC 1
#  elif defined(__CUDA_ARCH_SPECIFIC__)
#    define GEMM_TC ((__CUDA_ARCH_SPECIFIC__ >= 1000) ? 1 : 0)
#  elif defined(__CUDA_ARCH_FAMILY_SPECIFIC__)
#    define GEMM_TC ((__CUDA_ARCH_FAMILY_SPECIFIC__ >= 1000) ? 1 : 0)
#  else
#    define GEMM_TC 0
#  endif
#else
#  define GEMM_TC 0
#endif

// ---------------- scratch (static device globals; no allocation) ----------------
static __device__ float g_x2 [T_SEQ * DM];           // residual after attn (fp32)
// fp16 weights [N,K] K-major
static __device__ __half g_wqkv16[3 * DM * DM];
static __device__ __half g_wo16  [DM * DM];
static __device__ __half g_w1_16 [DFF * DM];
static __device__ __half g_w2_16 [DM * DFF];
// fp16 activations
static __device__ __half g_ln16[T_SEQ * DM];   // LN1 out, then LN2 out (sequential reuse)
static __device__ __half g_y16 [T_SEQ * DM];   // attention out
static __device__ __half g_ff16[T_SEQ * DFF];  // gelu out
// fp16 attention operands written by the QKV GEMM epilogue, all [h][t][d]
static __device__ __half g_q16[NHEADS * T_SEQ * HDIM];   // scaled log2e/8
static __device__ __half g_k16[NHEADS * T_SEQ * HDIM];
static __device__ __half g_v16[NHEADS * T_SEQ * HDIM];

#define QSCALE 0.18033688011112042f   // (1/8) * log2(e)

// ---------------- helpers ----------------
__device__ __forceinline__ uint32_t packh(float hi, float lo) {
    uint32_t r;
    asm("cvt.rn.f16x2.f32 %0, %1, %2;" : "=r"(r) : "f"(hi), "f"(lo));
    return r;
}

__device__ __forceinline__ float ex2(float x) {
    float r;
    asm("ex2.approx.f32 %0, %1;" : "=f"(r) : "f"(x));
    return r;
}

__device__ __forceinline__ uint32_t ex2h2(uint32_t x) {
    uint32_t r;
    asm("ex2.approx.f16x2 %0, %1;" : "=r"(r) : "r"(x));
    return r;
}

__device__ __forceinline__ void mma_f16(float* c,
    uint32_t a0, uint32_t a1, uint32_t a2, uint32_t a3,
    uint32_t b0, uint32_t b1)
{
    asm volatile(
        "mma.sync.aligned.m16n8k16.row.col.f32.f16.f16.f32 "
        "{%0,%1,%2,%3}, {%4,%5,%6,%7}, {%8,%9}, {%0,%1,%2,%3};\n"
        : "+f"(c[0]), "+f"(c[1]), "+f"(c[2]), "+f"(c[3])
        : "r"(a0), "r"(a1), "r"(a2), "r"(a3), "r"(b0), "r"(b1));
}

__device__ __forceinline__ void ldsm4(uint32_t* r, uint32_t a) {
    asm volatile("ldmatrix.sync.aligned.m8n8.x4.shared.b16 {%0,%1,%2,%3}, [%4];"
        : "=r"(r[0]), "=r"(r[1]), "=r"(r[2]), "=r"(r[3]) : "r"(a));
}
__device__ __forceinline__ void ldsm4t(uint32_t* r, uint32_t a) {
    asm volatile("ldmatrix.sync.aligned.m8n8.x4.trans.shared.b16 {%0,%1,%2,%3}, [%4];"
        : "=r"(r[0]), "=r"(r[1]), "=r"(r[2]), "=r"(r[3]) : "r"(a));
}

__device__ __forceinline__ void cp16(uint32_t dst, const void* src) {
    asm volatile("cp.async.ca.shared.global [%0], [%1], 16;\n"
                 :: "r"(dst), "l"(src));
}

__device__ __forceinline__ float gelu_exact(float v) {
    return 0.5f * v * (1.0f + erff(v * 0.70710678118654752440f));
}

__device__ __forceinline__ float4 ld4h(const void* p, size_t elem) {
    uint2 t = *(const uint2*)((const __half*)p + elem);
    float2 a = __half22float2(*(__half2*)&t.x);
    float2 b = __half22float2(*(__half2*)&t.y);
    float4 v; v.x = a.x; v.y = a.y; v.z = b.x; v.w = b.y;
    return v;
}

// ---------------- merged weight transpose (one launch): all -> fp16 [N,K] ----
__global__ __launch_bounds__(256) void transpose_all(
    const float* __restrict__ Wqkv, const float* __restrict__ Wo,
    const float* __restrict__ W1,   const float* __restrict__ W2,
    __half* __restrict__ oqkv, __half* __restrict__ oo,
    __half* __restrict__ o1,   __half* __restrict__ o2)
{
    __shared__ float t[32][33];
    int tb = blockIdx.x;
    const float* in; __half* out; int R, C, txw;
    if (tb < 3072)      { in = Wqkv; out = oqkv; R = 1024; C = 3072; txw = 96; }
    else if (tb < 4096) { tb -= 3072; in = Wo; out = oo; R = 1024; C = 1024; txw = 32; }
    else if (tb < 8192) { tb -= 4096; in = W1; out = o1; R = 1024; C = 4096; txw = 128; }
    else                { tb -= 8192; in = W2; out = o2; R = 4096; C = 1024; txw = 32; }
    int bx = (tb % txw) * 32, by = (tb / txw) * 32;
    int x = threadIdx.x & 31, y = threadIdx.x >> 5;
    #pragma unroll
    for (int i = 0; i < 32; i += 8)
        t[y + i][x] = in[(size_t)(by + y + i) * C + bx + x];
    __syncthreads();
    #pragma unroll
    for (int i = 0; i < 32; i += 8)
        out[(size_t)(bx + y + i) * R + by + x] = __float2half_rn(t[x][y + i]);
}

// ---------------- LayerNorm -> fp16 out ----------------
__global__ __launch_bounds__(256) void ln_kernel(
    const float* __restrict__ x, const float* __restrict__ g,
    const float* __restrict__ b, __half* __restrict__ outp)
{
    int row = blockIdx.x;
    int tid = threadIdx.x;
    const float4 v = ((const float4*)(x + (size_t)row * DM))[tid];
    float s  = v.x + v.y + v.z + v.w;
    float sq = v.x * v.x + v.y * v.y + v.z * v.z + v.w * v.w;
    #pragma unroll
    for (int o = 16; o; o >>= 1) {
        s  += __shfl_xor_sync(0xffffffffu, s,  o);
        sq += __shfl_xor_sync(0xffffffffu, sq, o);
    }
    __shared__ float ss[8], ssq[8];
    __shared__ float mean_s, inv_s;
    int w = tid >> 5, l = tid & 31;
    if (l == 0) { ss[w] = s; ssq[w] = sq; }
    __syncthreads();
    if (tid == 0) {
        float st = 0.f, sqt = 0.f;
        #pragma unroll
        for (int i = 0; i < 8; i++) { st += ss[i]; sqt += ssq[i]; }
        float mean = st * (1.0f / DM);
        float var  = sqt * (1.0f / DM) - mean * mean;
        mean_s = mean;
        inv_s  = rsqrtf(var + LN_EPS);
    }
    __syncthreads();
    float mean = mean_s, inv = inv_s;
    const float4 gv = ((const float4*)g)[tid];
    const float4 bv = ((const float4*)b)[tid];
    float o0 = (v.x - mean) * inv * gv.x + bv.x;
    float o1 = (v.y - mean) * inv * gv.y + bv.y;
    float o2 = (v.z - mean) * inv * gv.z + bv.z;
    float o3 = (v.w - mean) * inv * gv.w + bv.w;
    uint32_t* o16 = (uint32_t*)outp;
    size_t wi = ((size_t)row * DM + tid * 4) >> 1;
    o16[wi]     = packh(o1, o0);
    o16[wi + 1] = packh(o3, o2);
}

// ---------------- unified fp16 GEMM (R14 winner, V epilogue simplified) ------
#define GS        3
#define G_BASE    1024
#define G_SMEM_T(TM) (G_BASE + GS * ((TM) * 128 + 32768))

#if GEMM_TC
__device__ __forceinline__ bool elect_one() {
    uint32_t pred;
    asm volatile(
        "{\n\t.reg .pred p;\n\t"
        "elect.sync _|p, 0xFFFFFFFF;\n\t"
        "selp.b32 %0, 1, 0, p;\n\t}"
        : "=r"(pred));
    return pred != 0;
}
__device__ __forceinline__ uint64_t make_desc(uint32_t addr) {
    const uint64_t base = (2ULL << 61) | (1ULL << 46) | (64ULL << 32) | (1ULL << 16);
    return base | ((uint64_t)(addr >> 4) & 0x3FFF);
}
__device__ __forceinline__ void tc_mma_f16_ss(uint32_t d, uint64_t ad, uint64_t bd,
                                              uint32_t idesc, bool acc)
{
    uint32_t en = acc ? 1u : 0u;
    asm volatile(
        "{\n\t.reg .pred p;\n\t"
        "setp.ne.u32 p, %4, 0;\n\t"
        "tcgen05.mma.cta_group::1.kind::f16 [%0], %1, %2, %3, {%5, %5, %5, %5}, p;\n\t}"
        :: "r"(d), "l"(ad), "l"(bd), "r"(idesc), "r"(en), "r"(0u)
        : "memory");
}
#define MBAR_INIT(a, c) \
    asm volatile("mbarrier.init.shared.b64 [%0], %1;" :: "r"(a), "r"(c) : "memory")
#define MBAR_WAIT(a, par) do { \
    uint32_t _m = (a), _p = (par), _d; \
    asm volatile("{\n\t.reg .pred p;\n\t" \
        "mbarrier.try_wait.parity.acquire.cta.shared::cta.b64 p, [%1], %2;\n\t" \
        "selp.b32 %0, 1, 0, p;\n\t}" : "=r"(_d) : "r"(_m), "r"(_p) : "memory"); \
    if (!_d) { \
        asm volatile("{\n\t.reg .pred P1;\n\t" \
            "WL_%=:\n\t" \
            "mbarrier.try_wait.parity.acquire.cta.shared::cta.b64 P1, [%0], %1, 0x989680;\n\t" \
            "@P1 bra.uni WD_%=;\n\t" \
            "bra.uni WL_%=;\n\t" \
            "WD_%=:\n\t}" :: "r"(_m), "r"(_p) : "memory"); \
    } \
} while (0)
#define CPASYNC_MBAR_ARRIVE_NOINC(a) \
    asm volatile("cp.async.mbarrier.arrive.noinc.shared.b64 [%0];" :: "r"(a) : "memory")
#endif  // GEMM_TC

// epilogue write helper for MODE 3 (pair of adjacent columns, one row)
__device__ __forceinline__ void qkv_write_pair(int n, int row, float v0, float v1) {
    if (n < 1024) {
        int hd = n >> 6, d = n & 63;
        ((uint32_t*)g_q16)[(((size_t)hd * T_SEQ + row) * 64 + d) >> 1]
            = packh(v1 * QSCALE, v0 * QSCALE);
    } else if (n < 2048) {
        int hd = (n - 1024) >> 6, d = (n - 1024) & 63;
        ((uint32_t*)g_k16)[(((size_t)hd * T_SEQ + row) * 64 + d) >> 1]
            = packh(v1, v0);
    } else {
        int hd = (n - 2048) >> 6, d = (n - 2048) & 63;
        ((uint32_t*)g_v16)[(((size_t)hd * T_SEQ + row) * 64 + d) >> 1]
            = packh(v1, v0);
    }
}

template<int MODE, int TM>
__global__ __launch_bounds__(256)
void gemm_any(const __half* __restrict__ A, const __half* __restrict__ Bt,
              const float* __restrict__ bias, const float* __restrict__ res,
              float* __restrict__ C, int M, int N, int K)
{
    extern __shared__ __align__(1024) char gsm[];
    const int tid = threadIdx.x, wid = tid >> 5, lane = tid & 31;

#if GEMM_TC
    constexpr int A_TILE = TM * 128;
    constexpr int STAGE  = A_TILE + 32768;
    constexpr int TCOLS  = (TM == 256) ? 512 : 256;
    const int m0 = blockIdx.y * TM, n0 = blockIdx.x * 256;
    const uint32_t sb = (uint32_t)__cvta_generic_to_shared(gsm);
    const uint32_t mb0 = sb + 16, mb1 = sb + 24;
    const uint32_t fmb = sb + 32;

    if (wid == 0) {
        asm volatile("tcgen05.alloc.cta_group::1.sync.aligned.shared::cta.b32 [%0], %1;"
                     :: "r"(sb), "r"((uint32_t)TCOLS) : "memory");
        asm volatile("tcgen05.relinquish_alloc_permit.cta_group::1.sync.aligned;");
    }
    if (tid == 0) {
        MBAR_INIT(mb0, 1); MBAR_INIT(mb1, 1);
        MBAR_INIT(fmb + 0, 256); MBAR_INIT(fmb + 8, 256); MBAR_INIT(fmb + 16, 256);
    }
    __syncthreads();
    uint32_t tb;
    asm volatile("ld.shared.b32 %0, [%1];" : "=r"(tb) : "r"(sb));

    const int KT = K >> 6;
    const size_t rowB = (size_t)K * 2;

    auto fill = [&](int slot, int ktile) {
        uint32_t s = sb + G_BASE + slot * STAGE;
        const char* Ab = (const char*)A + ((size_t)m0 * K + (size_t)ktile * 64) * 2;
        const char* Bb = (const char*)Bt + ((size_t)n0 * K + (size_t)ktile * 64) * 2;
        #pragma unroll
        for (int i = 0; i < TM / 32; i++) {
            int idx = tid + i * 256;
            int r = idx >> 3, ch = (idx & 7) * 16;
            uint32_t byte = (uint32_t)(r * 128 + ch);
            uint32_t sw = byte ^ ((byte >> 3) & 0x70);
            cp16(s + sw, Ab + (size_t)r * rowB + ch);
        }
        #pragma unroll
        for (int i = 0; i < 8; i++) {
            int idx = tid + i * 256;
            int r = idx >> 3, ch = (idx & 7) * 16;
            uint32_t byte = (uint32_t)(r * 128 + ch);
            uint32_t sw = byte ^ ((byte >> 3) & 0x70);
            cp16(s + A_TILE + sw, Bb + (size_t)r * rowB + ch);
        }
        CPASYNC_MBAR_ARRIVE_NOINC(fmb + slot * 8);
    };

    #pragma unroll
    for (int st = 0; st < GS - 1; st++) fill(st, st);

    const uint32_t idesc = (1u << 4) | (0u << 7) | (0u << 10)
                         | (32u << 17) | (8u << 24);

    int ph0 = 0, ph1 = 0;
    for (int kt = 0; kt < KT; kt++) {
        if (wid == 0) {
            int slot = kt % GS;
            int fph = (kt / GS) & 1;
            MBAR_WAIT(fmb + slot * 8, fph);
            asm volatile("fence.proxy.async.shared::cta;" ::: "memory");
            if (elect_one()) {
                uint32_t s = sb + G_BASE + slot * STAGE;
                uint64_t ad = make_desc(s);
                uint64_t bd = make_desc(s + A_TILE);
                #pragma unroll
                for (int ks = 0; ks < 4; ks++) {
                    bool acc = (kt > 0) || (ks > 0);
                    tc_mma_f16_ss(tb, ad + ks * 2, bd + ks * 2, idesc, acc);
                    if (TM == 256)
                        tc_mma_f16_ss(tb + 256, ad + 1024 + ks * 2, bd + ks * 2, idesc, acc);
                }
                uint32_t mb = (kt & 1) ? mb1 : mb0;
                asm volatile(
                    "tcgen05.commit.cta_group::1.mbarrier::arrive::one.shared::cluster.b64 [%0];"
                    :: "r"(mb) : "memory");
            }
        }

        if (kt >= 1) {
            if ((kt - 1) & 1) { MBAR_WAIT(mb1, ph1); ph1 ^= 1; }
            else              { MBAR_WAIT(mb0, ph0); ph0 ^= 1; }
        }
        if (kt + GS - 1 < KT) fill((kt + GS - 1) % GS, kt + GS - 1);
    }

    if ((KT - 1) & 1) { MBAR_WAIT(mb1, ph1); }
    else              { MBAR_WAIT(mb0, ph0); }
    asm volatile("tcgen05.fence::after_thread_sync;" ::: "memory");

    {
        int row; uint32_t dbase; int cstart;
        if (TM == 256) {
            row = m0 + ((wid < 4) ? wid * 32 : 128 + (wid - 4) * 32) + lane;
            dbase = tb + ((wid < 4) ? 0u : 256u);
            cstart = 0;
        } else {
            row = m0 + (wid & 3) * 32 + lane;
            dbase = tb;
            cstart = (wid < 4) ? 0 : 128;
        }
        const int cspan = (TM == 256) ? 256 : 128;
        #pragma unroll
        for (int ci = 0; ci < 256; ci += 32) {
            if (ci >= cspan) break;
            const int c0 = cstart + ci;
            float d[32];
            asm volatile(
                "tcgen05.ld.sync.aligned.32x32b.x32.b32 "
                "{%0,%1,%2,%3,%4,%5,%6,%7,%8,%9,%10,%11,%12,%13,%14,%15,"
                "%16,%17,%18,%19,%20,%21,%22,%23,%24,%25,%26,%27,%28,%29,%30,%31}, [%32];"
                : "=f"(d[0]),  "=f"(d[1]),  "=f"(d[2]),  "=f"(d[3]),
                  "=f"(d[4]),  "=f"(d[5]),  "=f"(d[6]),  "=f"(d[7]),
                  "=f"(d[8]),  "=f"(d[9]),  "=f"(d[10]), "=f"(d[11]),
                  "=f"(d[12]), "=f"(d[13]), "=f"(d[14]), "=f"(d[15]),
                  "=f"(d[16]), "=f"(d[17]), "=f"(d[18]), "=f"(d[19]),
                  "=f"(d[20]), "=f"(d[21]), "=f"(d[22]), "=f"(d[23]),
                  "=f"(d[24]), "=f"(d[25]), "=f"(d[26]), "=f"(d[27]),
                  "=f"(d[28]), "=f"(d[29]), "=f"(d[30]), "=f"(d[31])
                : "r"(dbase + c0));
            asm volatile("tcgen05.wait::ld.sync.aligned;" ::: "memory");

            #pragma unroll
            for (int c = 0; c < 32; c += 4) {
                const int n = n0 + c0 + c;
                const float4 bv = *(const float4*)(bias + n);
                float4 v;
                v.x = d[c + 0] + bv.x; v.y = d[c + 1] + bv.y;
                v.z = d[c + 2] + bv.z; v.w = d[c + 3] + bv.w;
                if (MODE == 3) {
                    qkv_write_pair(n,     row, v.x, v.y);
                    qkv_write_pair(n + 2, row, v.z, v.w);
                } else if (MODE == 4) {
                    uint32_t* o16 = (uint32_t*)g_ff16;
                    size_t wi = ((size_t)row * N + n) >> 1;
                    o16[wi]     = packh(gelu_exact(v.y), gelu_exact(v.x));
                    o16[wi + 1] = packh(gelu_exact(v.w), gelu_exact(v.z));
                } else {
                    const float4 rv = *(const float4*)(res + (size_t)row * N + n);
                    v.x += rv.x; v.y += rv.y; v.z += rv.z; v.w += rv.w;
                    *(float4*)(C + (size_t)row * N + n) = v;
                }
            }
        }
    }

    __syncthreads();
    if (tid == 0) {
        asm volatile("mbarrier.inval.shared.b64 [%0];" :: "r"(mb0) : "memory");
        asm volatile("mbarrier.inval.shared.b64 [%0];" :: "r"(mb1) : "memory");
        asm volatile("mbarrier.inval.shared.b64 [%0];" :: "r"(fmb + 0) : "memory");
        asm volatile("mbarrier.inval.shared.b64 [%0];" :: "r"(fmb + 8) : "memory");
        asm volatile("mbarrier.inval.shared.b64 [%0];" :: "r"(fmb + 16) : "memory");
    }
    __syncthreads();
    if (wid == 0)
        asm volatile("tcgen05.dealloc.cta_group::1.sync.aligned.b32 %0, %1;"
                     :: "r"(tb), "r"((uint32_t)TCOLS));

#else
    // ================= mma.sync fp16 fallback (unchanged from R14) =============
    float* As = (float*)gsm;
    float* Bs = As + 2 * 16 * 132;
    #define AS(buf, k, m) As[((buf) * 16 + (k)) * 132 + (m)]
    #define BS(buf, k, n) Bs[((buf) * 16 + (k)) * 132 + (n)]

    const int wm = wid >> 2, wn = wid & 3;
    const int gp = lane >> 2, tg = lane & 3;

    for (int mi = 0; mi < TM / 128; mi++)
    for (int ni = 0; ni < 2; ni++) {
        const int m0 = blockIdx.y * TM + mi * 128;
        const int n0 = blockIdx.x * 256 + ni * 128;

        float c[4][4][4];
        #pragma unroll
        for (int i = 0; i < 4; i++)
            #pragma unroll
            for (int j = 0; j < 4; j++)
                #pragma unroll
                for (int r = 0; r < 4; r++) c[i][j][r] = 0.f;

        const int KT = K >> 4;
        float4 va[2], vb[2];

        __syncthreads();
        #pragma unroll
        for (int i = 0; i < 2; i++) {
            int idx = tid + i * 256;
            int r = idx >> 2, c4 = (idx & 3) << 2;
            va[i] = ld4h(A,  (size_t)(m0 + r) * K + c4);
            vb[i] = ld4h(Bt, (size_t)(n0 + r) * K + c4);
        }
        #pragma unroll
        for (int i = 0; i < 2; i++) {
            int idx = tid + i * 256;
            int r = idx >> 2, c4 = (idx & 3) << 2;
            AS(0, c4 + 0, r) = va[i].x; AS(0, c4 + 1, r) = va[i].y;
            AS(0, c4 + 2, r) = va[i].z; AS(0, c4 + 3, r) = va[i].w;
            BS(0, c4 + 0, r) = vb[i].x; BS(0, c4 + 1, r) = vb[i].y;
            BS(0, c4 + 2, r) = vb[i].z; BS(0, c4 + 3, r) = vb[i].w;
        }
        __syncthreads();

        int cur = 0;
        for (int kt = 0; kt < KT; kt++) {
            if (kt + 1 < KT) {
                #pragma unroll
                for (int i = 0; i < 2; i++) {
                    int idx = tid + i * 256;
                    int r = idx >> 2, c4 = (idx & 3) << 2;
                    va[i] = ld4h(A,  (size_t)(m0 + r) * K + (kt + 1) * 16 + c4);
                    vb[i] = ld4h(Bt, (size_t)(n0 + r) * K + (kt + 1) * 16 + c4);
                }
            }
            {
                uint32_t a[4][4], b[4][2];
                #pragma unroll
                for (int mf = 0; mf < 4; mf++) {
                    int r0 = wm * 64 + mf * 16;
                    a[mf][0] = packh(AS(cur, 2*tg+1, r0 + gp    ), AS(cur, 2*tg,   r0 + gp    ));
                    a[mf][1] = packh(AS(cur, 2*tg+1, r0 + gp + 8), AS(cur, 2*tg,   r0 + gp + 8));
                    a[mf][2] = packh(AS(cur, 2*tg+9, r0 + gp    ), AS(cur, 2*tg+8, r0 + gp    ));
                    a[mf][3] = packh(AS(cur, 2*tg+9, r0 + gp + 8), AS(cur, 2*tg+8, r0 + gp + 8));
                }
                #pragma unroll
                for (int nf = 0; nf < 4; nf++) {
                    int c0 = wn * 32 + nf * 8;
                    b[nf][0] = packh(BS(cur, 2*tg+1, c0 + gp), BS(cur, 2*tg,   c0 + gp));
                    b[nf][1] = packh(BS(cur, 2*tg+9, c0 + gp), BS(cur, 2*tg+8, c0 + gp));
                }
                #pragma unroll
                for (int mf = 0; mf < 4; mf++)
                    #pragma unroll
                    for (int nf = 0; nf < 4; nf++)
                        mma_f16(c[mf][nf], a[mf][0], a[mf][1], a[mf][2], a[mf][3],
                                b[nf][0], b[nf][1]);
            }
            if (kt + 1 < KT) {
                int nxt = cur ^ 1;
                #pragma unroll
                for (int i = 0; i < 2; i++) {
                    int idx = tid + i * 256;
                    int r = idx >> 2, c4 = (idx & 3) << 2;
                    AS(nxt, c4 + 0, r) = va[i].x; AS(nxt, c4 + 1, r) = va[i].y;
                    AS(nxt, c4 + 2, r) = va[i].z; AS(nxt, c4 + 3, r) = va[i].w;
                    BS(nxt, c4 + 0, r) = vb[i].x; BS(nxt, c4 + 1, r) = vb[i].y;
                    BS(nxt, c4 + 2, r) = vb[i].z; BS(nxt, c4 + 3, r) = vb[i].w;
                }
                __syncthreads();
                cur = nxt;
            }
        }

        #pragma unroll
        for (int mf = 0; mf < 4; mf++) {
            #pragma unroll
            for (int nf = 0; nf < 4; nf++) {
                int col = n0 + wn * 32 + nf * 8 + 2 * tg;
                float bi0 = bias[col], bi1 = bias[col + 1];
                #pragma unroll
                for (int hh = 0; hh < 2; hh++) {
                    int row = m0 + wm * 64 + mf * 16 + gp + hh * 8;
                    float v0 = c[mf][nf][hh * 2 + 0] + bi0;
                    float v1 = c[mf][nf][hh * 2 + 1] + bi1;
                    if (MODE == 3) {
                        qkv_write_pair(col, row, v0, v1);
                    } else if (MODE == 4) {
                        ((uint32_t*)g_ff16)[((size_t)row * N + col) >> 1]
                            = packh(gelu_exact(v1), gelu_exact(v0));
                    } else {
                        const float2 rv = *(const float2*)(res + (size_t)row * N + col);
                        v0 += rv.x; v1 += rv.y;
                        float2 o; o.x = v0; o.y = v1;
                        *(float2*)(C + (size_t)row * N + col) = o;
                    }
                }
            }
        }
    }
    #undef AS
    #undef BS
#endif
}

// ---------------- causal flash attention: fp16 + ldmatrix + f16x2 softmax ----
// grid (32 qtiles, 16 heads), 256 threads, 128-q x 64-key tiles, 2 CTAs/SM.
// smem words: Qs[128][36] | Ks 2x[64][36] | Vs 2x[64][36] (cols 64..71: ones) | msk 2x64
#define AQ_OFF  0
#define AK_OFF  4608
#define AV_OFF  9216
#define AM_OFF  13824
#define ATTN_SMEM ((13824 + 128) * 4)   // 55808

__global__ __launch_bounds__(256, 2) void attn_kernel(
    const int* __restrict__ amask, __half* __restrict__ y)
{
    extern __shared__ uint32_t shw[];
    uint32_t* Qs = shw + AQ_OFF;
    uint32_t* Ks = shw + AK_OFF;
    uint32_t* Vs = shw + AV_OFF;
    int*      mk = (int*)(shw + AM_OFF);

    const int tid = threadIdx.x, lane = tid & 31, w = tid >> 5;
    const int gp = lane >> 2, tg = lane & 3;
    const int h = blockIdx.y;
    const int q0 = (gridDim.x - 1 - blockIdx.x) * 128;
    const int qw = q0 + w * 16;

    // ldmatrix per-thread byte offsets
    const int lm = lane >> 3, lr = lane & 7;
    const uint32_t koff = (uint32_t)(((lm >> 1) * 8 + lr) * 144 + (lm & 1) * 16);
    const uint32_t voff = (uint32_t)(((lm & 1) * 8 + lr) * 144 + (lm >> 1) * 16);
    const uint32_t Kb = (uint32_t)__cvta_generic_to_shared(Ks);
    const uint32_t Vb = (uint32_t)__cvta_generic_to_shared(Vs);

    // ---- stage Q (fp16, pre-scaled) ----
    {
        const __half* qb = g_q16 + ((size_t)h * T_SEQ + q0) * 64;
        #pragma unroll
        for (int i = 0; i < 4; i++) {
            int idx = tid + i * 256;
            int r = idx >> 3, ch = idx & 7;
            cp16((uint32_t)__cvta_generic_to_shared(Qs + r * 36 + ch * 4),
                 qb + (size_t)r * 64 + ch * 8);
        }
    }
    asm volatile("cp.async.commit_group;" ::: "memory");

    // ones-column init for both V buffers (fp16 cols 64..71: col64=1, rest 0)
    if (tid < 128) {
        int buf = tid >> 6, r = tid & 63;
        uint32_t* vr = Vs + buf * 2304 + r * 36;
        vr[32] = 0x00003C00u; vr[33] = 0u; vr[34] = 0u; vr[35] = 0u;
    }

    auto fill_kv = [&](int buf, int kt) {
        const __half* kbs = g_k16 + ((size_t)h * T_SEQ + kt * 64) * 64;
        const __half* vbs = g_v16 + ((size_t)h * T_SEQ + kt * 64) * 64;
        #pragma unroll
        for (int i = 0; i < 2; i++) {
            int idx = tid + i * 256;
            int r = idx >> 3, ch = idx & 7;
            cp16((uint32_t)__cvta_generic_to_shared(Ks + buf * 2304 + r * 36 + ch * 4),
                 kbs + (size_t)r * 64 + ch * 8);
            cp16((uint32_t)__cvta_generic_to_shared(Vs + buf * 2304 + r * 36 + ch * 4),
                 vbs + (size_t)r * 64 + ch * 8);
        }
        if (tid < 16)
            cp16((uint32_t)__cvta_generic_to_shared(mk + buf * 64 + tid * 4),
                 amask + kt * 64 + tid * 4);
    };

    fill_kv(0, 0);
    asm volatile("cp.async.commit_group;" ::: "memory");
    asm volatile("cp.async.wait_group 0;" ::: "memory");
    __syncthreads();

    // ---- Q fragments ----
    uint32_t qa[4][4];
    {
        int r0 = w * 16;
        #pragma unroll
        for (int ks = 0; ks < 4; ks++) {
            qa[ks][0] = Qs[(r0 + gp    ) * 36 + 8 * ks + tg    ];
            qa[ks][1] = Qs[(r0 + gp + 8) * 36 + 8 * ks + tg    ];
            qa[ks][2] = Qs[(r0 + gp    ) * 36 + 8 * ks + 4 + tg];
            qa[ks][3] = Qs[(r0 + gp + 8) * 36 + 8 * ks + 4 + tg];
        }
    }

    float m0 = -INFINITY, m1 = -INFINITY;
    float o[9][4];     // o[8] = ones-column accumulator (row sums l)
    #pragma unroll
    for (int nf = 0; nf < 9; nf++)
        #pragma unroll
        for (int r = 0; r < 4; r++) o[nf][r] = 0.f;

    const uint32_t onesb = (gp == 0) ? 0x3C003C00u : 0u;

    const int ktmax = (q0 + 127) >> 6;
    const int kdiag = q0 >> 6;
    const int row0 = qw + gp, row1 = qw + gp + 8;
    int cur = 0;

    for (int kt = 0; kt <= ktmax; kt++) {
        asm volatile("cp.async.wait_group 0;" ::: "memory");
        __syncthreads();

        if (kt < ktmax) {
            fill_kv(cur ^ 1, kt + 1);
            asm volatile("cp.async.commit_group;" ::: "memory");
        }

        const uint32_t Kcur = Kb + cur * 9216;
        const uint32_t Vcur = Vb + cur * 9216;
        const int*     M    = mk + cur * 64;
        const bool diag = (kt >= kdiag);

        // ---- S = Q @ K^T via ldmatrix B-frags ----
        float sc[8][4];
        #pragma unroll
        for (int nf = 0; nf < 8; nf++)
            #pragma unroll
            for (int r = 0; r < 4; r++) sc[nf][r] = 0.f;

        #pragma unroll
        for (int ks = 0; ks < 4; ks++) {
            #pragma unroll
            for (int j = 0; j < 4; j++) {
                uint32_t kb[4];
                ldsm4(kb, Kcur + j * 2304 + ks * 32 + koff);
                mma_f16(sc[2*j],   qa[ks][0], qa[ks][1], qa[ks][2], qa[ks][3], kb[0], kb[1]);
                mma_f16(sc[2*j+1], qa[ks][0], qa[ks][1], qa[ks][2], qa[ks][3], kb[2], kb[3]);
            }
        }

        // ---- mask + row max ----
        float tm0 = -INFINITY, tm1 = -INFINITY;
        if (diag) {
            #pragma unroll
            for (int nf = 0; nf < 8; nf++) {
                int cl = nf * 8 + 2 * tg;
                int c  = kt * 64 + cl;
                bool mk0 = M[cl] != 0, mk1 = M[cl + 1] != 0;
                float s0 = sc[nf][0], s1 = sc[nf][1];
                float s2 = sc[nf][2], s3 = sc[nf][3];
                s0 = (c     <= row0 && mk0) ? s0 : -INFINITY;
                s1 = (c + 1 <= row0 && mk1) ? s1 : -INFINITY;
                s2 = (c     <= row1 && mk0) ? s2 : -INFINITY;
                s3 = (c + 1 <= row1 && mk1) ? s3 : -INFINITY;
                sc[nf][0] = s0; sc[nf][1] = s1; sc[nf][2] = s2; sc[nf][3] = s3;
                tm0 = fmaxf(tm0, fmaxf(s0, s1));
                tm1 = fmaxf(tm1, fmaxf(s2, s3));
            }
        } else {
            #pragma unroll
            for (int nf = 0; nf < 8; nf++) {
                int cl = nf * 8 + 2 * tg;
                bool mk0 = M[cl] != 0, mk1 = M[cl + 1] != 0;
                float s0 = mk0 ? sc[nf][0] : -INFINITY;
                float s1 = mk1 ? sc[nf][1] : -INFINITY;
                float s2 = mk0 ? sc[nf][2] : -INFINITY;
                float s3 = mk1 ? sc[nf][3] : -INFINITY;
                sc[nf][0] = s0; sc[nf][1] = s1; sc[nf][2] = s2; sc[nf][3] = s3;
                tm0 = fmaxf(tm0, fmaxf(s0, s1));
                tm1 = fmaxf(tm1, fmaxf(s2, s3));
            }
        }
        tm0 = fmaxf(tm0, __shfl_xor_sync(0xffffffffu, tm0, 1));
        tm0 = fmaxf(tm0, __shfl_xor_sync(0xffffffffu, tm0, 2));
        tm1 = fmaxf(tm1, __shfl_xor_sync(0xffffffffu, tm1, 1));
        tm1 = fmaxf(tm1, __shfl_xor_sync(0xffffffffu, tm1, 2));

        float nm0 = fmaxf(m0, tm0), nm1 = fmaxf(m1, tm1);
        float ne0 = fmaxf(nm0, -1e30f), ne1 = fmaxf(nm1, -1e30f);
        float al0 = ex2(m0 - ne0), al1 = ex2(m1 - ne1);
        m0 = nm0; m1 = nm1;

        #pragma unroll
        for (int nf = 0; nf < 9; nf++) {
            o[nf][0] *= al0; o[nf][1] *= al0;
            o[nf][2] *= al1; o[nf][3] *= al1;
        }

        // ---- P = exp2(S - ne) packed straight to fp16x2 A-frags; O += P @ V ----
        #pragma unroll
        for (int ks = 0; ks < 4; ks++) {
            uint32_t pa0 = ex2h2(packh(sc[2*ks  ][1] - ne0, sc[2*ks  ][0] - ne0));
            uint32_t pa1 = ex2h2(packh(sc[2*ks  ][3] - ne1, sc[2*ks  ][2] - ne1));
            uint32_t pa2 = ex2h2(packh(sc[2*ks+1][1] - ne0, sc[2*ks+1][0] - ne0));
            uint32_t pa3 = ex2h2(packh(sc[2*ks+1][3] - ne1, sc[2*ks+1][2] - ne1));
            #pragma unroll
            for (int j = 0; j < 4; j++) {
                uint32_t vb[4];
                ldsm4t(vb, Vcur + ks * 2304 + j * 32 + voff);
                mma_f16(o[2*j],   pa0, pa1, pa2, pa3, vb[0], vb[1]);
                mma_f16(o[2*j+1], pa0, pa1, pa2, pa3, vb[2], vb[3]);
            }
            mma_f16(o[8], pa0, pa1, pa2, pa3, onesb, onesb);
        }
        cur ^= 1;
    }

    // ---- l from the ones column (col 64 -> tg==0 lanes of o[8]) ----
    float l0 = __shfl_sync(0xffffffffu, o[8][0], lane & ~3);
    float l1 = __shfl_sync(0xffffffffu, o[8][2], lane & ~3);
    float il0 = 1.0f / fmaxf(l0, 1e-30f);
    float il1 = 1.0f / fmaxf(l1, 1e-30f);
    uint32_t* yw = (uint32_t*)y;
    #pragma unroll
    for (int nf = 0; nf < 8; nf++) {
        int col = h * HDIM + nf * 8 + 2 * tg;
        yw[((size_t)row0 * DM + col) >> 1] = packh(o[nf][1] * il0, o[nf][0] * il0);
        yw[((size_t)row1 * DM + col) >> 1] = packh(o[nf][3] * il1, o[nf][2] * il1);
    }
}

// ---------------- launcher ----------------
extern "C" void kernel_launch(void* const* d_in, const int* in_sizes, int n_in,
                              void* d_out, int out_size)
{
    const float* x     = (const float*)d_in[0];
    const int*   amask = (const int*)  d_in[1];
    const float* ln1g  = (const float*)d_in[2];
    const float* ln1b  = (const float*)d_in[3];
    const float* Wqkv  = (const float*)d_in[4];
    const float* bqkv  = (const float*)d_in[5];
    const float* Wo    = (const float*)d_in[6];
    const float* bo    = (const float*)d_in[7];
    const float* ln2g  = (const float*)d_in[8];
    const float* ln2b  = (const float*)d_in[9];
    const float* W1    = (const float*)d_in[10];
    const float* b1    = (const float*)d_in[11];
    const float* W2    = (const float*)d_in[12];
    const float* b2    = (const float*)d_in[13];
    float* out = (float*)d_out;

    void *p_x2, *p_wqkv, *p_wo, *p_w1, *p_w2, *p_ln16, *p_y16, *p_ff16;
    cudaGetSymbolAddress(&p_x2,   g_x2);
    cudaGetSymbolAddress(&p_wqkv, g_wqkv16);
    cudaGetSymbolAddress(&p_wo,   g_wo16);
    cudaGetSymbolAddress(&p_w1,   g_w1_16);
    cudaGetSymbolAddress(&p_w2,   g_w2_16);
    cudaGetSymbolAddress(&p_ln16, g_ln16);
    cudaGetSymbolAddress(&p_y16,  g_y16);
    cudaGetSymbolAddress(&p_ff16, g_ff16);

    cudaFuncSetAttribute(attn_kernel,
        cudaFuncAttributeMaxDynamicSharedMemorySize, ATTN_SMEM);
    cudaFuncSetAttribute(gemm_any<3, 256>,
        cudaFuncAttributeMaxDynamicSharedMemorySize, G_SMEM_T(256));
    cudaFuncSetAttribute(gemm_any<4, 256>,
        cudaFuncAttributeMaxDynamicSharedMemorySize, G_SMEM_T(256));
    cudaFuncSetAttribute(gemm_any<5, 128>,
        cudaFuncAttributeMaxDynamicSharedMemorySize, G_SMEM_T(128));

    // 0. weight transposes — single launch (all -> fp16 [N,K])
    transpose_all<<<12288, 256>>>(Wqkv, Wo, W1, W2,
                                  (__half*)p_wqkv, (__half*)p_wo,
                                  (__half*)p_w1, (__half*)p_w2);

    // 1. LN1 -> fp16
    ln_kernel<<<T_SEQ, 256>>>(x, ln1g, ln1b, (__half*)p_ln16);
    // 2. QKV (fp16) -> fp16 q/k/v buffers
    gemm_any<3, 256><<<dim3(12, 16), 256, G_SMEM_T(256)>>>(
        (__half*)p_ln16, (__half*)p_wqkv, bqkv, nullptr, nullptr, T_SEQ, 3 * DM, DM);
    // 3. attention -> fp16 y
    attn_kernel<<<dim3(32, 16), 256, ATTN_SMEM>>>(amask, (__half*)p_y16);
    // 4. x2 = x + y @ W_o + b_o
    gemm_any<5, 128><<<dim3(4, 32), 256, G_SMEM_T(128)>>>(
        (__half*)p_y16, (__half*)p_wo, bo, x, (float*)p_x2, T_SEQ, DM, DM);
    // 5. LN2 -> fp16
    ln_kernel<<<T_SEQ, 256>>>((float*)p_x2, ln2g, ln2b, (__half*)p_ln16);
    // 6. FF1: gelu -> fp16 g_ff16
    gemm_any<4, 256><<<dim3(16, 16), 256, G_SMEM_T(256)>>>(
        (__half*)p_ln16, (__half*)p_w1, b1, nullptr, nullptr, T_SEQ, DFF, DM);
    // 7. FF2: out = x2 + ff @ W2 + b2
    gemm_any<5, 128><<<dim3(4, 32), 256, G_SMEM_T(128)>>>(
        (__half*)p_ff16, (__half*)p_w2, b2, (float*)p_x2, out, T_SEQ, DM, DFF);
}